// round 1
// baseline (speedup 1.0000x reference)
#include <cuda_runtime.h>
#include <cuda_bf16.h>
#include <math.h>

// Problem constants
#define BB 2
#define SS 2048
#define DIM 2048
#define NH 16
#define KVH 4
#define DH 128
#define MROWS (BB * SS)   // 4096

// ---------------- scratch (device globals; no allocation allowed) -------------
__device__ float g_qraw[MROWS * (NH * DH)];     // [4096, 2048]
__device__ float g_kraw[MROWS * (KVH * DH)];    // [4096, 512]
__device__ float g_vraw[MROWS * (KVH * DH)];    // [4096, 512]
__device__ float g_qT[BB * NH * DH * SS];       // [b,h,d,s]
__device__ float g_kT[BB * KVH * DH * SS];      // [b,kvh,d,s]
__device__ float g_vv[BB * KVH * SS * DH];      // [b,kvh,s,d]
__device__ float g_att[MROWS * (NH * DH)];      // [b,s,h*dh]

// ---------------- fp32 tiled SGEMM: C[M,N] = A[M,K] @ B[K,N] (row-major) ------
#define GBM 128
#define GBN 128
#define GBK 8

__global__ __launch_bounds__(256) void sgemm_kernel(
    const float* __restrict__ A, const float* __restrict__ B,
    float* __restrict__ C, int M, int N, int K)
{
    __shared__ float As[GBK][GBM];
    __shared__ float Bs[GBK][GBN];

    const int tid = threadIdx.x;
    const int tx = tid & 15;        // 0..15  -> col group
    const int ty = tid >> 4;        // 0..15  -> row group
    const int brow = blockIdx.y * GBM;
    const int bcol = blockIdx.x * GBN;

    // A load mapping: 128 rows x 8 k, one float4 per thread
    const int arow = tid >> 1;           // 0..127
    const int ak4  = (tid & 1) * 4;      // 0 or 4
    // B load mapping: 8 k-rows x 128 cols, one float4 per thread
    const int bk  = tid >> 5;            // 0..7
    const int bc4 = (tid & 31) * 4;      // 0..124

    const float* Aptr = A + (size_t)(brow + arow) * K + ak4;
    const float* Bptr = B + (size_t)bk * N + bcol + bc4;

    float acc[8][8];
#pragma unroll
    for (int i = 0; i < 8; i++)
#pragma unroll
        for (int j = 0; j < 8; j++) acc[i][j] = 0.0f;

    for (int k0 = 0; k0 < K; k0 += GBK) {
        float4 av = *(const float4*)Aptr;  Aptr += GBK;
        float4 bv = *(const float4*)Bptr;  Bptr += (size_t)GBK * N;

        As[ak4 + 0][arow] = av.x;
        As[ak4 + 1][arow] = av.y;
        As[ak4 + 2][arow] = av.z;
        As[ak4 + 3][arow] = av.w;
        *(float4*)&Bs[bk][bc4] = bv;
        __syncthreads();

#pragma unroll
        for (int kk = 0; kk < GBK; kk++) {
            float a[8], b[8];
            *(float4*)(a)     = *(const float4*)&As[kk][ty * 8];
            *(float4*)(a + 4) = *(const float4*)&As[kk][ty * 8 + 4];
            *(float4*)(b)     = *(const float4*)&Bs[kk][tx * 8];
            *(float4*)(b + 4) = *(const float4*)&Bs[kk][tx * 8 + 4];
#pragma unroll
            for (int i = 0; i < 8; i++)
#pragma unroll
                for (int j = 0; j < 8; j++)
                    acc[i][j] = fmaf(a[i], b[j], acc[i][j]);
        }
        __syncthreads();
    }

#pragma unroll
    for (int i = 0; i < 8; i++) {
        float* Crow = C + (size_t)(brow + ty * 8 + i) * N + bcol + tx * 8;
        *(float4*)Crow       = make_float4(acc[i][0], acc[i][1], acc[i][2], acc[i][3]);
        *(float4*)(Crow + 4) = make_float4(acc[i][4], acc[i][5], acc[i][6], acc[i][7]);
    }
}

// ---------------- RoPE + layout transform -------------------------------------
// grid: (S, B), block 256. Writes q/k transposed to [b,h,d,s]; v to [b,kvh,s,d].
__global__ __launch_bounds__(256) void rope_kernel(const int* __restrict__ pos_ids)
{
    const int s = blockIdx.x;
    const int b = blockIdx.y;
    const int t = threadIdx.x;

    __shared__ float cs[64], sn[64];
    if (t < 64) {
        double invf = exp(-((double)(2 * t) / (double)DH) * log(10000.0));
        double ang = (double)pos_ids[s] * invf;
        cs[t] = (float)cos(ang);
        sn[t] = (float)sin(ang);
    }
    __syncthreads();

    const float* qrow = g_qraw + (size_t)(b * SS + s) * (NH * DH);
    for (int idx = t; idx < NH * 64; idx += 256) {
        int h = idx >> 6, i = idx & 63;
        float x1 = qrow[h * DH + i];
        float x2 = qrow[h * DH + 64 + i];
        size_t base = (size_t)(b * NH + h) * DH * SS;
        g_qT[base + (size_t)i * SS + s]        = x1 * cs[i] - x2 * sn[i];
        g_qT[base + (size_t)(i + 64) * SS + s] = x2 * cs[i] + x1 * sn[i];
    }

    const float* krow = g_kraw + (size_t)(b * SS + s) * (KVH * DH);
    for (int idx = t; idx < KVH * 64; idx += 256) {
        int h = idx >> 6, i = idx & 63;
        float x1 = krow[h * DH + i];
        float x2 = krow[h * DH + 64 + i];
        size_t base = (size_t)(b * KVH + h) * DH * SS;
        g_kT[base + (size_t)i * SS + s]        = x1 * cs[i] - x2 * sn[i];
        g_kT[base + (size_t)(i + 64) * SS + s] = x2 * cs[i] + x1 * sn[i];
    }

    const float* vrow = g_vraw + (size_t)(b * SS + s) * (KVH * DH);
    for (int idx = t; idx < KVH * DH; idx += 256) {
        int h = idx >> 7, d = idx & 127;
        g_vv[((size_t)(b * KVH + h) * SS + s) * DH + d] = vrow[idx];
    }
}

// ---------------- flash attention (fp32, causal, GQA) --------------------------
// tiles: 64 queries x 64 keys, DH=128. 256 threads; thread = (ty,tx) 16x16.
// thread owns 4 query rows (ty*4+r) and: S cols tx*4+j, O cols tx*8+c.
#define ATM 64
#define ATN 64
#define TP 68    // padded stride for Qt/Kt/Ps rows
#define VP 132   // padded stride for Vs rows

#define ATT_SMEM ((128 * TP * 2 + ATN * VP + ATM * TP) * 4)

__global__ __launch_bounds__(256) void attn_kernel()
{
    extern __shared__ float sm[];
    float* Qt = sm;                       // [128][TP]  (d-major)
    float* Kt = Qt + 128 * TP;            // [128][TP]
    float* Vs = Kt + 128 * TP;            // [64][VP]   (j-major)
    float* Ps = Vs + ATN * VP;            // [64][TP]

    const int qt = (int)gridDim.x - 1 - (int)blockIdx.x;   // heavy tiles first
    const int h = blockIdx.y;
    const int b = blockIdx.z;
    const int kvh = h >> 2;

    const int tid = threadIdx.x;
    const int tx = tid & 15;
    const int ty = tid >> 4;
    const int q0 = qt * ATM;

    const float* qTb = g_qT + (size_t)(b * NH + h) * DH * SS;
    const float* kTb = g_kT + (size_t)(b * KVH + kvh) * DH * SS;
    const float* vb  = g_vv + (size_t)(b * KVH + kvh) * SS * DH;

    // load Q tile (128 d-rows x 64 query-cols), coalesced, conflict-free stores
    for (int i = tid; i < 128 * 16; i += 256) {
        int d = i >> 4, c4 = (i & 15) * 4;
        *(float4*)&Qt[d * TP + c4] = *(const float4*)(qTb + (size_t)d * SS + q0 + c4);
    }

    float acc[4][8];
#pragma unroll
    for (int r = 0; r < 4; r++)
#pragma unroll
        for (int c = 0; c < 8; c++) acc[r][c] = 0.0f;
    float m_run[4] = {-INFINITY, -INFINITY, -INFINITY, -INFINITY};
    float l_run[4] = {0.0f, 0.0f, 0.0f, 0.0f};

    const float scale = 0.08838834764831845f;  // 1/sqrt(128)
    const int ntiles = qt + 1;

    for (int kt = 0; kt < ntiles; kt++) {
        const int k0 = kt * ATN;
        __syncthreads();  // protect Kt/Vs/Ps (and publish Qt on first iter)

        for (int i = tid; i < 128 * 16; i += 256) {
            int d = i >> 4, c4 = (i & 15) * 4;
            *(float4*)&Kt[d * TP + c4] = *(const float4*)(kTb + (size_t)d * SS + k0 + c4);
        }
        for (int i = tid; i < ATN * 32; i += 256) {
            int j = i >> 5, d4 = (i & 31) * 4;
            *(float4*)&Vs[j * VP + d4] = *(const float4*)(vb + (size_t)(k0 + j) * DH + d4);
        }
        __syncthreads();

        // S = Q K^T   (4x4 per thread)
        float s[4][4];
#pragma unroll
        for (int r = 0; r < 4; r++)
#pragma unroll
            for (int j = 0; j < 4; j++) s[r][j] = 0.0f;

#pragma unroll 8
        for (int d = 0; d < 128; d++) {
            float4 a  = *(const float4*)&Qt[d * TP + (ty << 2)];
            float4 kb = *(const float4*)&Kt[d * TP + (tx << 2)];
            s[0][0] = fmaf(a.x, kb.x, s[0][0]); s[0][1] = fmaf(a.x, kb.y, s[0][1]);
            s[0][2] = fmaf(a.x, kb.z, s[0][2]); s[0][3] = fmaf(a.x, kb.w, s[0][3]);
            s[1][0] = fmaf(a.y, kb.x, s[1][0]); s[1][1] = fmaf(a.y, kb.y, s[1][1]);
            s[1][2] = fmaf(a.y, kb.z, s[1][2]); s[1][3] = fmaf(a.y, kb.w, s[1][3]);
            s[2][0] = fmaf(a.z, kb.x, s[2][0]); s[2][1] = fmaf(a.z, kb.y, s[2][1]);
            s[2][2] = fmaf(a.z, kb.z, s[2][2]); s[2][3] = fmaf(a.z, kb.w, s[2][3]);
            s[3][0] = fmaf(a.w, kb.x, s[3][0]); s[3][1] = fmaf(a.w, kb.y, s[3][1]);
            s[3][2] = fmaf(a.w, kb.z, s[3][2]); s[3][3] = fmaf(a.w, kb.w, s[3][3]);
        }

        const bool diag = (kt == qt);
#pragma unroll
        for (int r = 0; r < 4; r++) {
#pragma unroll
            for (int j = 0; j < 4; j++) {
                float v = s[r][j] * scale;
                if (diag && (k0 + tx * 4 + j > q0 + ty * 4 + r)) v = -INFINITY;
                s[r][j] = v;
            }
        }

        // online softmax per query row (reduce over 16 tx lanes in half-warp)
#pragma unroll
        for (int r = 0; r < 4; r++) {
            float mv = fmaxf(fmaxf(s[r][0], s[r][1]), fmaxf(s[r][2], s[r][3]));
#pragma unroll
            for (int off = 8; off > 0; off >>= 1)
                mv = fmaxf(mv, __shfl_xor_sync(0xffffffffu, mv, off));
            float mnew = fmaxf(m_run[r], mv);
            float e0 = __expf(s[r][0] - mnew);
            float e1 = __expf(s[r][1] - mnew);
            float e2 = __expf(s[r][2] - mnew);
            float e3 = __expf(s[r][3] - mnew);
            float sum = (e0 + e1) + (e2 + e3);
#pragma unroll
            for (int off = 8; off > 0; off >>= 1)
                sum += __shfl_xor_sync(0xffffffffu, sum, off);
            float corr = __expf(m_run[r] - mnew);
            l_run[r] = l_run[r] * corr + sum;
            m_run[r] = mnew;
#pragma unroll
            for (int c = 0; c < 8; c++) acc[r][c] *= corr;
            *(float4*)&Ps[(ty * 4 + r) * TP + tx * 4] = make_float4(e0, e1, e2, e3);
        }
        __syncthreads();

        // O += P V
#pragma unroll 4
        for (int j = 0; j < ATN; j++) {
            float p[4];
#pragma unroll
            for (int r = 0; r < 4; r++) p[r] = Ps[(ty * 4 + r) * TP + j];
            float v[8];
            *(float4*)(v)     = *(const float4*)&Vs[j * VP + tx * 8];
            *(float4*)(v + 4) = *(const float4*)&Vs[j * VP + tx * 8 + 4];
#pragma unroll
            for (int r = 0; r < 4; r++)
#pragma unroll
                for (int c = 0; c < 8; c++)
                    acc[r][c] = fmaf(p[r], v[c], acc[r][c]);
        }
    }

    // epilogue: normalize, write [b, s, h*DH + d]
#pragma unroll
    for (int r = 0; r < 4; r++) {
        float inv = 1.0f / l_run[r];
        int row = b * SS + q0 + ty * 4 + r;
        float* outp = g_att + (size_t)row * (NH * DH) + h * DH + tx * 8;
        *(float4*)outp       = make_float4(acc[r][0] * inv, acc[r][1] * inv,
                                           acc[r][2] * inv, acc[r][3] * inv);
        *(float4*)(outp + 4) = make_float4(acc[r][4] * inv, acc[r][5] * inv,
                                           acc[r][6] * inv, acc[r][7] * inv);
    }
}

// ---------------- launch --------------------------------------------------------
extern "C" void kernel_launch(void* const* d_in, const int* in_sizes, int n_in,
                              void* d_out, int out_size)
{
    const float* x   = (const float*)d_in[0];
    // d_in[1] = mask (causal; handled analytically)
    const int*   pos = (const int*)d_in[2];
    const float* Wq  = (const float*)d_in[3];
    const float* Wk  = (const float*)d_in[4];
    const float* Wv  = (const float*)d_in[5];
    const float* Wo  = (const float*)d_in[6];
    float* out = (float*)d_out;

    float *qraw, *kraw, *vraw, *att;
    cudaGetSymbolAddress((void**)&qraw, g_qraw);
    cudaGetSymbolAddress((void**)&kraw, g_kraw);
    cudaGetSymbolAddress((void**)&vraw, g_vraw);
    cudaGetSymbolAddress((void**)&att,  g_att);

    cudaFuncSetAttribute(attn_kernel,
                         cudaFuncAttributeMaxDynamicSharedMemorySize, ATT_SMEM);

    // QKV projections
    sgemm_kernel<<<dim3((NH * DH) / GBN, MROWS / GBM), 256>>>(x, Wq, qraw, MROWS, NH * DH, DIM);
    sgemm_kernel<<<dim3((KVH * DH) / GBN, MROWS / GBM), 256>>>(x, Wk, kraw, MROWS, KVH * DH, DIM);
    sgemm_kernel<<<dim3((KVH * DH) / GBN, MROWS / GBM), 256>>>(x, Wv, vraw, MROWS, KVH * DH, DIM);

    // RoPE + transpose
    rope_kernel<<<dim3(SS, BB), 256>>>(pos);

    // attention
    attn_kernel<<<dim3(SS / ATM, NH, BB), 256, ATT_SMEM>>>();

    // output projection
    sgemm_kernel<<<dim3(DIM / GBN, MROWS / GBM), 256>>>(att, Wo, out, MROWS, DIM, NH * DH);
}

// round 3
// speedup vs baseline: 1.6284x; 1.6284x over previous
#include <cuda_runtime.h>
#include <cuda_bf16.h>
#include <math.h>
#include <stdint.h>

// Problem constants
#define BB 2
#define SS 2048
#define DIM 2048
#define NH 16
#define KVH 4
#define DH 128
#define MROWS (BB * SS)   // 4096

// ---------------- scratch (device globals; no allocation allowed) -------------
__device__ float g_qraw[MROWS * (NH * DH)];
__device__ float g_kraw[MROWS * (KVH * DH)];
__device__ float g_vraw[MROWS * (KVH * DH)];
__device__ float g_qT[BB * NH * DH * SS];       // [b,h,d,s]
__device__ float g_kT[BB * KVH * DH * SS];      // [b,kvh,d,s]
__device__ float g_vv[BB * KVH * SS * DH];      // [b,kvh,s,d]

// bf16 hi/lo split operands
__device__ __nv_bfloat16 g_xh[MROWS * DIM];
__device__ __nv_bfloat16 g_xl[MROWS * DIM];
__device__ __nv_bfloat16 g_wqh[DIM * DIM];      // transposed [N][K]
__device__ __nv_bfloat16 g_wql[DIM * DIM];
__device__ __nv_bfloat16 g_wkh[(KVH*DH) * DIM];
__device__ __nv_bfloat16 g_wkl[(KVH*DH) * DIM];
__device__ __nv_bfloat16 g_wvh[(KVH*DH) * DIM];
__device__ __nv_bfloat16 g_wvl[(KVH*DH) * DIM];
__device__ __nv_bfloat16 g_woh[DIM * DIM];
__device__ __nv_bfloat16 g_wol[DIM * DIM];
__device__ __nv_bfloat16 g_atth[MROWS * (NH*DH)];
__device__ __nv_bfloat16 g_attl[MROWS * (NH*DH)];

// ---------------- PTX helpers ---------------------------------------------------
__device__ __forceinline__ uint32_t smem_u32(const void* p) {
    uint32_t a;
    asm("{ .reg .u64 t; cvta.to.shared.u64 t, %1; cvt.u32.u64 %0, t; }"
        : "=r"(a) : "l"(p));
    return a;
}

__device__ __forceinline__ void cp16(uint32_t dst, const void* src) {
    asm volatile("cp.async.cg.shared.global [%0], [%1], 16;\n"
                 :: "r"(dst), "l"(src));
}

__device__ __forceinline__ void ldm_x4(uint32_t r[4], uint32_t addr) {
    asm volatile("ldmatrix.sync.aligned.m8n8.x4.shared.b16 {%0,%1,%2,%3}, [%4];"
                 : "=r"(r[0]), "=r"(r[1]), "=r"(r[2]), "=r"(r[3]) : "r"(addr));
}

__device__ __forceinline__ void mma_bf16(float c[4], const uint32_t a[4],
                                         uint32_t b0, uint32_t b1) {
    asm volatile(
        "mma.sync.aligned.m16n8k16.row.col.f32.bf16.bf16.f32 "
        "{%0,%1,%2,%3}, {%4,%5,%6,%7}, {%8,%9}, {%0,%1,%2,%3};"
        : "+f"(c[0]), "+f"(c[1]), "+f"(c[2]), "+f"(c[3])
        : "r"(a[0]), "r"(a[1]), "r"(a[2]), "r"(a[3]), "r"(b0), "r"(b1));
}

// ---------------- fp32 -> bf16 hi/lo split -------------------------------------
__global__ __launch_bounds__(256) void split_kernel(
    const float* __restrict__ in, __nv_bfloat16* __restrict__ hi,
    __nv_bfloat16* __restrict__ lo, int n4)
{
    int i = blockIdx.x * blockDim.x + threadIdx.x;
    if (i >= n4) return;
    float4 v = ((const float4*)in)[i];
    __nv_bfloat16 h0 = __float2bfloat16(v.x);
    __nv_bfloat16 h1 = __float2bfloat16(v.y);
    __nv_bfloat16 h2 = __float2bfloat16(v.z);
    __nv_bfloat16 h3 = __float2bfloat16(v.w);
    __nv_bfloat162 ha, hb, la, lb;
    ha.x = h0; ha.y = h1; hb.x = h2; hb.y = h3;
    la.x = __float2bfloat16(v.x - __bfloat162float(h0));
    la.y = __float2bfloat16(v.y - __bfloat162float(h1));
    lb.x = __float2bfloat16(v.z - __bfloat162float(h2));
    lb.y = __float2bfloat16(v.w - __bfloat162float(h3));
    ((__nv_bfloat162*)hi)[2*i]   = ha;
    ((__nv_bfloat162*)hi)[2*i+1] = hb;
    ((__nv_bfloat162*)lo)[2*i]   = la;
    ((__nv_bfloat162*)lo)[2*i+1] = lb;
}

// ---------------- fp32 [K][N] -> bf16 hi/lo transposed [N][K] -------------------
__global__ __launch_bounds__(256) void splitT_kernel(
    const float* __restrict__ W, __nv_bfloat16* __restrict__ Th,
    __nv_bfloat16* __restrict__ Tl, int K, int N)
{
    __shared__ float t[32][33];
    const int n0 = blockIdx.x * 32, k0 = blockIdx.y * 32;
    const int tx = threadIdx.x, ty = threadIdx.y;   // (32, 8)
    for (int i = ty; i < 32; i += 8)
        t[i][tx] = W[(size_t)(k0 + i) * N + n0 + tx];
    __syncthreads();
    for (int i = ty; i < 32; i += 8) {
        float v = t[tx][i];
        __nv_bfloat16 h = __float2bfloat16(v);
        Th[(size_t)(n0 + i) * K + k0 + tx] = h;
        Tl[(size_t)(n0 + i) * K + k0 + tx] = __float2bfloat16(v - __bfloat162float(h));
    }
}

// ---------------- bf16 mma.sync 3-pass GEMM ------------------------------------
// C[M,N] = Ah@Bh^T + Ah@Bl^T + Al@Bh^T.  A:[M][K] bf16, B:[N][K] bf16 (K-major).
// CTA 128x128, BK=32, 8 warps (4m x 2n), warp tile 32x64, cp.async double buffer.
#define GK 2048
#define ROWB 80                 // smem row stride bytes (32 bf16 + 8 pad)
#define TILE_B (128 * ROWB)     // 10240
#define OFF_AH 0
#define OFF_AL (1 * TILE_B)
#define OFF_BH (2 * TILE_B)
#define OFF_BL (3 * TILE_B)
#define STG (4 * TILE_B)        // 40960 per stage
#define MM_SMEM (2 * STG)       // 81920

__global__ __launch_bounds__(256) void mm_bf16_kernel(
    const __nv_bfloat16* __restrict__ Ah, const __nv_bfloat16* __restrict__ Al,
    const __nv_bfloat16* __restrict__ Bh, const __nv_bfloat16* __restrict__ Bl,
    float* __restrict__ C, int N)
{
    extern __shared__ char smem[];
    const uint32_t sb = smem_u32(smem);
    const int tid = threadIdx.x;
    const int lane = tid & 31, warp = tid >> 5;
    const int m0 = blockIdx.y * 128, n0 = blockIdx.x * 128;
    const int wm0 = (warp >> 1) * 32;       // warp m offset in CTA tile
    const int wn0 = (warp & 1) * 64;        // warp n offset

    // ldmatrix lane address components
    const int arow_l  = lane & 15;
    const int akoff_l = (lane >> 4) << 3;                   // 0 or 8 elems
    const int brow_l  = (lane & 7) + ((lane >> 4) << 3);    // 0..15
    const int bkoff_l = ((lane >> 3) & 1) << 3;             // 0 or 8 elems

    // global load mapping: 512 chunks (128 rows x 4x16B) per operand, 2/thread
    const int r0 = tid >> 2;           // rows tid/4 and tid/4+64
    const int ch0 = (tid & 3) << 3;    // elem offset 0,8,16,24

    float acc[2][8][4];
#pragma unroll
    for (int im = 0; im < 2; im++)
#pragma unroll
        for (int j = 0; j < 8; j++)
#pragma unroll
            for (int c = 0; c < 4; c++) acc[im][j][c] = 0.0f;

    const int NT = GK / 32;   // 64 k-tiles

    // ---- stage issue ----
    auto issue = [&](int t) {
        const int k0 = t * 32;
        const uint32_t sbase = sb + (t & 1) * STG;
#pragma unroll
        for (int i = 0; i < 2; i++) {
            const int row = r0 + i * 64;
            const uint32_t soff = (uint32_t)row * ROWB + ((uint32_t)ch0 << 1);
            const size_t ga = (size_t)(m0 + row) * GK + k0 + ch0;
            const size_t gb = (size_t)(n0 + row) * GK + k0 + ch0;
            cp16(sbase + OFF_AH + soff, Ah + ga);
            cp16(sbase + OFF_AL + soff, Al + ga);
            cp16(sbase + OFF_BH + soff, Bh + gb);
            cp16(sbase + OFF_BL + soff, Bl + gb);
        }
        asm volatile("cp.async.commit_group;");
    };

    issue(0);

    for (int t = 0; t < NT; t++) {
        if (t + 1 < NT) issue(t + 1);
        if (t + 1 < NT) { asm volatile("cp.async.wait_group 1;"); }
        else            { asm volatile("cp.async.wait_group 0;"); }
        __syncthreads();

        const uint32_t sbase = sb + (t & 1) * STG;
#pragma unroll
        for (int ks = 0; ks < 2; ks++) {
            uint32_t ah[2][4], al[2][4];
            const uint32_t kba = (uint32_t)(ks * 16 + akoff_l) << 1;
#pragma unroll
            for (int im = 0; im < 2; im++) {
                uint32_t ra = sbase + (uint32_t)(wm0 + im * 16 + arow_l) * ROWB + kba;
                ldm_x4(ah[im], ra + OFF_AH);
                ldm_x4(al[im], ra + OFF_AL);
            }
            const uint32_t kbb = (uint32_t)(ks * 16 + bkoff_l) << 1;
#pragma unroll
            for (int np = 0; np < 4; np++) {
                uint32_t rb = sbase + (uint32_t)(wn0 + np * 16 + brow_l) * ROWB + kbb;
                uint32_t bh[4], bl[4];
                ldm_x4(bh, rb + OFF_BH);
                ldm_x4(bl, rb + OFF_BL);
#pragma unroll
                for (int im = 0; im < 2; im++) {
#pragma unroll
                    for (int ia = 0; ia < 2; ia++) {
                        float* c = acc[im][np * 2 + ia];
                        mma_bf16(c, ah[im], bh[2 * ia], bh[2 * ia + 1]);
                        mma_bf16(c, ah[im], bl[2 * ia], bl[2 * ia + 1]);
                        mma_bf16(c, al[im], bh[2 * ia], bh[2 * ia + 1]);
                    }
                }
            }
        }
        __syncthreads();
    }

    // ---- epilogue ----
#pragma unroll
    for (int im = 0; im < 2; im++) {
        const int rbase = m0 + wm0 + im * 16 + (lane >> 2);
#pragma unroll
        for (int j = 0; j < 8; j++) {
            const int col = n0 + wn0 + j * 8 + (lane & 3) * 2;
            float2 v0 = make_float2(acc[im][j][0], acc[im][j][1]);
            float2 v1 = make_float2(acc[im][j][2], acc[im][j][3]);
            *(float2*)(C + (size_t)rbase * N + col)       = v0;
            *(float2*)(C + (size_t)(rbase + 8) * N + col) = v1;
        }
    }
}

// ---------------- RoPE + layout transform -------------------------------------
__global__ __launch_bounds__(256) void rope_kernel(const int* __restrict__ pos_ids)
{
    const int s = blockIdx.x;
    const int b = blockIdx.y;
    const int t = threadIdx.x;

    __shared__ float cs[64], sn[64];
    if (t < 64) {
        double invf = exp(-((double)(2 * t) / (double)DH) * log(10000.0));
        double ang = (double)pos_ids[s] * invf;
        cs[t] = (float)cos(ang);
        sn[t] = (float)sin(ang);
    }
    __syncthreads();

    const float* qrow = g_qraw + (size_t)(b * SS + s) * (NH * DH);
    for (int idx = t; idx < NH * 64; idx += 256) {
        int h = idx >> 6, i = idx & 63;
        float x1 = qrow[h * DH + i];
        float x2 = qrow[h * DH + 64 + i];
        size_t base = (size_t)(b * NH + h) * DH * SS;
        g_qT[base + (size_t)i * SS + s]        = x1 * cs[i] - x2 * sn[i];
        g_qT[base + (size_t)(i + 64) * SS + s] = x2 * cs[i] + x1 * sn[i];
    }

    const float* krow = g_kraw + (size_t)(b * SS + s) * (KVH * DH);
    for (int idx = t; idx < KVH * 64; idx += 256) {
        int h = idx >> 6, i = idx & 63;
        float x1 = krow[h * DH + i];
        float x2 = krow[h * DH + 64 + i];
        size_t base = (size_t)(b * KVH + h) * DH * SS;
        g_kT[base + (size_t)i * SS + s]        = x1 * cs[i] - x2 * sn[i];
        g_kT[base + (size_t)(i + 64) * SS + s] = x2 * cs[i] + x1 * sn[i];
    }

    const float* vrow = g_vraw + (size_t)(b * SS + s) * (KVH * DH);
    for (int idx = t; idx < KVH * DH; idx += 256) {
        int h = idx >> 7, d = idx & 127;
        g_vv[((size_t)(b * KVH + h) * SS + s) * DH + d] = vrow[idx];
    }
}

// ---------------- flash attention (fp32, causal, GQA) --------------------------
#define ATM 64
#define ATN 64
#define TP 68
#define VP 132
#define ATT_SMEM ((128 * TP * 2 + ATN * VP + ATM * TP) * 4)

__global__ __launch_bounds__(256) void attn_kernel()
{
    extern __shared__ float sm[];
    float* Qt = sm;
    float* Kt = Qt + 128 * TP;
    float* Vs = Kt + 128 * TP;
    float* Ps = Vs + ATN * VP;

    const int qt = (int)gridDim.x - 1 - (int)blockIdx.x;
    const int h = blockIdx.y;
    const int b = blockIdx.z;
    const int kvh = h >> 2;

    const int tid = threadIdx.x;
    const int tx = tid & 15;
    const int ty = tid >> 4;
    const int q0 = qt * ATM;

    const float* qTb = g_qT + (size_t)(b * NH + h) * DH * SS;
    const float* kTb = g_kT + (size_t)(b * KVH + kvh) * DH * SS;
    const float* vb  = g_vv + (size_t)(b * KVH + kvh) * SS * DH;

    for (int i = tid; i < 128 * 16; i += 256) {
        int d = i >> 4, c4 = (i & 15) * 4;
        *(float4*)&Qt[d * TP + c4] = *(const float4*)(qTb + (size_t)d * SS + q0 + c4);
    }

    float acc[4][8];
#pragma unroll
    for (int r = 0; r < 4; r++)
#pragma unroll
        for (int c = 0; c < 8; c++) acc[r][c] = 0.0f;
    float m_run[4] = {-INFINITY, -INFINITY, -INFINITY, -INFINITY};
    float l_run[4] = {0.0f, 0.0f, 0.0f, 0.0f};

    const float scale = 0.08838834764831845f;
    const int ntiles = qt + 1;

    for (int kt = 0; kt < ntiles; kt++) {
        const int k0 = kt * ATN;
        __syncthreads();

        for (int i = tid; i < 128 * 16; i += 256) {
            int d = i >> 4, c4 = (i & 15) * 4;
            *(float4*)&Kt[d * TP + c4] = *(const float4*)(kTb + (size_t)d * SS + k0 + c4);
        }
        for (int i = tid; i < ATN * 32; i += 256) {
            int j = i >> 5, d4 = (i & 31) * 4;
            *(float4*)&Vs[j * VP + d4] = *(const float4*)(vb + (size_t)(k0 + j) * DH + d4);
        }
        __syncthreads();

        float s[4][4];
#pragma unroll
        for (int r = 0; r < 4; r++)
#pragma unroll
            for (int j = 0; j < 4; j++) s[r][j] = 0.0f;

#pragma unroll 8
        for (int d = 0; d < 128; d++) {
            float4 a  = *(const float4*)&Qt[d * TP + (ty << 2)];
            float4 kb = *(const float4*)&Kt[d * TP + (tx << 2)];
            s[0][0] = fmaf(a.x, kb.x, s[0][0]); s[0][1] = fmaf(a.x, kb.y, s[0][1]);
            s[0][2] = fmaf(a.x, kb.z, s[0][2]); s[0][3] = fmaf(a.x, kb.w, s[0][3]);
            s[1][0] = fmaf(a.y, kb.x, s[1][0]); s[1][1] = fmaf(a.y, kb.y, s[1][1]);
            s[1][2] = fmaf(a.y, kb.z, s[1][2]); s[1][3] = fmaf(a.y, kb.w, s[1][3]);
            s[2][0] = fmaf(a.z, kb.x, s[2][0]); s[2][1] = fmaf(a.z, kb.y, s[2][1]);
            s[2][2] = fmaf(a.z, kb.z, s[2][2]); s[2][3] = fmaf(a.z, kb.w, s[2][3]);
            s[3][0] = fmaf(a.w, kb.x, s[3][0]); s[3][1] = fmaf(a.w, kb.y, s[3][1]);
            s[3][2] = fmaf(a.w, kb.z, s[3][2]); s[3][3] = fmaf(a.w, kb.w, s[3][3]);
        }

        const bool diag = (kt == qt);
#pragma unroll
        for (int r = 0; r < 4; r++) {
#pragma unroll
            for (int j = 0; j < 4; j++) {
                float v = s[r][j] * scale;
                if (diag && (k0 + tx * 4 + j > q0 + ty * 4 + r)) v = -INFINITY;
                s[r][j] = v;
            }
        }

#pragma unroll
        for (int r = 0; r < 4; r++) {
            float mv = fmaxf(fmaxf(s[r][0], s[r][1]), fmaxf(s[r][2], s[r][3]));
#pragma unroll
            for (int off = 8; off > 0; off >>= 1)
                mv = fmaxf(mv, __shfl_xor_sync(0xffffffffu, mv, off));
            float mnew = fmaxf(m_run[r], mv);
            float e0 = __expf(s[r][0] - mnew);
            float e1 = __expf(s[r][1] - mnew);
            float e2 = __expf(s[r][2] - mnew);
            float e3 = __expf(s[r][3] - mnew);
            float sum = (e0 + e1) + (e2 + e3);
#pragma unroll
            for (int off = 8; off > 0; off >>= 1)
                sum += __shfl_xor_sync(0xffffffffu, sum, off);
            float corr = __expf(m_run[r] - mnew);
            l_run[r] = l_run[r] * corr + sum;
            m_run[r] = mnew;
#pragma unroll
            for (int c = 0; c < 8; c++) acc[r][c] *= corr;
            *(float4*)&Ps[(ty * 4 + r) * TP + tx * 4] = make_float4(e0, e1, e2, e3);
        }
        __syncthreads();

#pragma unroll 4
        for (int j = 0; j < ATN; j++) {
            float p[4];
#pragma unroll
            for (int r = 0; r < 4; r++) p[r] = Ps[(ty * 4 + r) * TP + j];
            float v[8];
            *(float4*)(v)     = *(const float4*)&Vs[j * VP + tx * 8];
            *(float4*)(v + 4) = *(const float4*)&Vs[j * VP + tx * 8 + 4];
#pragma unroll
            for (int r = 0; r < 4; r++)
#pragma unroll
                for (int c = 0; c < 8; c++)
                    acc[r][c] = fmaf(p[r], v[c], acc[r][c]);
        }
    }

    // epilogue: normalize, write bf16 hi/lo split for the Wo GEMM
#pragma unroll
    for (int r = 0; r < 4; r++) {
        float inv = 1.0f / l_run[r];
        int row = b * SS + q0 + ty * 4 + r;
        size_t off = (size_t)row * (NH * DH) + h * DH + tx * 8;
#pragma unroll
        for (int c = 0; c < 8; c += 2) {
            float v0 = acc[r][c] * inv;
            float v1 = acc[r][c + 1] * inv;
            __nv_bfloat162 hh, ll;
            hh.x = __float2bfloat16(v0);
            hh.y = __float2bfloat16(v1);
            ll.x = __float2bfloat16(v0 - __bfloat162float(hh.x));
            ll.y = __float2bfloat16(v1 - __bfloat162float(hh.y));
            *(__nv_bfloat162*)(g_atth + off + c) = hh;
            *(__nv_bfloat162*)(g_attl + off + c) = ll;
        }
    }
}

// ---------------- launch --------------------------------------------------------
extern "C" void kernel_launch(void* const* d_in, const int* in_sizes, int n_in,
                              void* d_out, int out_size)
{
    const float* x   = (const float*)d_in[0];
    // d_in[1] = mask (causal; handled analytically)
    const int*   pos = (const int*)d_in[2];
    const float* Wq  = (const float*)d_in[3];
    const float* Wk  = (const float*)d_in[4];
    const float* Wv  = (const float*)d_in[5];
    const float* Wo  = (const float*)d_in[6];
    float* out = (float*)d_out;

    float *qraw, *kraw, *vraw;
    cudaGetSymbolAddress((void**)&qraw, g_qraw);
    cudaGetSymbolAddress((void**)&kraw, g_kraw);
    cudaGetSymbolAddress((void**)&vraw, g_vraw);
    __nv_bfloat16 *xh, *xl, *wqh, *wql, *wkh, *wkl, *wvh, *wvl, *woh, *wol, *atth, *attl;
    cudaGetSymbolAddress((void**)&xh,  g_xh);
    cudaGetSymbolAddress((void**)&xl,  g_xl);
    cudaGetSymbolAddress((void**)&wqh, g_wqh);
    cudaGetSymbolAddress((void**)&wql, g_wql);
    cudaGetSymbolAddress((void**)&wkh, g_wkh);
    cudaGetSymbolAddress((void**)&wkl, g_wkl);
    cudaGetSymbolAddress((void**)&wvh, g_wvh);
    cudaGetSymbolAddress((void**)&wvl, g_wvl);
    cudaGetSymbolAddress((void**)&woh, g_woh);
    cudaGetSymbolAddress((void**)&wol, g_wol);
    cudaGetSymbolAddress((void**)&atth, g_atth);
    cudaGetSymbolAddress((void**)&attl, g_attl);

    cudaFuncSetAttribute(attn_kernel,
                         cudaFuncAttributeMaxDynamicSharedMemorySize, ATT_SMEM);
    cudaFuncSetAttribute(mm_bf16_kernel,
                         cudaFuncAttributeMaxDynamicSharedMemorySize, MM_SMEM);

    // split x into bf16 hi/lo
    split_kernel<<<(MROWS * DIM / 4 + 255) / 256, 256>>>(x, xh, xl, MROWS * DIM / 4);
    // transpose+split weights: [K][N] -> [N][K]
    splitT_kernel<<<dim3(DIM / 32, DIM / 32), dim3(32, 8)>>>(Wq, wqh, wql, DIM, DIM);
    splitT_kernel<<<dim3((KVH * DH) / 32, DIM / 32), dim3(32, 8)>>>(Wk, wkh, wkl, DIM, KVH * DH);
    splitT_kernel<<<dim3((KVH * DH) / 32, DIM / 32), dim3(32, 8)>>>(Wv, wvh, wvl, DIM, KVH * DH);
    splitT_kernel<<<dim3(DIM / 32, DIM / 32), dim3(32, 8)>>>(Wo, woh, wol, DIM, DIM);

    // QKV projections on tensor cores (mma.sync bf16, 3-pass compensated)
    mm_bf16_kernel<<<dim3((NH * DH) / 128, MROWS / 128), 256, MM_SMEM>>>(
        xh, xl, wqh, wql, qraw, NH * DH);
    mm_bf16_kernel<<<dim3((KVH * DH) / 128, MROWS / 128), 256, MM_SMEM>>>(
        xh, xl, wkh, wkl, kraw, KVH * DH);
    mm_bf16_kernel<<<dim3((KVH * DH) / 128, MROWS / 128), 256, MM_SMEM>>>(
        xh, xl, wvh, wvl, vraw, KVH * DH);

    // RoPE + transpose
    rope_kernel<<<dim3(SS, BB), 256>>>(pos);

    // attention
    attn_kernel<<<dim3(SS / ATM, NH, BB), 256, ATT_SMEM>>>();

    // output projection
    mm_bf16_kernel<<<dim3(DIM / 128, MROWS / 128), 256, MM_SMEM>>>(
        atth, attl, woh, wol, out, DIM);
}

// round 5
// speedup vs baseline: 3.1388x; 1.9275x over previous
#include <cuda_runtime.h>
#include <cuda_bf16.h>
#include <math.h>
#include <stdint.h>

// Problem constants
#define BB 2
#define SS 2048
#define DIM 2048
#define NH 16
#define KVH 4
#define DH 128
#define MROWS (BB * SS)   // 4096

// ---------------- scratch (device globals; no allocation allowed) -------------
__device__ float g_qraw[MROWS * (NH * DH)];
__device__ float g_kraw[MROWS * (KVH * DH)];
__device__ float g_vraw[MROWS * (KVH * DH)];

// attention operands, bf16 hi/lo, layout [b,h,s,d]
__device__ __nv_bfloat16 g_qah[BB * NH * SS * DH];
__device__ __nv_bfloat16 g_qal[BB * NH * SS * DH];
__device__ __nv_bfloat16 g_kbh[BB * KVH * SS * DH];
__device__ __nv_bfloat16 g_kbl[BB * KVH * SS * DH];
__device__ __nv_bfloat16 g_vbh[BB * KVH * SS * DH];
__device__ __nv_bfloat16 g_vbl[BB * KVH * SS * DH];

// bf16 hi/lo split operands for GEMMs
__device__ __nv_bfloat16 g_xh[MROWS * DIM];
__device__ __nv_bfloat16 g_xl[MROWS * DIM];
__device__ __nv_bfloat16 g_wqh[DIM * DIM];      // transposed [N][K]
__device__ __nv_bfloat16 g_wql[DIM * DIM];
__device__ __nv_bfloat16 g_wkh[(KVH*DH) * DIM];
__device__ __nv_bfloat16 g_wkl[(KVH*DH) * DIM];
__device__ __nv_bfloat16 g_wvh[(KVH*DH) * DIM];
__device__ __nv_bfloat16 g_wvl[(KVH*DH) * DIM];
__device__ __nv_bfloat16 g_woh[DIM * DIM];
__device__ __nv_bfloat16 g_wol[DIM * DIM];
__device__ __nv_bfloat16 g_atth[MROWS * (NH*DH)];
__device__ __nv_bfloat16 g_attl[MROWS * (NH*DH)];

// ---------------- PTX helpers ---------------------------------------------------
__device__ __forceinline__ uint32_t smem_u32(const void* p) {
    uint32_t a;
    asm("{ .reg .u64 t; cvta.to.shared.u64 t, %1; cvt.u32.u64 %0, t; }"
        : "=r"(a) : "l"(p));
    return a;
}

__device__ __forceinline__ void cp16(uint32_t dst, const void* src) {
    asm volatile("cp.async.cg.shared.global [%0], [%1], 16;\n"
                 :: "r"(dst), "l"(src));
}

__device__ __forceinline__ void ldm_x4(uint32_t r[4], uint32_t addr) {
    asm volatile("ldmatrix.sync.aligned.m8n8.x4.shared.b16 {%0,%1,%2,%3}, [%4];"
                 : "=r"(r[0]), "=r"(r[1]), "=r"(r[2]), "=r"(r[3]) : "r"(addr));
}

__device__ __forceinline__ void ldm_x4_t(uint32_t r[4], uint32_t addr) {
    asm volatile("ldmatrix.sync.aligned.m8n8.x4.trans.shared.b16 {%0,%1,%2,%3}, [%4];"
                 : "=r"(r[0]), "=r"(r[1]), "=r"(r[2]), "=r"(r[3]) : "r"(addr));
}

__device__ __forceinline__ void mma_bf16(float c[4], const uint32_t a[4],
                                         uint32_t b0, uint32_t b1) {
    asm volatile(
        "mma.sync.aligned.m16n8k16.row.col.f32.bf16.bf16.f32 "
        "{%0,%1,%2,%3}, {%4,%5,%6,%7}, {%8,%9}, {%0,%1,%2,%3};"
        : "+f"(c[0]), "+f"(c[1]), "+f"(c[2]), "+f"(c[3])
        : "r"(a[0]), "r"(a[1]), "r"(a[2]), "r"(a[3]), "r"(b0), "r"(b1));
}

// split two floats into packed bf16x2 hi + residual lo (x = low half = first elem)
__device__ __forceinline__ void split_pack(float a, float b, uint32_t& hi, uint32_t& lo) {
    __nv_bfloat162 h = __floats2bfloat162_rn(a, b);
    float fa = __bfloat162float(h.x), fb = __bfloat162float(h.y);
    __nv_bfloat162 l = __floats2bfloat162_rn(a - fa, b - fb);
    hi = *(uint32_t*)&h;
    lo = *(uint32_t*)&l;
}

// ---------------- fp32 -> bf16 hi/lo split -------------------------------------
__global__ __launch_bounds__(256) void split_kernel(
    const float* __restrict__ in, __nv_bfloat16* __restrict__ hi,
    __nv_bfloat16* __restrict__ lo, int n4)
{
    int i = blockIdx.x * blockDim.x + threadIdx.x;
    if (i >= n4) return;
    float4 v = ((const float4*)in)[i];
    uint32_t h0, l0, h1, l1;
    split_pack(v.x, v.y, h0, l0);
    split_pack(v.z, v.w, h1, l1);
    ((uint32_t*)hi)[2*i]   = h0;
    ((uint32_t*)hi)[2*i+1] = h1;
    ((uint32_t*)lo)[2*i]   = l0;
    ((uint32_t*)lo)[2*i+1] = l1;
}

// ---------------- fp32 [K][N] -> bf16 hi/lo transposed [N][K] -------------------
__global__ __launch_bounds__(256) void splitT_kernel(
    const float* __restrict__ W, __nv_bfloat16* __restrict__ Th,
    __nv_bfloat16* __restrict__ Tl, int K, int N)
{
    __shared__ float t[32][33];
    const int n0 = blockIdx.x * 32, k0 = blockIdx.y * 32;
    const int tx = threadIdx.x, ty = threadIdx.y;   // (32, 8)
    for (int i = ty; i < 32; i += 8)
        t[i][tx] = W[(size_t)(k0 + i) * N + n0 + tx];
    __syncthreads();
    for (int i = ty; i < 32; i += 8) {
        float v = t[tx][i];
        __nv_bfloat16 h = __float2bfloat16(v);
        Th[(size_t)(n0 + i) * K + k0 + tx] = h;
        Tl[(size_t)(n0 + i) * K + k0 + tx] = __float2bfloat16(v - __bfloat162float(h));
    }
}

// ---------------- bf16 mma.sync 3-pass GEMM ------------------------------------
#define GK 2048
#define ROWB 80
#define TILE_B (128 * ROWB)
#define OFF_AH 0
#define OFF_AL (1 * TILE_B)
#define OFF_BH (2 * TILE_B)
#define OFF_BL (3 * TILE_B)
#define STG (4 * TILE_B)
#define MM_SMEM (2 * STG)   // 81920

__global__ __launch_bounds__(256) void mm_bf16_kernel(
    const __nv_bfloat16* __restrict__ Ah, const __nv_bfloat16* __restrict__ Al,
    const __nv_bfloat16* __restrict__ Bh, const __nv_bfloat16* __restrict__ Bl,
    float* __restrict__ C, int N)
{
    extern __shared__ char smem[];
    const uint32_t sb = smem_u32(smem);
    const int tid = threadIdx.x;
    const int lane = tid & 31, warp = tid >> 5;
    const int m0 = blockIdx.y * 128, n0 = blockIdx.x * 128;
    const int wm0 = (warp >> 1) * 32;
    const int wn0 = (warp & 1) * 64;

    const int arow_l  = lane & 15;
    const int akoff_l = (lane >> 4) << 3;
    const int brow_l  = (lane & 7) + ((lane >> 4) << 3);
    const int bkoff_l = ((lane >> 3) & 1) << 3;

    const int r0 = tid >> 2;
    const int ch0 = (tid & 3) << 3;

    float acc[2][8][4];
#pragma unroll
    for (int im = 0; im < 2; im++)
#pragma unroll
        for (int j = 0; j < 8; j++)
#pragma unroll
            for (int c = 0; c < 4; c++) acc[im][j][c] = 0.0f;

    const int NT = GK / 32;

    auto issue = [&](int t) {
        const int k0 = t * 32;
        const uint32_t sbase = sb + (t & 1) * STG;
#pragma unroll
        for (int i = 0; i < 2; i++) {
            const int row = r0 + i * 64;
            const uint32_t soff = (uint32_t)row * ROWB + ((uint32_t)ch0 << 1);
            const size_t ga = (size_t)(m0 + row) * GK + k0 + ch0;
            const size_t gb = (size_t)(n0 + row) * GK + k0 + ch0;
            cp16(sbase + OFF_AH + soff, Ah + ga);
            cp16(sbase + OFF_AL + soff, Al + ga);
            cp16(sbase + OFF_BH + soff, Bh + gb);
            cp16(sbase + OFF_BL + soff, Bl + gb);
        }
        asm volatile("cp.async.commit_group;");
    };

    issue(0);

    for (int t = 0; t < NT; t++) {
        if (t + 1 < NT) issue(t + 1);
        if (t + 1 < NT) { asm volatile("cp.async.wait_group 1;"); }
        else            { asm volatile("cp.async.wait_group 0;"); }
        __syncthreads();

        const uint32_t sbase = sb + (t & 1) * STG;
#pragma unroll
        for (int ks = 0; ks < 2; ks++) {
            uint32_t ah[2][4], al[2][4];
            const uint32_t kba = (uint32_t)(ks * 16 + akoff_l) << 1;
#pragma unroll
            for (int im = 0; im < 2; im++) {
                uint32_t ra = sbase + (uint32_t)(wm0 + im * 16 + arow_l) * ROWB + kba;
                ldm_x4(ah[im], ra + OFF_AH);
                ldm_x4(al[im], ra + OFF_AL);
            }
            const uint32_t kbb = (uint32_t)(ks * 16 + bkoff_l) << 1;
#pragma unroll
            for (int np = 0; np < 4; np++) {
                uint32_t rb = sbase + (uint32_t)(wn0 + np * 16 + brow_l) * ROWB + kbb;
                uint32_t bh[4], bl[4];
                ldm_x4(bh, rb + OFF_BH);
                ldm_x4(bl, rb + OFF_BL);
#pragma unroll
                for (int im = 0; im < 2; im++) {
#pragma unroll
                    for (int ia = 0; ia < 2; ia++) {
                        float* c = acc[im][np * 2 + ia];
                        mma_bf16(c, ah[im], bh[2 * ia], bh[2 * ia + 1]);
                        mma_bf16(c, ah[im], bl[2 * ia], bl[2 * ia + 1]);
                        mma_bf16(c, al[im], bh[2 * ia], bh[2 * ia + 1]);
                    }
                }
            }
        }
        __syncthreads();
    }

#pragma unroll
    for (int im = 0; im < 2; im++) {
        const int rbase = m0 + wm0 + im * 16 + (lane >> 2);
#pragma unroll
        for (int j = 0; j < 8; j++) {
            const int col = n0 + wn0 + j * 8 + (lane & 3) * 2;
            float2 v0 = make_float2(acc[im][j][0], acc[im][j][1]);
            float2 v1 = make_float2(acc[im][j][2], acc[im][j][3]);
            *(float2*)(C + (size_t)rbase * N + col)       = v0;
            *(float2*)(C + (size_t)(rbase + 8) * N + col) = v1;
        }
    }
}

// ---------------- RoPE -> bf16 hi/lo [b,h,s,d] ---------------------------------
__global__ __launch_bounds__(256) void rope_kernel(const int* __restrict__ pos_ids)
{
    const int s = blockIdx.x;
    const int b = blockIdx.y;
    const int t = threadIdx.x;

    __shared__ float cs[64], sn[64];
    if (t < 64) {
        double invf = exp(-((double)(2 * t) / (double)DH) * log(10000.0));
        double ang = (double)pos_ids[s] * invf;
        cs[t] = (float)cos(ang);
        sn[t] = (float)sin(ang);
    }
    __syncthreads();

    const float qk_scale = 0.08838834764831845f;   // 1/sqrt(128), folded into Q

    const float* qrow = g_qraw + (size_t)(b * SS + s) * (NH * DH);
    for (int idx = t; idx < NH * 64; idx += 256) {
        int h = idx >> 6, i = idx & 63;
        float x1 = qrow[h * DH + i];
        float x2 = qrow[h * DH + 64 + i];
        float y1 = (x1 * cs[i] - x2 * sn[i]) * qk_scale;
        float y2 = (x2 * cs[i] + x1 * sn[i]) * qk_scale;
        size_t dst = ((size_t)(b * NH + h) * SS + s) * DH;
        __nv_bfloat16 h1 = __float2bfloat16(y1);
        __nv_bfloat16 h2 = __float2bfloat16(y2);
        g_qah[dst + i]      = h1;
        g_qal[dst + i]      = __float2bfloat16(y1 - __bfloat162float(h1));
        g_qah[dst + 64 + i] = h2;
        g_qal[dst + 64 + i] = __float2bfloat16(y2 - __bfloat162float(h2));
    }

    const float* krow = g_kraw + (size_t)(b * SS + s) * (KVH * DH);
    for (int idx = t; idx < KVH * 64; idx += 256) {
        int h = idx >> 6, i = idx & 63;
        float x1 = krow[h * DH + i];
        float x2 = krow[h * DH + 64 + i];
        float y1 = x1 * cs[i] - x2 * sn[i];
        float y2 = x2 * cs[i] + x1 * sn[i];
        size_t dst = ((size_t)(b * KVH + h) * SS + s) * DH;
        __nv_bfloat16 h1 = __float2bfloat16(y1);
        __nv_bfloat16 h2 = __float2bfloat16(y2);
        g_kbh[dst + i]      = h1;
        g_kbl[dst + i]      = __float2bfloat16(y1 - __bfloat162float(h1));
        g_kbh[dst + 64 + i] = h2;
        g_kbl[dst + 64 + i] = __float2bfloat16(y2 - __bfloat162float(h2));
    }

    const float* vrow = g_vraw + (size_t)(b * SS + s) * (KVH * DH);
    for (int idx = t; idx < KVH * DH; idx += 256) {
        int h = idx >> 7, d = idx & 127;
        float v = vrow[idx];
        size_t dst = ((size_t)(b * KVH + h) * SS + s) * DH + d;
        __nv_bfloat16 hv = __float2bfloat16(v);
        g_vbh[dst] = hv;
        g_vbl[dst] = __float2bfloat16(v - __bfloat162float(hv));
    }
}

// ---------------- flash attention (bf16 mma.sync 3-pass, causal, GQA) -----------
// CTA: 128 q rows x 64-key blocks. 8 warps x 16 q rows.
#define AQM 128
#define AKN 64
#define KROW 272                  // smem row stride bytes (256 data + 16 pad)
#define TB (AKN * KROW)           // 17408
#define AT_SMEM (8 * TB)          // 139264: 2 stages x (Kh,Kl,Vh,Vl)

__global__ __launch_bounds__(256) void attn_kernel()
{
    extern __shared__ char smc[];
    const uint32_t sb = smem_u32(smc);
    const int tid = threadIdx.x, lane = tid & 31, warp = tid >> 5;
    const int qt = (int)gridDim.x - 1 - (int)blockIdx.x;   // heavy tiles first
    const int h = blockIdx.y, b = blockIdx.z, kvh = h >> 2;
    const int q0 = qt * AQM;
    const int wm = warp * 16;

    const char* qhp = (const char*)(g_qah + ((size_t)(b * NH + h) * SS + q0) * DH);
    const char* qlp = (const char*)(g_qal + ((size_t)(b * NH + h) * SS + q0) * DH);
    const char* khp = (const char*)(g_kbh + (size_t)(b * KVH + kvh) * SS * DH);
    const char* klp = (const char*)(g_kbl + (size_t)(b * KVH + kvh) * SS * DH);
    const char* vhp = (const char*)(g_vbh + (size_t)(b * KVH + kvh) * SS * DH);
    const char* vlp = (const char*)(g_vbl + (size_t)(b * KVH + kvh) * SS * DH);

    // ---- stage Q (128x128 bf16 hi/lo) into smem, ldmatrix to registers --------
    for (int i = tid; i < 128 * 16; i += 256) {
        int row = i >> 4, ch = (i & 15) << 4;
        cp16(sb + (uint32_t)row * KROW + ch,          qhp + row * 256 + ch);
        cp16(sb + 2 * TB + (uint32_t)row * KROW + ch, qlp + row * 256 + ch);
    }
    asm volatile("cp.async.commit_group;");
    asm volatile("cp.async.wait_group 0;");
    __syncthreads();

    const int arow = lane & 15, akoff = (lane >> 4) << 3;
    uint32_t qfh[8][4], qfl[8][4];
#pragma unroll
    for (int kc = 0; kc < 8; kc++) {
        uint32_t ra = sb + (uint32_t)(wm + arow) * KROW + ((uint32_t)(kc * 16 + akoff) << 1);
        ldm_x4(qfh[kc], ra);
        ldm_x4(qfl[kc], ra + 2 * TB);
    }
    __syncthreads();   // staging area free for K/V now

    float oacc[16][4];
#pragma unroll
    for (int j = 0; j < 16; j++)
#pragma unroll
        for (int c = 0; c < 4; c++) oacc[j][c] = 0.0f;
    float mrun0 = -INFINITY, mrun1 = -INFINITY;
    float lrun0 = 0.0f, lrun1 = 0.0f;

    const int nblocks = 2 * (qt + 1);
    const int brow = (lane & 7) + ((lane >> 4) << 3);
    const int bkoff = ((lane >> 3) & 1) << 3;
    const int vrow = lane & 15, vcoff = (lane >> 4) << 3;

    auto issue = [&](int t) {
        const uint32_t base = sb + (uint32_t)(t & 1) * (4 * TB);
        const size_t g0 = (size_t)t * AKN * 256;
        for (int i = tid; i < AKN * 16; i += 256) {
            int row = i >> 4, ch = (i & 15) << 4;
            uint32_t soff = (uint32_t)row * KROW + ch;
            size_t goff = g0 + (size_t)row * 256 + ch;
            cp16(base + soff,          khp + goff);
            cp16(base + TB + soff,     klp + goff);
            cp16(base + 2 * TB + soff, vhp + goff);
            cp16(base + 3 * TB + soff, vlp + goff);
        }
        asm volatile("cp.async.commit_group;");
    };

    issue(0);

    for (int t = 0; t < nblocks; t++) {
        if (t + 1 < nblocks) { issue(t + 1); asm volatile("cp.async.wait_group 1;"); }
        else                 { asm volatile("cp.async.wait_group 0;"); }
        __syncthreads();
        const uint32_t base = sb + (uint32_t)(t & 1) * (4 * TB);

        // ---- S = Q K^T (3-pass compensated) -----------------------------------
        float sacc[8][4];
#pragma unroll
        for (int j = 0; j < 8; j++)
#pragma unroll
            for (int c = 0; c < 4; c++) sacc[j][c] = 0.0f;

#pragma unroll
        for (int kc = 0; kc < 8; kc++) {
            const uint32_t kb = (uint32_t)(kc * 16 + bkoff) << 1;
#pragma unroll
            for (int np = 0; np < 4; np++) {
                uint32_t rb = base + (uint32_t)(np * 16 + brow) * KROW + kb;
                uint32_t bh4[4], bl4[4];
                ldm_x4(bh4, rb);
                ldm_x4(bl4, rb + TB);
#pragma unroll
                for (int ia = 0; ia < 2; ia++) {
                    float* c = sacc[np * 2 + ia];
                    mma_bf16(c, qfh[kc], bh4[2 * ia], bh4[2 * ia + 1]);
                    mma_bf16(c, qfh[kc], bl4[2 * ia], bl4[2 * ia + 1]);
                    mma_bf16(c, qfl[kc], bh4[2 * ia], bh4[2 * ia + 1]);
                }
            }
        }

        // ---- causal mask (warp-uniform skip when fully unmasked) --------------
        const int k0 = t * AKN;
        if (k0 + AKN - 1 > q0 + wm) {
            const int r0 = q0 + wm + (lane >> 2);
#pragma unroll
            for (int j = 0; j < 8; j++) {
                int cb = k0 + j * 8 + ((lane & 3) << 1);
                if (cb     > r0)     sacc[j][0] = -INFINITY;
                if (cb + 1 > r0)     sacc[j][1] = -INFINITY;
                if (cb     > r0 + 8) sacc[j][2] = -INFINITY;
                if (cb + 1 > r0 + 8) sacc[j][3] = -INFINITY;
            }
        }

        // ---- online softmax (rows r0 = lane>>2, r1 = r0+8 within warp tile) ---
        float mx0 = -INFINITY, mx1 = -INFINITY;
#pragma unroll
        for (int j = 0; j < 8; j++) {
            mx0 = fmaxf(mx0, fmaxf(sacc[j][0], sacc[j][1]));
            mx1 = fmaxf(mx1, fmaxf(sacc[j][2], sacc[j][3]));
        }
        mx0 = fmaxf(mx0, __shfl_xor_sync(0xffffffffu, mx0, 1));
        mx0 = fmaxf(mx0, __shfl_xor_sync(0xffffffffu, mx0, 2));
        mx1 = fmaxf(mx1, __shfl_xor_sync(0xffffffffu, mx1, 1));
        mx1 = fmaxf(mx1, __shfl_xor_sync(0xffffffffu, mx1, 2));
        float mn0 = fmaxf(mrun0, mx0), mn1 = fmaxf(mrun1, mx1);

        float sum0 = 0.0f, sum1 = 0.0f;
#pragma unroll
        for (int j = 0; j < 8; j++) {
            float e0 = __expf(sacc[j][0] - mn0);
            float e1 = __expf(sacc[j][1] - mn0);
            float e2 = __expf(sacc[j][2] - mn1);
            float e3 = __expf(sacc[j][3] - mn1);
            sacc[j][0] = e0; sacc[j][1] = e1; sacc[j][2] = e2; sacc[j][3] = e3;
            sum0 += e0 + e1; sum1 += e2 + e3;
        }
        sum0 += __shfl_xor_sync(0xffffffffu, sum0, 1);
        sum0 += __shfl_xor_sync(0xffffffffu, sum0, 2);
        sum1 += __shfl_xor_sync(0xffffffffu, sum1, 1);
        sum1 += __shfl_xor_sync(0xffffffffu, sum1, 2);

        float c0 = __expf(mrun0 - mn0), c1 = __expf(mrun1 - mn1);
        lrun0 = lrun0 * c0 + sum0;
        lrun1 = lrun1 * c1 + sum1;
        mrun0 = mn0; mrun1 = mn1;
#pragma unroll
        for (int j = 0; j < 16; j++) {
            oacc[j][0] *= c0; oacc[j][1] *= c0;
            oacc[j][2] *= c1; oacc[j][3] *= c1;
        }

        // ---- O += P V (3-pass compensated, P from registers) ------------------
#pragma unroll
        for (int kc = 0; kc < 4; kc++) {
            uint32_t pah[4], pal[4];
            split_pack(sacc[2*kc][0],   sacc[2*kc][1],   pah[0], pal[0]);
            split_pack(sacc[2*kc][2],   sacc[2*kc][3],   pah[1], pal[1]);
            split_pack(sacc[2*kc+1][0], sacc[2*kc+1][1], pah[2], pal[2]);
            split_pack(sacc[2*kc+1][2], sacc[2*kc+1][3], pah[3], pal[3]);
#pragma unroll
            for (int nd = 0; nd < 8; nd++) {
                uint32_t rv = base + 2 * TB + (uint32_t)(kc * 16 + vrow) * KROW
                              + ((uint32_t)(nd * 16 + vcoff) << 1);
                uint32_t vh4[4], vl4[4];
                ldm_x4_t(vh4, rv);
                ldm_x4_t(vl4, rv + TB);
#pragma unroll
                for (int ia = 0; ia < 2; ia++) {
                    float* o = oacc[nd * 2 + ia];
                    mma_bf16(o, pah, vh4[2 * ia], vh4[2 * ia + 1]);
                    mma_bf16(o, pah, vl4[2 * ia], vl4[2 * ia + 1]);
                    mma_bf16(o, pal, vh4[2 * ia], vh4[2 * ia + 1]);
                }
            }
        }
        __syncthreads();
    }

    // ---- epilogue: normalize, write bf16 hi/lo for the Wo GEMM -----------------
    const float inv0 = 1.0f / lrun0, inv1 = 1.0f / lrun1;
    const size_t r0 = (size_t)(b * SS + q0 + wm + (lane >> 2)) * (NH * DH)
                      + h * DH + ((lane & 3) << 1);
    const size_t r1 = r0 + (size_t)8 * (NH * DH);
#pragma unroll
    for (int nd = 0; nd < 16; nd++) {
        uint32_t h0, l0, h1, l1;
        split_pack(oacc[nd][0] * inv0, oacc[nd][1] * inv0, h0, l0);
        split_pack(oacc[nd][2] * inv1, oacc[nd][3] * inv1, h1, l1);
        *(uint32_t*)(g_atth + r0 + nd * 8) = h0;
        *(uint32_t*)(g_attl + r0 + nd * 8) = l0;
        *(uint32_t*)(g_atth + r1 + nd * 8) = h1;
        *(uint32_t*)(g_attl + r1 + nd * 8) = l1;
    }
}

// ---------------- launch --------------------------------------------------------
extern "C" void kernel_launch(void* const* d_in, const int* in_sizes, int n_in,
                              void* d_out, int out_size)
{
    const float* x   = (const float*)d_in[0];
    // d_in[1] = mask (causal; handled analytically)
    const int*   pos = (const int*)d_in[2];
    const float* Wq  = (const float*)d_in[3];
    const float* Wk  = (const float*)d_in[4];
    const float* Wv  = (const float*)d_in[5];
    const float* Wo  = (const float*)d_in[6];
    float* out = (float*)d_out;

    float *qraw, *kraw, *vraw;
    cudaGetSymbolAddress((void**)&qraw, g_qraw);
    cudaGetSymbolAddress((void**)&kraw, g_kraw);
    cudaGetSymbolAddress((void**)&vraw, g_vraw);
    __nv_bfloat16 *xh, *xl, *wqh, *wql, *wkh, *wkl, *wvh, *wvl, *woh, *wol, *atth, *attl;
    cudaGetSymbolAddress((void**)&xh,  g_xh);
    cudaGetSymbolAddress((void**)&xl,  g_xl);
    cudaGetSymbolAddress((void**)&wqh, g_wqh);
    cudaGetSymbolAddress((void**)&wql, g_wql);
    cudaGetSymbolAddress((void**)&wkh, g_wkh);
    cudaGetSymbolAddress((void**)&wkl, g_wkl);
    cudaGetSymbolAddress((void**)&wvh, g_wvh);
    cudaGetSymbolAddress((void**)&wvl, g_wvl);
    cudaGetSymbolAddress((void**)&woh, g_woh);
    cudaGetSymbolAddress((void**)&wol, g_wol);
    cudaGetSymbolAddress((void**)&atth, g_atth);
    cudaGetSymbolAddress((void**)&attl, g_attl);

    cudaFuncSetAttribute(attn_kernel,
                         cudaFuncAttributeMaxDynamicSharedMemorySize, AT_SMEM);
    cudaFuncSetAttribute(mm_bf16_kernel,
                         cudaFuncAttributeMaxDynamicSharedMemorySize, MM_SMEM);

    // split x into bf16 hi/lo
    split_kernel<<<(MROWS * DIM / 4 + 255) / 256, 256>>>(x, xh, xl, MROWS * DIM / 4);
    // transpose+split weights: [K][N] -> [N][K]
    splitT_kernel<<<dim3(DIM / 32, DIM / 32), dim3(32, 8)>>>(Wq, wqh, wql, DIM, DIM);
    splitT_kernel<<<dim3((KVH * DH) / 32, DIM / 32), dim3(32, 8)>>>(Wk, wkh, wkl, DIM, KVH * DH);
    splitT_kernel<<<dim3((KVH * DH) / 32, DIM / 32), dim3(32, 8)>>>(Wv, wvh, wvl, DIM, KVH * DH);
    splitT_kernel<<<dim3(DIM / 32, DIM / 32), dim3(32, 8)>>>(Wo, woh, wol, DIM, DIM);

    // QKV projections on tensor cores
    mm_bf16_kernel<<<dim3((NH * DH) / 128, MROWS / 128), 256, MM_SMEM>>>(
        xh, xl, wqh, wql, qraw, NH * DH);
    mm_bf16_kernel<<<dim3((KVH * DH) / 128, MROWS / 128), 256, MM_SMEM>>>(
        xh, xl, wkh, wkl, kraw, KVH * DH);
    mm_bf16_kernel<<<dim3((KVH * DH) / 128, MROWS / 128), 256, MM_SMEM>>>(
        xh, xl, wvh, wvl, vraw, KVH * DH);

    // RoPE -> bf16 hi/lo attention operands
    rope_kernel<<<dim3(SS, BB), 256>>>(pos);

    // attention on tensor cores
    attn_kernel<<<dim3(SS / AQM, NH, BB), 256, AT_SMEM>>>();

    // output projection
    mm_bf16_kernel<<<dim3(DIM / 128, MROWS / 128), 256, MM_SMEM>>>(
        atth, attl, woh, wol, out, DIM);
}

// round 6
// speedup vs baseline: 3.2491x; 1.0351x over previous
#include <cuda_runtime.h>
#include <cuda_bf16.h>
#include <math.h>
#include <stdint.h>

// Problem constants
#define BB 2
#define SS 2048
#define DIM 2048
#define NH 16
#define KVH 4
#define DH 128
#define MROWS (BB * SS)   // 4096

// ---------------- scratch (device globals; no allocation allowed) -------------
__device__ float g_qraw[MROWS * (NH * DH)];
__device__ float g_kraw[MROWS * (KVH * DH)];
__device__ float g_vraw[MROWS * (KVH * DH)];

// attention operands, bf16 hi/lo, layout [b,h,s,d]
__device__ __nv_bfloat16 g_qah[BB * NH * SS * DH];
__device__ __nv_bfloat16 g_qal[BB * NH * SS * DH];
__device__ __nv_bfloat16 g_kbh[BB * KVH * SS * DH];
__device__ __nv_bfloat16 g_kbl[BB * KVH * SS * DH];
__device__ __nv_bfloat16 g_vbh[BB * KVH * SS * DH];
__device__ __nv_bfloat16 g_vbl[BB * KVH * SS * DH];

// bf16 hi/lo split operands for GEMMs
__device__ __nv_bfloat16 g_xh[MROWS * DIM];
__device__ __nv_bfloat16 g_xl[MROWS * DIM];
__device__ __nv_bfloat16 g_wqh[DIM * DIM];      // transposed [N][K]
__device__ __nv_bfloat16 g_wql[DIM * DIM];
__device__ __nv_bfloat16 g_wkh[(KVH*DH) * DIM];
__device__ __nv_bfloat16 g_wkl[(KVH*DH) * DIM];
__device__ __nv_bfloat16 g_wvh[(KVH*DH) * DIM];
__device__ __nv_bfloat16 g_wvl[(KVH*DH) * DIM];
__device__ __nv_bfloat16 g_woh[DIM * DIM];
__device__ __nv_bfloat16 g_wol[DIM * DIM];
__device__ __nv_bfloat16 g_atth[MROWS * (NH*DH)];
__device__ __nv_bfloat16 g_attl[MROWS * (NH*DH)];

// ---------------- PTX helpers ---------------------------------------------------
__device__ __forceinline__ uint32_t smem_u32(const void* p) {
    uint32_t a;
    asm("{ .reg .u64 t; cvta.to.shared.u64 t, %1; cvt.u32.u64 %0, t; }"
        : "=r"(a) : "l"(p));
    return a;
}

__device__ __forceinline__ void cp16(uint32_t dst, const void* src) {
    asm volatile("cp.async.cg.shared.global [%0], [%1], 16;\n"
                 :: "r"(dst), "l"(src));
}

__device__ __forceinline__ void ldm_x4(uint32_t r[4], uint32_t addr) {
    asm volatile("ldmatrix.sync.aligned.m8n8.x4.shared.b16 {%0,%1,%2,%3}, [%4];"
                 : "=r"(r[0]), "=r"(r[1]), "=r"(r[2]), "=r"(r[3]) : "r"(addr));
}

__device__ __forceinline__ void ldm_x4_t(uint32_t r[4], uint32_t addr) {
    asm volatile("ldmatrix.sync.aligned.m8n8.x4.trans.shared.b16 {%0,%1,%2,%3}, [%4];"
                 : "=r"(r[0]), "=r"(r[1]), "=r"(r[2]), "=r"(r[3]) : "r"(addr));
}

__device__ __forceinline__ void mma_bf16(float c[4], const uint32_t a[4],
                                         uint32_t b0, uint32_t b1) {
    asm volatile(
        "mma.sync.aligned.m16n8k16.row.col.f32.bf16.bf16.f32 "
        "{%0,%1,%2,%3}, {%4,%5,%6,%7}, {%8,%9}, {%0,%1,%2,%3};"
        : "+f"(c[0]), "+f"(c[1]), "+f"(c[2]), "+f"(c[3])
        : "r"(a[0]), "r"(a[1]), "r"(a[2]), "r"(a[3]), "r"(b0), "r"(b1));
}

// split two floats into packed bf16x2 hi + residual lo (x = low half = first elem)
__device__ __forceinline__ void split_pack(float a, float b, uint32_t& hi, uint32_t& lo) {
    __nv_bfloat162 h = __floats2bfloat162_rn(a, b);
    float fa = __bfloat162float(h.x), fb = __bfloat162float(h.y);
    __nv_bfloat162 l = __floats2bfloat162_rn(a - fa, b - fb);
    hi = *(uint32_t*)&h;
    lo = *(uint32_t*)&l;
}

// ---------------- fp32 -> bf16 hi/lo split -------------------------------------
__global__ __launch_bounds__(256) void split_kernel(
    const float* __restrict__ in, __nv_bfloat16* __restrict__ hi,
    __nv_bfloat16* __restrict__ lo, int n4)
{
    int i = blockIdx.x * blockDim.x + threadIdx.x;
    if (i >= n4) return;
    float4 v = ((const float4*)in)[i];
    uint32_t h0, l0, h1, l1;
    split_pack(v.x, v.y, h0, l0);
    split_pack(v.z, v.w, h1, l1);
    ((uint32_t*)hi)[2*i]   = h0;
    ((uint32_t*)hi)[2*i+1] = h1;
    ((uint32_t*)lo)[2*i]   = l0;
    ((uint32_t*)lo)[2*i+1] = l1;
}

// ---------------- fp32 [K][N] -> bf16 hi/lo transposed [N][K] -------------------
__global__ __launch_bounds__(256) void splitT_kernel(
    const float* __restrict__ W, __nv_bfloat16* __restrict__ Th,
    __nv_bfloat16* __restrict__ Tl, int K, int N)
{
    __shared__ float t[32][33];
    const int n0 = blockIdx.x * 32, k0 = blockIdx.y * 32;
    const int tx = threadIdx.x, ty = threadIdx.y;   // (32, 8)
    for (int i = ty; i < 32; i += 8)
        t[i][tx] = W[(size_t)(k0 + i) * N + n0 + tx];
    __syncthreads();
    for (int i = ty; i < 32; i += 8) {
        float v = t[tx][i];
        __nv_bfloat16 h = __float2bfloat16(v);
        Th[(size_t)(n0 + i) * K + k0 + tx] = h;
        Tl[(size_t)(n0 + i) * K + k0 + tx] = __float2bfloat16(v - __bfloat162float(h));
    }
}

// ---------------- bf16 mma.sync 3-pass GEMM ------------------------------------
// 4 warps, warp tile 64x64; CTA 128x128, BK=32, double-buffered cp.async.
#define GK 2048
#define ROWB 80
#define TILE_B (128 * ROWB)
#define OFF_AH 0
#define OFF_AL (1 * TILE_B)
#define OFF_BH (2 * TILE_B)
#define OFF_BL (3 * TILE_B)
#define STG (4 * TILE_B)
#define MM_SMEM (2 * STG)   // 81920

__global__ __launch_bounds__(128) void mm_bf16_kernel(
    const __nv_bfloat16* __restrict__ Ah, const __nv_bfloat16* __restrict__ Al,
    const __nv_bfloat16* __restrict__ Bh, const __nv_bfloat16* __restrict__ Bl,
    float* __restrict__ C, int N)
{
    extern __shared__ char smem[];
    const uint32_t sb = smem_u32(smem);
    const int tid = threadIdx.x;
    const int lane = tid & 31, warp = tid >> 5;
    const int m0 = blockIdx.y * 128, n0 = blockIdx.x * 128;
    const int wm0 = (warp >> 1) * 64;       // 2x2 warp grid, warp tile 64x64
    const int wn0 = (warp & 1) * 64;

    const int arow_l  = lane & 15;
    const int akoff_l = (lane >> 4) << 3;
    const int brow_l  = (lane & 7) + ((lane >> 4) << 3);
    const int bkoff_l = ((lane >> 3) & 1) << 3;

    float acc[4][8][4];
#pragma unroll
    for (int im = 0; im < 4; im++)
#pragma unroll
        for (int j = 0; j < 8; j++)
#pragma unroll
            for (int c = 0; c < 4; c++) acc[im][j][c] = 0.0f;

    const int NT = GK / 32;

    auto issue = [&](int t) {
        const int k0 = t * 32;
        const uint32_t sbase = sb + (t & 1) * STG;
#pragma unroll
        for (int i = 0; i < 4; i++) {
            const int c = tid + (i << 7);        // 0..511
            const int row = c >> 2;              // 0..127
            const int off = (c & 3) << 3;        // elem offset 0,8,16,24
            const uint32_t soff = (uint32_t)row * ROWB + ((uint32_t)off << 1);
            const size_t ga = (size_t)(m0 + row) * GK + k0 + off;
            const size_t gb = (size_t)(n0 + row) * GK + k0 + off;
            cp16(sbase + OFF_AH + soff, Ah + ga);
            cp16(sbase + OFF_AL + soff, Al + ga);
            cp16(sbase + OFF_BH + soff, Bh + gb);
            cp16(sbase + OFF_BL + soff, Bl + gb);
        }
        asm volatile("cp.async.commit_group;");
    };

    issue(0);

    for (int t = 0; t < NT; t++) {
        if (t + 1 < NT) issue(t + 1);
        if (t + 1 < NT) { asm volatile("cp.async.wait_group 1;"); }
        else            { asm volatile("cp.async.wait_group 0;"); }
        __syncthreads();

        const uint32_t sbase = sb + (t & 1) * STG;
#pragma unroll
        for (int ks = 0; ks < 2; ks++) {
            uint32_t ah[4][4], al[4][4];
            const uint32_t kba = (uint32_t)(ks * 16 + akoff_l) << 1;
#pragma unroll
            for (int im = 0; im < 4; im++) {
                uint32_t ra = sbase + (uint32_t)(wm0 + im * 16 + arow_l) * ROWB + kba;
                ldm_x4(ah[im], ra + OFF_AH);
                ldm_x4(al[im], ra + OFF_AL);
            }
            const uint32_t kbb = (uint32_t)(ks * 16 + bkoff_l) << 1;
#pragma unroll
            for (int np = 0; np < 4; np++) {
                uint32_t rb = sbase + (uint32_t)(wn0 + np * 16 + brow_l) * ROWB + kbb;
                uint32_t bh[4], bl[4];
                ldm_x4(bh, rb + OFF_BH);
                ldm_x4(bl, rb + OFF_BL);
#pragma unroll
                for (int im = 0; im < 4; im++) {
#pragma unroll
                    for (int ia = 0; ia < 2; ia++) {
                        float* c = acc[im][np * 2 + ia];
                        mma_bf16(c, ah[im], bh[2 * ia], bh[2 * ia + 1]);
                        mma_bf16(c, ah[im], bl[2 * ia], bl[2 * ia + 1]);
                        mma_bf16(c, al[im], bh[2 * ia], bh[2 * ia + 1]);
                    }
                }
            }
        }
        __syncthreads();
    }

#pragma unroll
    for (int im = 0; im < 4; im++) {
        const int rbase = m0 + wm0 + im * 16 + (lane >> 2);
#pragma unroll
        for (int j = 0; j < 8; j++) {
            const int col = n0 + wn0 + j * 8 + (lane & 3) * 2;
            float2 v0 = make_float2(acc[im][j][0], acc[im][j][1]);
            float2 v1 = make_float2(acc[im][j][2], acc[im][j][3]);
            *(float2*)(C + (size_t)rbase * N + col)       = v0;
            *(float2*)(C + (size_t)(rbase + 8) * N + col) = v1;
        }
    }
}

// ---------------- RoPE -> bf16 hi/lo [b,h,s,d] ---------------------------------
__global__ __launch_bounds__(256) void rope_kernel(const int* __restrict__ pos_ids)
{
    const int s = blockIdx.x;
    const int b = blockIdx.y;
    const int t = threadIdx.x;

    __shared__ float cs[64], sn[64];
    if (t < 64) {
        double invf = exp(-((double)(2 * t) / (double)DH) * log(10000.0));
        double ang = (double)pos_ids[s] * invf;
        cs[t] = (float)cos(ang);
        sn[t] = (float)sin(ang);
    }
    __syncthreads();

    const float qk_scale = 0.08838834764831845f;   // 1/sqrt(128), folded into Q

    const float* qrow = g_qraw + (size_t)(b * SS + s) * (NH * DH);
    for (int idx = t; idx < NH * 64; idx += 256) {
        int h = idx >> 6, i = idx & 63;
        float x1 = qrow[h * DH + i];
        float x2 = qrow[h * DH + 64 + i];
        float y1 = (x1 * cs[i] - x2 * sn[i]) * qk_scale;
        float y2 = (x2 * cs[i] + x1 * sn[i]) * qk_scale;
        size_t dst = ((size_t)(b * NH + h) * SS + s) * DH;
        __nv_bfloat16 h1 = __float2bfloat16(y1);
        __nv_bfloat16 h2 = __float2bfloat16(y2);
        g_qah[dst + i]      = h1;
        g_qal[dst + i]      = __float2bfloat16(y1 - __bfloat162float(h1));
        g_qah[dst + 64 + i] = h2;
        g_qal[dst + 64 + i] = __float2bfloat16(y2 - __bfloat162float(h2));
    }

    const float* krow = g_kraw + (size_t)(b * SS + s) * (KVH * DH);
    for (int idx = t; idx < KVH * 64; idx += 256) {
        int h = idx >> 6, i = idx & 63;
        float x1 = krow[h * DH + i];
        float x2 = krow[h * DH + 64 + i];
        float y1 = x1 * cs[i] - x2 * sn[i];
        float y2 = x2 * cs[i] + x1 * sn[i];
        size_t dst = ((size_t)(b * KVH + h) * SS + s) * DH;
        __nv_bfloat16 h1 = __float2bfloat16(y1);
        __nv_bfloat16 h2 = __float2bfloat16(y2);
        g_kbh[dst + i]      = h1;
        g_kbl[dst + i]      = __float2bfloat16(y1 - __bfloat162float(h1));
        g_kbh[dst + 64 + i] = h2;
        g_kbl[dst + 64 + i] = __float2bfloat16(y2 - __bfloat162float(h2));
    }

    const float* vrow = g_vraw + (size_t)(b * SS + s) * (KVH * DH);
    for (int idx = t; idx < KVH * DH; idx += 256) {
        int h = idx >> 7, d = idx & 127;
        float v = vrow[idx];
        size_t dst = ((size_t)(b * KVH + h) * SS + s) * DH + d;
        __nv_bfloat16 hv = __float2bfloat16(v);
        g_vbh[dst] = hv;
        g_vbl[dst] = __float2bfloat16(v - __bfloat162float(hv));
    }
}

// ---------------- flash attention (bf16 mma.sync 3-pass, causal, GQA) -----------
// CTA: 128 q rows x 64-key blocks. 8 warps x 16 q rows.
#define AQM 128
#define AKN 64
#define KROW 272                  // smem row stride bytes (256 data + 16 pad)
#define TB (AKN * KROW)           // 17408
#define AT_SMEM (8 * TB)          // 139264: 2 stages x (Kh,Kl,Vh,Vl)

__global__ __launch_bounds__(256) void attn_kernel()
{
    extern __shared__ char smc[];
    const uint32_t sb = smem_u32(smc);
    const int tid = threadIdx.x, lane = tid & 31, warp = tid >> 5;
    const int qt = (int)gridDim.x - 1 - (int)blockIdx.x;   // heavy tiles first
    const int h = blockIdx.y, b = blockIdx.z, kvh = h >> 2;
    const int q0 = qt * AQM;
    const int wm = warp * 16;

    const char* qhp = (const char*)(g_qah + ((size_t)(b * NH + h) * SS + q0) * DH);
    const char* qlp = (const char*)(g_qal + ((size_t)(b * NH + h) * SS + q0) * DH);
    const char* khp = (const char*)(g_kbh + (size_t)(b * KVH + kvh) * SS * DH);
    const char* klp = (const char*)(g_kbl + (size_t)(b * KVH + kvh) * SS * DH);
    const char* vhp = (const char*)(g_vbh + (size_t)(b * KVH + kvh) * SS * DH);
    const char* vlp = (const char*)(g_vbl + (size_t)(b * KVH + kvh) * SS * DH);

    // ---- stage Q (128x128 bf16 hi/lo) into smem, ldmatrix to registers --------
    for (int i = tid; i < 128 * 16; i += 256) {
        int row = i >> 4, ch = (i & 15) << 4;
        cp16(sb + (uint32_t)row * KROW + ch,          qhp + row * 256 + ch);
        cp16(sb + 2 * TB + (uint32_t)row * KROW + ch, qlp + row * 256 + ch);
    }
    asm volatile("cp.async.commit_group;");
    asm volatile("cp.async.wait_group 0;");
    __syncthreads();

    const int arow = lane & 15, akoff = (lane >> 4) << 3;
    uint32_t qfh[8][4], qfl[8][4];
#pragma unroll
    for (int kc = 0; kc < 8; kc++) {
        uint32_t ra = sb + (uint32_t)(wm + arow) * KROW + ((uint32_t)(kc * 16 + akoff) << 1);
        ldm_x4(qfh[kc], ra);
        ldm_x4(qfl[kc], ra + 2 * TB);
    }
    __syncthreads();   // staging area free for K/V now

    float oacc[16][4];
#pragma unroll
    for (int j = 0; j < 16; j++)
#pragma unroll
        for (int c = 0; c < 4; c++) oacc[j][c] = 0.0f;
    float mrun0 = -INFINITY, mrun1 = -INFINITY;
    float lrun0 = 0.0f, lrun1 = 0.0f;

    const int nblocks = 2 * (qt + 1);
    const int brow = (lane & 7) + ((lane >> 4) << 3);
    const int bkoff = ((lane >> 3) & 1) << 3;
    const int vrow = lane & 15, vcoff = (lane >> 4) << 3;

    auto issue = [&](int t) {
        const uint32_t base = sb + (uint32_t)(t & 1) * (4 * TB);
        const size_t g0 = (size_t)t * AKN * 256;
        for (int i = tid; i < AKN * 16; i += 256) {
            int row = i >> 4, ch = (i & 15) << 4;
            uint32_t soff = (uint32_t)row * KROW + ch;
            size_t goff = g0 + (size_t)row * 256 + ch;
            cp16(base + soff,          khp + goff);
            cp16(base + TB + soff,     klp + goff);
            cp16(base + 2 * TB + soff, vhp + goff);
            cp16(base + 3 * TB + soff, vlp + goff);
        }
        asm volatile("cp.async.commit_group;");
    };

    issue(0);

    for (int t = 0; t < nblocks; t++) {
        if (t + 1 < nblocks) { issue(t + 1); asm volatile("cp.async.wait_group 1;"); }
        else                 { asm volatile("cp.async.wait_group 0;"); }
        __syncthreads();
        const uint32_t base = sb + (uint32_t)(t & 1) * (4 * TB);

        // ---- S = Q K^T (3-pass compensated) -----------------------------------
        float sacc[8][4];
#pragma unroll
        for (int j = 0; j < 8; j++)
#pragma unroll
            for (int c = 0; c < 4; c++) sacc[j][c] = 0.0f;

#pragma unroll
        for (int kc = 0; kc < 8; kc++) {
            const uint32_t kb = (uint32_t)(kc * 16 + bkoff) << 1;
#pragma unroll
            for (int np = 0; np < 4; np++) {
                uint32_t rb = base + (uint32_t)(np * 16 + brow) * KROW + kb;
                uint32_t bh4[4], bl4[4];
                ldm_x4(bh4, rb);
                ldm_x4(bl4, rb + TB);
#pragma unroll
                for (int ia = 0; ia < 2; ia++) {
                    float* c = sacc[np * 2 + ia];
                    mma_bf16(c, qfh[kc], bh4[2 * ia], bh4[2 * ia + 1]);
                    mma_bf16(c, qfh[kc], bl4[2 * ia], bl4[2 * ia + 1]);
                    mma_bf16(c, qfl[kc], bh4[2 * ia], bh4[2 * ia + 1]);
                }
            }
        }

        // ---- causal mask (warp-uniform skip when fully unmasked) --------------
        const int k0 = t * AKN;
        if (k0 + AKN - 1 > q0 + wm) {
            const int r0 = q0 + wm + (lane >> 2);
#pragma unroll
            for (int j = 0; j < 8; j++) {
                int cb = k0 + j * 8 + ((lane & 3) << 1);
                if (cb     > r0)     sacc[j][0] = -INFINITY;
                if (cb + 1 > r0)     sacc[j][1] = -INFINITY;
                if (cb     > r0 + 8) sacc[j][2] = -INFINITY;
                if (cb + 1 > r0 + 8) sacc[j][3] = -INFINITY;
            }
        }

        // ---- online softmax (rows r0 = lane>>2, r1 = r0+8 within warp tile) ---
        float mx0 = -INFINITY, mx1 = -INFINITY;
#pragma unroll
        for (int j = 0; j < 8; j++) {
            mx0 = fmaxf(mx0, fmaxf(sacc[j][0], sacc[j][1]));
            mx1 = fmaxf(mx1, fmaxf(sacc[j][2], sacc[j][3]));
        }
        mx0 = fmaxf(mx0, __shfl_xor_sync(0xffffffffu, mx0, 1));
        mx0 = fmaxf(mx0, __shfl_xor_sync(0xffffffffu, mx0, 2));
        mx1 = fmaxf(mx1, __shfl_xor_sync(0xffffffffu, mx1, 1));
        mx1 = fmaxf(mx1, __shfl_xor_sync(0xffffffffu, mx1, 2));
        float mn0 = fmaxf(mrun0, mx0), mn1 = fmaxf(mrun1, mx1);

        float sum0 = 0.0f, sum1 = 0.0f;
#pragma unroll
        for (int j = 0; j < 8; j++) {
            float e0 = __expf(sacc[j][0] - mn0);
            float e1 = __expf(sacc[j][1] - mn0);
            float e2 = __expf(sacc[j][2] - mn1);
            float e3 = __expf(sacc[j][3] - mn1);
            sacc[j][0] = e0; sacc[j][1] = e1; sacc[j][2] = e2; sacc[j][3] = e3;
            sum0 += e0 + e1; sum1 += e2 + e3;
        }
        sum0 += __shfl_xor_sync(0xffffffffu, sum0, 1);
        sum0 += __shfl_xor_sync(0xffffffffu, sum0, 2);
        sum1 += __shfl_xor_sync(0xffffffffu, sum1, 1);
        sum1 += __shfl_xor_sync(0xffffffffu, sum1, 2);

        float c0 = __expf(mrun0 - mn0), c1 = __expf(mrun1 - mn1);
        lrun0 = lrun0 * c0 + sum0;
        lrun1 = lrun1 * c1 + sum1;
        mrun0 = mn0; mrun1 = mn1;
#pragma unroll
        for (int j = 0; j < 16; j++) {
            oacc[j][0] *= c0; oacc[j][1] *= c0;
            oacc[j][2] *= c1; oacc[j][3] *= c1;
        }

        // ---- O += P V (3-pass compensated, P from registers) ------------------
#pragma unroll
        for (int kc = 0; kc < 4; kc++) {
            uint32_t pah[4], pal[4];
            split_pack(sacc[2*kc][0],   sacc[2*kc][1],   pah[0], pal[0]);
            split_pack(sacc[2*kc][2],   sacc[2*kc][3],   pah[1], pal[1]);
            split_pack(sacc[2*kc+1][0], sacc[2*kc+1][1], pah[2], pal[2]);
            split_pack(sacc[2*kc+1][2], sacc[2*kc+1][3], pah[3], pal[3]);
#pragma unroll
            for (int nd = 0; nd < 8; nd++) {
                uint32_t rv = base + 2 * TB + (uint32_t)(kc * 16 + vrow) * KROW
                              + ((uint32_t)(nd * 16 + vcoff) << 1);
                uint32_t vh4[4], vl4[4];
                ldm_x4_t(vh4, rv);
                ldm_x4_t(vl4, rv + TB);
#pragma unroll
                for (int ia = 0; ia < 2; ia++) {
                    float* o = oacc[nd * 2 + ia];
                    mma_bf16(o, pah, vh4[2 * ia], vh4[2 * ia + 1]);
                    mma_bf16(o, pah, vl4[2 * ia], vl4[2 * ia + 1]);
                    mma_bf16(o, pal, vh4[2 * ia], vh4[2 * ia + 1]);
                }
            }
        }
        __syncthreads();
    }

    // ---- epilogue: normalize, write bf16 hi/lo for the Wo GEMM -----------------
    const float inv0 = 1.0f / lrun0, inv1 = 1.0f / lrun1;
    const size_t r0 = (size_t)(b * SS + q0 + wm + (lane >> 2)) * (NH * DH)
                      + h * DH + ((lane & 3) << 1);
    const size_t r1 = r0 + (size_t)8 * (NH * DH);
#pragma unroll
    for (int nd = 0; nd < 16; nd++) {
        uint32_t h0, l0, h1, l1;
        split_pack(oacc[nd][0] * inv0, oacc[nd][1] * inv0, h0, l0);
        split_pack(oacc[nd][2] * inv1, oacc[nd][3] * inv1, h1, l1);
        *(uint32_t*)(g_atth + r0 + nd * 8) = h0;
        *(uint32_t*)(g_attl + r0 + nd * 8) = l0;
        *(uint32_t*)(g_atth + r1 + nd * 8) = h1;
        *(uint32_t*)(g_attl + r1 + nd * 8) = l1;
    }
}

// ---------------- launch --------------------------------------------------------
extern "C" void kernel_launch(void* const* d_in, const int* in_sizes, int n_in,
                              void* d_out, int out_size)
{
    const float* x   = (const float*)d_in[0];
    // d_in[1] = mask (causal; handled analytically)
    const int*   pos = (const int*)d_in[2];
    const float* Wq  = (const float*)d_in[3];
    const float* Wk  = (const float*)d_in[4];
    const float* Wv  = (const float*)d_in[5];
    const float* Wo  = (const float*)d_in[6];
    float* out = (float*)d_out;

    float *qraw, *kraw, *vraw;
    cudaGetSymbolAddress((void**)&qraw, g_qraw);
    cudaGetSymbolAddress((void**)&kraw, g_kraw);
    cudaGetSymbolAddress((void**)&vraw, g_vraw);
    __nv_bfloat16 *xh, *xl, *wqh, *wql, *wkh, *wkl, *wvh, *wvl, *woh, *wol, *atth, *attl;
    cudaGetSymbolAddress((void**)&xh,  g_xh);
    cudaGetSymbolAddress((void**)&xl,  g_xl);
    cudaGetSymbolAddress((void**)&wqh, g_wqh);
    cudaGetSymbolAddress((void**)&wql, g_wql);
    cudaGetSymbolAddress((void**)&wkh, g_wkh);
    cudaGetSymbolAddress((void**)&wkl, g_wkl);
    cudaGetSymbolAddress((void**)&wvh, g_wvh);
    cudaGetSymbolAddress((void**)&wvl, g_wvl);
    cudaGetSymbolAddress((void**)&woh, g_woh);
    cudaGetSymbolAddress((void**)&wol, g_wol);
    cudaGetSymbolAddress((void**)&atth, g_atth);
    cudaGetSymbolAddress((void**)&attl, g_attl);

    cudaFuncSetAttribute(attn_kernel,
                         cudaFuncAttributeMaxDynamicSharedMemorySize, AT_SMEM);
    cudaFuncSetAttribute(mm_bf16_kernel,
                         cudaFuncAttributeMaxDynamicSharedMemorySize, MM_SMEM);

    // split x into bf16 hi/lo
    split_kernel<<<(MROWS * DIM / 4 + 255) / 256, 256>>>(x, xh, xl, MROWS * DIM / 4);
    // transpose+split weights: [K][N] -> [N][K]
    splitT_kernel<<<dim3(DIM / 32, DIM / 32), dim3(32, 8)>>>(Wq, wqh, wql, DIM, DIM);
    splitT_kernel<<<dim3((KVH * DH) / 32, DIM / 32), dim3(32, 8)>>>(Wk, wkh, wkl, DIM, KVH * DH);
    splitT_kernel<<<dim3((KVH * DH) / 32, DIM / 32), dim3(32, 8)>>>(Wv, wvh, wvl, DIM, KVH * DH);
    splitT_kernel<<<dim3(DIM / 32, DIM / 32), dim3(32, 8)>>>(Wo, woh, wol, DIM, DIM);

    // QKV projections on tensor cores
    mm_bf16_kernel<<<dim3((NH * DH) / 128, MROWS / 128), 128, MM_SMEM>>>(
        xh, xl, wqh, wql, qraw, NH * DH);
    mm_bf16_kernel<<<dim3((KVH * DH) / 128, MROWS / 128), 128, MM_SMEM>>>(
        xh, xl, wkh, wkl, kraw, KVH * DH);
    mm_bf16_kernel<<<dim3((KVH * DH) / 128, MROWS / 128), 128, MM_SMEM>>>(
        xh, xl, wvh, wvl, vraw, KVH * DH);

    // RoPE -> bf16 hi/lo attention operands
    rope_kernel<<<dim3(SS, BB), 256>>>(pos);

    // attention on tensor cores
    attn_kernel<<<dim3(SS / AQM, NH, BB), 256, AT_SMEM>>>();

    // output projection
    mm_bf16_kernel<<<dim3(DIM / 128, MROWS / 128), 128, MM_SMEM>>>(
        atth, attl, woh, wol, out, DIM);
}

// round 7
// speedup vs baseline: 3.7079x; 1.1412x over previous
#include <cuda_runtime.h>
#include <cuda_bf16.h>
#include <cuda_fp16.h>
#include <math.h>
#include <stdint.h>

// Problem constants
#define BB 2
#define SS 2048
#define DIM 2048
#define NH 16
#define KVH 4
#define DH 128
#define MROWS (BB * SS)   // 4096
#define NQKV 3072         // fused QKV output width (2048 q + 512 k + 512 v)

// ---------------- scratch (device globals; no allocation allowed) -------------
__device__ float g_qkvraw[MROWS * NQKV];        // fused QKV projection output

// attention operands (fp16), layout [b,h,s,d]
__device__ __half g_qh16[BB * NH * SS * DH];    // Q hi
__device__ __half g_ql16[BB * NH * SS * DH];    // Q lo (residual)
__device__ __half g_k16[BB * KVH * SS * DH];    // K single fp16
__device__ __half g_v16[BB * KVH * SS * DH];    // V single fp16

// bf16 hi/lo split operands for GEMMs
__device__ __nv_bfloat16 g_xh[MROWS * DIM];
__device__ __nv_bfloat16 g_xl[MROWS * DIM];
__device__ __nv_bfloat16 g_wqkvh[NQKV * DIM];   // fused, transposed [N][K]
__device__ __nv_bfloat16 g_wqkvl[NQKV * DIM];
__device__ __nv_bfloat16 g_woh[DIM * DIM];
__device__ __nv_bfloat16 g_wol[DIM * DIM];
__device__ __nv_bfloat16 g_atth[MROWS * (NH*DH)];
__device__ __nv_bfloat16 g_attl[MROWS * (NH*DH)];

// ---------------- PTX helpers ---------------------------------------------------
__device__ __forceinline__ uint32_t smem_u32(const void* p) {
    uint32_t a;
    asm("{ .reg .u64 t; cvta.to.shared.u64 t, %1; cvt.u32.u64 %0, t; }"
        : "=r"(a) : "l"(p));
    return a;
}

__device__ __forceinline__ void cp16(uint32_t dst, const void* src) {
    asm volatile("cp.async.cg.shared.global [%0], [%1], 16;\n"
                 :: "r"(dst), "l"(src));
}

__device__ __forceinline__ void ldm_x4(uint32_t r[4], uint32_t addr) {
    asm volatile("ldmatrix.sync.aligned.m8n8.x4.shared.b16 {%0,%1,%2,%3}, [%4];"
                 : "=r"(r[0]), "=r"(r[1]), "=r"(r[2]), "=r"(r[3]) : "r"(addr));
}

__device__ __forceinline__ void ldm_x4_t(uint32_t r[4], uint32_t addr) {
    asm volatile("ldmatrix.sync.aligned.m8n8.x4.trans.shared.b16 {%0,%1,%2,%3}, [%4];"
                 : "=r"(r[0]), "=r"(r[1]), "=r"(r[2]), "=r"(r[3]) : "r"(addr));
}

__device__ __forceinline__ void mma_bf16(float c[4], const uint32_t a[4],
                                         uint32_t b0, uint32_t b1) {
    asm volatile(
        "mma.sync.aligned.m16n8k16.row.col.f32.bf16.bf16.f32 "
        "{%0,%1,%2,%3}, {%4,%5,%6,%7}, {%8,%9}, {%0,%1,%2,%3};"
        : "+f"(c[0]), "+f"(c[1]), "+f"(c[2]), "+f"(c[3])
        : "r"(a[0]), "r"(a[1]), "r"(a[2]), "r"(a[3]), "r"(b0), "r"(b1));
}

__device__ __forceinline__ void mma_f16(float c[4], const uint32_t a[4],
                                        uint32_t b0, uint32_t b1) {
    asm volatile(
        "mma.sync.aligned.m16n8k16.row.col.f32.f16.f16.f32 "
        "{%0,%1,%2,%3}, {%4,%5,%6,%7}, {%8,%9}, {%0,%1,%2,%3};"
        : "+f"(c[0]), "+f"(c[1]), "+f"(c[2]), "+f"(c[3])
        : "r"(a[0]), "r"(a[1]), "r"(a[2]), "r"(a[3]), "r"(b0), "r"(b1));
}

// split two floats into packed bf16x2 hi + residual lo
__device__ __forceinline__ void split_pack(float a, float b, uint32_t& hi, uint32_t& lo) {
    __nv_bfloat162 h = __floats2bfloat162_rn(a, b);
    float fa = __bfloat162float(h.x), fb = __bfloat162float(h.y);
    __nv_bfloat162 l = __floats2bfloat162_rn(a - fa, b - fb);
    hi = *(uint32_t*)&h;
    lo = *(uint32_t*)&l;
}

// split two floats into packed fp16x2 hi + residual lo
__device__ __forceinline__ void split_pack_h(float a, float b, uint32_t& hi, uint32_t& lo) {
    __half2 h = __floats2half2_rn(a, b);
    float fa = __half2float(__low2half(h)), fb = __half2float(__high2half(h));
    __half2 l = __floats2half2_rn(a - fa, b - fb);
    hi = *(uint32_t*)&h;
    lo = *(uint32_t*)&l;
}

// ---------------- fp32 -> bf16 hi/lo split -------------------------------------
__global__ __launch_bounds__(256) void split_kernel(
    const float* __restrict__ in, __nv_bfloat16* __restrict__ hi,
    __nv_bfloat16* __restrict__ lo, int n4)
{
    int i = blockIdx.x * blockDim.x + threadIdx.x;
    if (i >= n4) return;
    float4 v = ((const float4*)in)[i];
    uint32_t h0, l0, h1, l1;
    split_pack(v.x, v.y, h0, l0);
    split_pack(v.z, v.w, h1, l1);
    ((uint32_t*)hi)[2*i]   = h0;
    ((uint32_t*)hi)[2*i+1] = h1;
    ((uint32_t*)lo)[2*i]   = l0;
    ((uint32_t*)lo)[2*i+1] = l1;
}

// ---------------- fp32 [K][N] -> bf16 hi/lo transposed [N][K] -------------------
__global__ __launch_bounds__(256) void splitT_kernel(
    const float* __restrict__ W, __nv_bfloat16* __restrict__ Th,
    __nv_bfloat16* __restrict__ Tl, int K, int N)
{
    __shared__ float t[32][33];
    const int n0 = blockIdx.x * 32, k0 = blockIdx.y * 32;
    const int tx = threadIdx.x, ty = threadIdx.y;   // (32, 8)
    for (int i = ty; i < 32; i += 8)
        t[i][tx] = W[(size_t)(k0 + i) * N + n0 + tx];
    __syncthreads();
    for (int i = ty; i < 32; i += 8) {
        float v = t[tx][i];
        __nv_bfloat16 h = __float2bfloat16(v);
        Th[(size_t)(n0 + i) * K + k0 + tx] = h;
        Tl[(size_t)(n0 + i) * K + k0 + tx] = __float2bfloat16(v - __bfloat162float(h));
    }
}

// ---------------- bf16 mma.sync 3-pass GEMM ------------------------------------
// 4 warps, warp tile 64x64; CTA 128x128, BK=32, double-buffered cp.async.
#define GK 2048
#define ROWB 80
#define TILE_B (128 * ROWB)
#define OFF_AH 0
#define OFF_AL (1 * TILE_B)
#define OFF_BH (2 * TILE_B)
#define OFF_BL (3 * TILE_B)
#define STG (4 * TILE_B)
#define MM_SMEM (2 * STG)   // 81920

__global__ __launch_bounds__(128) void mm_bf16_kernel(
    const __nv_bfloat16* __restrict__ Ah, const __nv_bfloat16* __restrict__ Al,
    const __nv_bfloat16* __restrict__ Bh, const __nv_bfloat16* __restrict__ Bl,
    float* __restrict__ C, int N)
{
    extern __shared__ char smem[];
    const uint32_t sb = smem_u32(smem);
    const int tid = threadIdx.x;
    const int lane = tid & 31, warp = tid >> 5;
    const int m0 = blockIdx.y * 128, n0 = blockIdx.x * 128;
    const int wm0 = (warp >> 1) * 64;
    const int wn0 = (warp & 1) * 64;

    const int arow_l  = lane & 15;
    const int akoff_l = (lane >> 4) << 3;
    const int brow_l  = (lane & 7) + ((lane >> 4) << 3);
    const int bkoff_l = ((lane >> 3) & 1) << 3;

    float acc[4][8][4];
#pragma unroll
    for (int im = 0; im < 4; im++)
#pragma unroll
        for (int j = 0; j < 8; j++)
#pragma unroll
            for (int c = 0; c < 4; c++) acc[im][j][c] = 0.0f;

    const int NT = GK / 32;

    auto issue = [&](int t) {
        const int k0 = t * 32;
        const uint32_t sbase = sb + (t & 1) * STG;
#pragma unroll
        for (int i = 0; i < 4; i++) {
            const int c = tid + (i << 7);
            const int row = c >> 2;
            const int off = (c & 3) << 3;
            const uint32_t soff = (uint32_t)row * ROWB + ((uint32_t)off << 1);
            const size_t ga = (size_t)(m0 + row) * GK + k0 + off;
            const size_t gb = (size_t)(n0 + row) * GK + k0 + off;
            cp16(sbase + OFF_AH + soff, Ah + ga);
            cp16(sbase + OFF_AL + soff, Al + ga);
            cp16(sbase + OFF_BH + soff, Bh + gb);
            cp16(sbase + OFF_BL + soff, Bl + gb);
        }
        asm volatile("cp.async.commit_group;");
    };

    issue(0);

    for (int t = 0; t < NT; t++) {
        if (t + 1 < NT) issue(t + 1);
        if (t + 1 < NT) { asm volatile("cp.async.wait_group 1;"); }
        else            { asm volatile("cp.async.wait_group 0;"); }
        __syncthreads();

        const uint32_t sbase = sb + (t & 1) * STG;
#pragma unroll
        for (int ks = 0; ks < 2; ks++) {
            uint32_t ah[4][4], al[4][4];
            const uint32_t kba = (uint32_t)(ks * 16 + akoff_l) << 1;
#pragma unroll
            for (int im = 0; im < 4; im++) {
                uint32_t ra = sbase + (uint32_t)(wm0 + im * 16 + arow_l) * ROWB + kba;
                ldm_x4(ah[im], ra + OFF_AH);
                ldm_x4(al[im], ra + OFF_AL);
            }
            const uint32_t kbb = (uint32_t)(ks * 16 + bkoff_l) << 1;
#pragma unroll
            for (int np = 0; np < 4; np++) {
                uint32_t rb = sbase + (uint32_t)(wn0 + np * 16 + brow_l) * ROWB + kbb;
                uint32_t bh[4], bl[4];
                ldm_x4(bh, rb + OFF_BH);
                ldm_x4(bl, rb + OFF_BL);
#pragma unroll
                for (int im = 0; im < 4; im++) {
#pragma unroll
                    for (int ia = 0; ia < 2; ia++) {
                        float* c = acc[im][np * 2 + ia];
                        mma_bf16(c, ah[im], bh[2 * ia], bh[2 * ia + 1]);
                        mma_bf16(c, ah[im], bl[2 * ia], bl[2 * ia + 1]);
                        mma_bf16(c, al[im], bh[2 * ia], bh[2 * ia + 1]);
                    }
                }
            }
        }
        __syncthreads();
    }

#pragma unroll
    for (int im = 0; im < 4; im++) {
        const int rbase = m0 + wm0 + im * 16 + (lane >> 2);
#pragma unroll
        for (int j = 0; j < 8; j++) {
            const int col = n0 + wn0 + j * 8 + (lane & 3) * 2;
            float2 v0 = make_float2(acc[im][j][0], acc[im][j][1]);
            float2 v1 = make_float2(acc[im][j][2], acc[im][j][3]);
            *(float2*)(C + (size_t)rbase * N + col)       = v0;
            *(float2*)(C + (size_t)(rbase + 8) * N + col) = v1;
        }
    }
}

// ---------------- RoPE -> fp16 attention operands [b,h,s,d] --------------------
__global__ __launch_bounds__(256) void rope_kernel(const int* __restrict__ pos_ids)
{
    const int s = blockIdx.x;
    const int b = blockIdx.y;
    const int t = threadIdx.x;

    __shared__ float cs[64], sn[64];
    if (t < 64) {
        double invf = exp(-((double)(2 * t) / (double)DH) * log(10000.0));
        double ang = (double)pos_ids[s] * invf;
        cs[t] = (float)cos(ang);
        sn[t] = (float)sin(ang);
    }
    __syncthreads();

    const float qk_scale = 0.08838834764831845f;   // 1/sqrt(128), folded into Q
    const float* row = g_qkvraw + (size_t)(b * SS + s) * NQKV;

    // Q: fp16 hi/lo split
    for (int idx = t; idx < NH * 64; idx += 256) {
        int h = idx >> 6, i = idx & 63;
        float x1 = row[h * DH + i];
        float x2 = row[h * DH + 64 + i];
        float y1 = (x1 * cs[i] - x2 * sn[i]) * qk_scale;
        float y2 = (x2 * cs[i] + x1 * sn[i]) * qk_scale;
        size_t dst = ((size_t)(b * NH + h) * SS + s) * DH;
        __half h1 = __float2half_rn(y1);
        __half h2 = __float2half_rn(y2);
        g_qh16[dst + i]      = h1;
        g_ql16[dst + i]      = __float2half_rn(y1 - __half2float(h1));
        g_qh16[dst + 64 + i] = h2;
        g_ql16[dst + 64 + i] = __float2half_rn(y2 - __half2float(h2));
    }

    // K: single fp16
    const float* krow = row + 2048;
    for (int idx = t; idx < KVH * 64; idx += 256) {
        int h = idx >> 6, i = idx & 63;
        float x1 = krow[h * DH + i];
        float x2 = krow[h * DH + 64 + i];
        size_t dst = ((size_t)(b * KVH + h) * SS + s) * DH;
        g_k16[dst + i]      = __float2half_rn(x1 * cs[i] - x2 * sn[i]);
        g_k16[dst + 64 + i] = __float2half_rn(x2 * cs[i] + x1 * sn[i]);
    }

    // V: single fp16
    const float* vrow = row + 2560;
    for (int idx = t; idx < KVH * DH; idx += 256) {
        int h = idx >> 7, d = idx & 127;
        g_v16[((size_t)(b * KVH + h) * SS + s) * DH + d] = __float2half_rn(vrow[idx]);
    }
}

// ---------------- flash attention (fp16 mma.sync 2-pass, causal, GQA) -----------
// CTA: 128 q rows x 64-key blocks. 8 warps x 16 q rows.
#define AQM 128
#define AKN 64
#define KROW 272                  // smem row stride bytes (256 data + 16 pad)
#define TB (AKN * KROW)           // 17408
#define AT_SMEM (4 * TB)          // 69632: 2 stages x (K, V)

__global__ __launch_bounds__(256) void attn_kernel()
{
    extern __shared__ char smc[];
    const uint32_t sb = smem_u32(smc);
    const int tid = threadIdx.x, lane = tid & 31, warp = tid >> 5;
    const int qt = (int)gridDim.x - 1 - (int)blockIdx.x;   // heavy tiles first
    const int h = blockIdx.y, b = blockIdx.z, kvh = h >> 2;
    const int q0 = qt * AQM;
    const int wm = warp * 16;

    const char* qhp = (const char*)(g_qh16 + ((size_t)(b * NH + h) * SS + q0) * DH);
    const char* qlp = (const char*)(g_ql16 + ((size_t)(b * NH + h) * SS + q0) * DH);
    const char* kp  = (const char*)(g_k16 + (size_t)(b * KVH + kvh) * SS * DH);
    const char* vp  = (const char*)(g_v16 + (size_t)(b * KVH + kvh) * SS * DH);

    // ---- stage Q (128x128 fp16 hi/lo) into smem, ldmatrix to registers --------
    // qh occupies sb..sb+2TB, ql sb+2TB..sb+4TB (whole buffer, pre-loop only)
    for (int i = tid; i < 128 * 16; i += 256) {
        int row = i >> 4, ch = (i & 15) << 4;
        cp16(sb + (uint32_t)row * KROW + ch,          qhp + row * 256 + ch);
        cp16(sb + 2 * TB + (uint32_t)row * KROW + ch, qlp + row * 256 + ch);
    }
    asm volatile("cp.async.commit_group;");
    asm volatile("cp.async.wait_group 0;");
    __syncthreads();

    const int arow = lane & 15, akoff = (lane >> 4) << 3;
    uint32_t qfh[8][4], qfl[8][4];
#pragma unroll
    for (int kc = 0; kc < 8; kc++) {
        uint32_t ra = sb + (uint32_t)(wm + arow) * KROW + ((uint32_t)(kc * 16 + akoff) << 1);
        ldm_x4(qfh[kc], ra);
        ldm_x4(qfl[kc], ra + 2 * TB);
    }
    __syncthreads();   // staging area free for K/V now

    float oacc[16][4];
#pragma unroll
    for (int j = 0; j < 16; j++)
#pragma unroll
        for (int c = 0; c < 4; c++) oacc[j][c] = 0.0f;
    float mrun0 = -INFINITY, mrun1 = -INFINITY;
    float lrun0 = 0.0f, lrun1 = 0.0f;

    const int nblocks = 2 * (qt + 1);
    const int brow = (lane & 7) + ((lane >> 4) << 3);
    const int bkoff = ((lane >> 3) & 1) << 3;
    const int vrow = lane & 15, vcoff = (lane >> 4) << 3;

    auto issue = [&](int t) {
        const uint32_t base = sb + (uint32_t)(t & 1) * (2 * TB);
        const size_t g0 = (size_t)t * AKN * 256;
        for (int i = tid; i < AKN * 16; i += 256) {
            int row = i >> 4, ch = (i & 15) << 4;
            uint32_t soff = (uint32_t)row * KROW + ch;
            size_t goff = g0 + (size_t)row * 256 + ch;
            cp16(base + soff,      kp + goff);
            cp16(base + TB + soff, vp + goff);
        }
        asm volatile("cp.async.commit_group;");
    };

    issue(0);

    for (int t = 0; t < nblocks; t++) {
        if (t + 1 < nblocks) { issue(t + 1); asm volatile("cp.async.wait_group 1;"); }
        else                 { asm volatile("cp.async.wait_group 0;"); }
        __syncthreads();
        const uint32_t base = sb + (uint32_t)(t & 1) * (2 * TB);

        // ---- S = Q K^T (2-pass fp16: (Qh + Ql) x K) ---------------------------
        float sacc[8][4];
#pragma unroll
        for (int j = 0; j < 8; j++)
#pragma unroll
            for (int c = 0; c < 4; c++) sacc[j][c] = 0.0f;

#pragma unroll
        for (int kc = 0; kc < 8; kc++) {
            const uint32_t kb = (uint32_t)(kc * 16 + bkoff) << 1;
#pragma unroll
            for (int np = 0; np < 4; np++) {
                uint32_t rb = base + (uint32_t)(np * 16 + brow) * KROW + kb;
                uint32_t bh4[4];
                ldm_x4(bh4, rb);
#pragma unroll
                for (int ia = 0; ia < 2; ia++) {
                    float* c = sacc[np * 2 + ia];
                    mma_f16(c, qfh[kc], bh4[2 * ia], bh4[2 * ia + 1]);
                    mma_f16(c, qfl[kc], bh4[2 * ia], bh4[2 * ia + 1]);
                }
            }
        }

        // ---- causal mask (warp-uniform skip when fully unmasked) --------------
        const int k0 = t * AKN;
        if (k0 + AKN - 1 > q0 + wm) {
            const int r0 = q0 + wm + (lane >> 2);
#pragma unroll
            for (int j = 0; j < 8; j++) {
                int cb = k0 + j * 8 + ((lane & 3) << 1);
                if (cb     > r0)     sacc[j][0] = -INFINITY;
                if (cb + 1 > r0)     sacc[j][1] = -INFINITY;
                if (cb     > r0 + 8) sacc[j][2] = -INFINITY;
                if (cb + 1 > r0 + 8) sacc[j][3] = -INFINITY;
            }
        }

        // ---- online softmax ---------------------------------------------------
        float mx0 = -INFINITY, mx1 = -INFINITY;
#pragma unroll
        for (int j = 0; j < 8; j++) {
            mx0 = fmaxf(mx0, fmaxf(sacc[j][0], sacc[j][1]));
            mx1 = fmaxf(mx1, fmaxf(sacc[j][2], sacc[j][3]));
        }
        mx0 = fmaxf(mx0, __shfl_xor_sync(0xffffffffu, mx0, 1));
        mx0 = fmaxf(mx0, __shfl_xor_sync(0xffffffffu, mx0, 2));
        mx1 = fmaxf(mx1, __shfl_xor_sync(0xffffffffu, mx1, 1));
        mx1 = fmaxf(mx1, __shfl_xor_sync(0xffffffffu, mx1, 2));
        float mn0 = fmaxf(mrun0, mx0), mn1 = fmaxf(mrun1, mx1);

        float sum0 = 0.0f, sum1 = 0.0f;
#pragma unroll
        for (int j = 0; j < 8; j++) {
            float e0 = __expf(sacc[j][0] - mn0);
            float e1 = __expf(sacc[j][1] - mn0);
            float e2 = __expf(sacc[j][2] - mn1);
            float e3 = __expf(sacc[j][3] - mn1);
            sacc[j][0] = e0; sacc[j][1] = e1; sacc[j][2] = e2; sacc[j][3] = e3;
            sum0 += e0 + e1; sum1 += e2 + e3;
        }
        sum0 += __shfl_xor_sync(0xffffffffu, sum0, 1);
        sum0 += __shfl_xor_sync(0xffffffffu, sum0, 2);
        sum1 += __shfl_xor_sync(0xffffffffu, sum1, 1);
        sum1 += __shfl_xor_sync(0xffffffffu, sum1, 2);

        float c0 = __expf(mrun0 - mn0), c1 = __expf(mrun1 - mn1);
        lrun0 = lrun0 * c0 + sum0;
        lrun1 = lrun1 * c1 + sum1;
        mrun0 = mn0; mrun1 = mn1;
#pragma unroll
        for (int j = 0; j < 16; j++) {
            oacc[j][0] *= c0; oacc[j][1] *= c0;
            oacc[j][2] *= c1; oacc[j][3] *= c1;
        }

        // ---- O += P V (2-pass fp16: (Ph + Pl) x V) ----------------------------
#pragma unroll
        for (int kc = 0; kc < 4; kc++) {
            uint32_t pah[4], pal[4];
            split_pack_h(sacc[2*kc][0],   sacc[2*kc][1],   pah[0], pal[0]);
            split_pack_h(sacc[2*kc][2],   sacc[2*kc][3],   pah[1], pal[1]);
            split_pack_h(sacc[2*kc+1][0], sacc[2*kc+1][1], pah[2], pal[2]);
            split_pack_h(sacc[2*kc+1][2], sacc[2*kc+1][3], pah[3], pal[3]);
#pragma unroll
            for (int nd = 0; nd < 8; nd++) {
                uint32_t rv = base + TB + (uint32_t)(kc * 16 + vrow) * KROW
                              + ((uint32_t)(nd * 16 + vcoff) << 1);
                uint32_t vh4[4];
                ldm_x4_t(vh4, rv);
#pragma unroll
                for (int ia = 0; ia < 2; ia++) {
                    float* o = oacc[nd * 2 + ia];
                    mma_f16(o, pah, vh4[2 * ia], vh4[2 * ia + 1]);
                    mma_f16(o, pal, vh4[2 * ia], vh4[2 * ia + 1]);
                }
            }
        }
        __syncthreads();
    }

    // ---- epilogue: normalize, write bf16 hi/lo for the Wo GEMM -----------------
    const float inv0 = 1.0f / lrun0, inv1 = 1.0f / lrun1;
    const size_t r0 = (size_t)(b * SS + q0 + wm + (lane >> 2)) * (NH * DH)
                      + h * DH + ((lane & 3) << 1);
    const size_t r1 = r0 + (size_t)8 * (NH * DH);
#pragma unroll
    for (int nd = 0; nd < 16; nd++) {
        uint32_t h0, l0, h1, l1;
        split_pack(oacc[nd][0] * inv0, oacc[nd][1] * inv0, h0, l0);
        split_pack(oacc[nd][2] * inv1, oacc[nd][3] * inv1, h1, l1);
        *(uint32_t*)(g_atth + r0 + nd * 8) = h0;
        *(uint32_t*)(g_attl + r0 + nd * 8) = l0;
        *(uint32_t*)(g_atth + r1 + nd * 8) = h1;
        *(uint32_t*)(g_attl + r1 + nd * 8) = l1;
    }
}

// ---------------- launch --------------------------------------------------------
extern "C" void kernel_launch(void* const* d_in, const int* in_sizes, int n_in,
                              void* d_out, int out_size)
{
    const float* x   = (const float*)d_in[0];
    // d_in[1] = mask (causal; handled analytically)
    const int*   pos = (const int*)d_in[2];
    const float* Wq  = (const float*)d_in[3];
    const float* Wk  = (const float*)d_in[4];
    const float* Wv  = (const float*)d_in[5];
    const float* Wo  = (const float*)d_in[6];
    float* out = (float*)d_out;

    float* qkvraw;
    cudaGetSymbolAddress((void**)&qkvraw, g_qkvraw);
    __nv_bfloat16 *xh, *xl, *wqkvh, *wqkvl, *woh, *wol, *atth, *attl;
    cudaGetSymbolAddress((void**)&xh,    g_xh);
    cudaGetSymbolAddress((void**)&xl,    g_xl);
    cudaGetSymbolAddress((void**)&wqkvh, g_wqkvh);
    cudaGetSymbolAddress((void**)&wqkvl, g_wqkvl);
    cudaGetSymbolAddress((void**)&woh,   g_woh);
    cudaGetSymbolAddress((void**)&wol,   g_wol);
    cudaGetSymbolAddress((void**)&atth,  g_atth);
    cudaGetSymbolAddress((void**)&attl,  g_attl);

    cudaFuncSetAttribute(attn_kernel,
                         cudaFuncAttributeMaxDynamicSharedMemorySize, AT_SMEM);
    cudaFuncSetAttribute(mm_bf16_kernel,
                         cudaFuncAttributeMaxDynamicSharedMemorySize, MM_SMEM);

    // split x into bf16 hi/lo
    split_kernel<<<(MROWS * DIM / 4 + 255) / 256, 256>>>(x, xh, xl, MROWS * DIM / 4);
    // transpose+split weights into fused [3072][2048] (row offsets: q 0, k 2048, v 2560)
    splitT_kernel<<<dim3(DIM / 32, DIM / 32), dim3(32, 8)>>>(Wq, wqkvh, wqkvl, DIM, DIM);
    splitT_kernel<<<dim3((KVH * DH) / 32, DIM / 32), dim3(32, 8)>>>(
        Wk, wqkvh + (size_t)2048 * DIM, wqkvl + (size_t)2048 * DIM, DIM, KVH * DH);
    splitT_kernel<<<dim3((KVH * DH) / 32, DIM / 32), dim3(32, 8)>>>(
        Wv, wqkvh + (size_t)2560 * DIM, wqkvl + (size_t)2560 * DIM, DIM, KVH * DH);
    splitT_kernel<<<dim3(DIM / 32, DIM / 32), dim3(32, 8)>>>(Wo, woh, wol, DIM, DIM);

    // fused QKV projection on tensor cores (one launch, N=3072)
    mm_bf16_kernel<<<dim3(NQKV / 128, MROWS / 128), 128, MM_SMEM>>>(
        xh, xl, wqkvh, wqkvl, qkvraw, NQKV);

    // RoPE -> fp16 attention operands
    rope_kernel<<<dim3(SS, BB), 256>>>(pos);

    // attention on tensor cores (fp16 2-pass)
    attn_kernel<<<dim3(SS / AQM, NH, BB), 256, AT_SMEM>>>();

    // output projection
    mm_bf16_kernel<<<dim3(DIM / 128, MROWS / 128), 128, MM_SMEM>>>(
        atth, attl, woh, wol, out, DIM);
}

// round 8
// speedup vs baseline: 4.6229x; 1.2468x over previous
#include <cuda_runtime.h>
#include <cuda_bf16.h>
#include <cuda_fp16.h>
#include <math.h>
#include <stdint.h>

// Problem constants
#define BB 2
#define SS 2048
#define DIM 2048
#define NH 16
#define KVH 4
#define DH 128
#define MROWS (BB * SS)   // 4096
#define NQKV 3072         // fused QKV output width (2048 q + 512 k + 512 v)

// ---------------- scratch (device globals; no allocation allowed) -------------
__device__ float g_qkvraw[MROWS * NQKV];        // fused QKV projection output

// attention operands (fp16), layout [b,h,s,d]
__device__ __half g_qh16[BB * NH * SS * DH];    // Q hi
__device__ __half g_ql16[BB * NH * SS * DH];    // Q lo (residual)
__device__ __half g_k16[BB * KVH * SS * DH];    // K single fp16
__device__ __half g_v16[BB * KVH * SS * DH];    // V single fp16

// fp16 GEMM operands
__device__ __half g_x16[MROWS * DIM];           // x single fp16
__device__ __half g_wqkvh16[NQKV * DIM];        // fused W_qkv hi, transposed [N][K]
__device__ __half g_wqkvl16[NQKV * DIM];        // fused W_qkv lo
__device__ __half g_woh16[DIM * DIM];           // W_o hi, transposed [N][K]
__device__ __half g_wol16[DIM * DIM];           // W_o lo
__device__ __half g_att16[MROWS * (NH*DH)];     // attention output, single fp16

// ---------------- PTX helpers ---------------------------------------------------
__device__ __forceinline__ uint32_t smem_u32(const void* p) {
    uint32_t a;
    asm("{ .reg .u64 t; cvta.to.shared.u64 t, %1; cvt.u32.u64 %0, t; }"
        : "=r"(a) : "l"(p));
    return a;
}

__device__ __forceinline__ void cp16(uint32_t dst, const void* src) {
    asm volatile("cp.async.cg.shared.global [%0], [%1], 16;\n"
                 :: "r"(dst), "l"(src));
}

__device__ __forceinline__ void ldm_x4(uint32_t r[4], uint32_t addr) {
    asm volatile("ldmatrix.sync.aligned.m8n8.x4.shared.b16 {%0,%1,%2,%3}, [%4];"
                 : "=r"(r[0]), "=r"(r[1]), "=r"(r[2]), "=r"(r[3]) : "r"(addr));
}

__device__ __forceinline__ void ldm_x4_t(uint32_t r[4], uint32_t addr) {
    asm volatile("ldmatrix.sync.aligned.m8n8.x4.trans.shared.b16 {%0,%1,%2,%3}, [%4];"
                 : "=r"(r[0]), "=r"(r[1]), "=r"(r[2]), "=r"(r[3]) : "r"(addr));
}

__device__ __forceinline__ void mma_f16(float c[4], const uint32_t a[4],
                                        uint32_t b0, uint32_t b1) {
    asm volatile(
        "mma.sync.aligned.m16n8k16.row.col.f32.f16.f16.f32 "
        "{%0,%1,%2,%3}, {%4,%5,%6,%7}, {%8,%9}, {%0,%1,%2,%3};"
        : "+f"(c[0]), "+f"(c[1]), "+f"(c[2]), "+f"(c[3])
        : "r"(a[0]), "r"(a[1]), "r"(a[2]), "r"(a[3]), "r"(b0), "r"(b1));
}

// split two floats into packed fp16x2 hi + residual lo
__device__ __forceinline__ void split_pack_h(float a, float b, uint32_t& hi, uint32_t& lo) {
    __half2 h = __floats2half2_rn(a, b);
    float fa = __half2float(__low2half(h)), fb = __half2float(__high2half(h));
    __half2 l = __floats2half2_rn(a - fa, b - fb);
    hi = *(uint32_t*)&h;
    lo = *(uint32_t*)&l;
}

// ---------------- fp32 -> fp16 single convert ----------------------------------
__global__ __launch_bounds__(256) void cvt16_kernel(
    const float* __restrict__ in, __half* __restrict__ out, int n4)
{
    int i = blockIdx.x * blockDim.x + threadIdx.x;
    if (i >= n4) return;
    float4 v = ((const float4*)in)[i];
    __half2 a = __floats2half2_rn(v.x, v.y);
    __half2 b = __floats2half2_rn(v.z, v.w);
    ((__half2*)out)[2*i]   = a;
    ((__half2*)out)[2*i+1] = b;
}

// ---------------- fp32 [K][N] -> fp16 hi/lo transposed [N][K] -------------------
__global__ __launch_bounds__(256) void splitT16_kernel(
    const float* __restrict__ W, __half* __restrict__ Th,
    __half* __restrict__ Tl, int K, int N)
{
    __shared__ float t[32][33];
    const int n0 = blockIdx.x * 32, k0 = blockIdx.y * 32;
    const int tx = threadIdx.x, ty = threadIdx.y;   // (32, 8)
    for (int i = ty; i < 32; i += 8)
        t[i][tx] = W[(size_t)(k0 + i) * N + n0 + tx];
    __syncthreads();
    for (int i = ty; i < 32; i += 8) {
        float v = t[tx][i];
        __half h = __float2half_rn(v);
        Th[(size_t)(n0 + i) * K + k0 + tx] = h;
        Tl[(size_t)(n0 + i) * K + k0 + tx] = __float2half_rn(v - __half2float(h));
    }
}

// ---------------- fp16 mma.sync 2-pass GEMM ------------------------------------
// C[M,N] = A @ (Bh + Bl)^T.  A:[M][K] fp16 single, B:[N][K] fp16 hi/lo.
// 4 warps, warp tile 64x64; CTA 128x128, BK=32, double-buffered cp.async.
#define GK 2048
#define ROWB 80
#define TILE_B (128 * ROWB)
#define OFF_A  0
#define OFF_BH (1 * TILE_B)
#define OFF_BL (2 * TILE_B)
#define STG (3 * TILE_B)
#define MM_SMEM (2 * STG)   // 61440

__global__ __launch_bounds__(128) void mm_f16_kernel(
    const __half* __restrict__ A,
    const __half* __restrict__ Bh, const __half* __restrict__ Bl,
    float* __restrict__ C, int N)
{
    extern __shared__ char smem[];
    const uint32_t sb = smem_u32(smem);
    const int tid = threadIdx.x;
    const int lane = tid & 31, warp = tid >> 5;
    const int m0 = blockIdx.y * 128, n0 = blockIdx.x * 128;
    const int wm0 = (warp >> 1) * 64;
    const int wn0 = (warp & 1) * 64;

    const int arow_l  = lane & 15;
    const int akoff_l = (lane >> 4) << 3;
    const int brow_l  = (lane & 7) + ((lane >> 4) << 3);
    const int bkoff_l = ((lane >> 3) & 1) << 3;

    float acc[4][8][4];
#pragma unroll
    for (int im = 0; im < 4; im++)
#pragma unroll
        for (int j = 0; j < 8; j++)
#pragma unroll
            for (int c = 0; c < 4; c++) acc[im][j][c] = 0.0f;

    const int NT = GK / 32;

    auto issue = [&](int t) {
        const int k0 = t * 32;
        const uint32_t sbase = sb + (t & 1) * STG;
#pragma unroll
        for (int i = 0; i < 4; i++) {
            const int c = tid + (i << 7);
            const int row = c >> 2;
            const int off = (c & 3) << 3;
            const uint32_t soff = (uint32_t)row * ROWB + ((uint32_t)off << 1);
            const size_t ga = (size_t)(m0 + row) * GK + k0 + off;
            const size_t gb = (size_t)(n0 + row) * GK + k0 + off;
            cp16(sbase + OFF_A + soff,  A + ga);
            cp16(sbase + OFF_BH + soff, Bh + gb);
            cp16(sbase + OFF_BL + soff, Bl + gb);
        }
        asm volatile("cp.async.commit_group;");
    };

    issue(0);

    for (int t = 0; t < NT; t++) {
        if (t + 1 < NT) issue(t + 1);
        if (t + 1 < NT) { asm volatile("cp.async.wait_group 1;"); }
        else            { asm volatile("cp.async.wait_group 0;"); }
        __syncthreads();

        const uint32_t sbase = sb + (t & 1) * STG;
#pragma unroll
        for (int ks = 0; ks < 2; ks++) {
            uint32_t ah[4][4];
            const uint32_t kba = (uint32_t)(ks * 16 + akoff_l) << 1;
#pragma unroll
            for (int im = 0; im < 4; im++) {
                uint32_t ra = sbase + (uint32_t)(wm0 + im * 16 + arow_l) * ROWB + kba;
                ldm_x4(ah[im], ra + OFF_A);
            }
            const uint32_t kbb = (uint32_t)(ks * 16 + bkoff_l) << 1;
#pragma unroll
            for (int np = 0; np < 4; np++) {
                uint32_t rb = sbase + (uint32_t)(wn0 + np * 16 + brow_l) * ROWB + kbb;
                uint32_t bh[4], bl[4];
                ldm_x4(bh, rb + OFF_BH);
                ldm_x4(bl, rb + OFF_BL);
#pragma unroll
                for (int im = 0; im < 4; im++) {
#pragma unroll
                    for (int ia = 0; ia < 2; ia++) {
                        float* c = acc[im][np * 2 + ia];
                        mma_f16(c, ah[im], bh[2 * ia], bh[2 * ia + 1]);
                        mma_f16(c, ah[im], bl[2 * ia], bl[2 * ia + 1]);
                    }
                }
            }
        }
        __syncthreads();
    }

#pragma unroll
    for (int im = 0; im < 4; im++) {
        const int rbase = m0 + wm0 + im * 16 + (lane >> 2);
#pragma unroll
        for (int j = 0; j < 8; j++) {
            const int col = n0 + wn0 + j * 8 + (lane & 3) * 2;
            float2 v0 = make_float2(acc[im][j][0], acc[im][j][1]);
            float2 v1 = make_float2(acc[im][j][2], acc[im][j][3]);
            *(float2*)(C + (size_t)rbase * N + col)       = v0;
            *(float2*)(C + (size_t)(rbase + 8) * N + col) = v1;
        }
    }
}

// ---------------- RoPE -> fp16 attention operands [b,h,s,d] --------------------
__global__ __launch_bounds__(256) void rope_kernel(const int* __restrict__ pos_ids)
{
    const int s = blockIdx.x;
    const int b = blockIdx.y;
    const int t = threadIdx.x;

    __shared__ float cs[64], sn[64];
    if (t < 64) {
        double invf = exp(-((double)(2 * t) / (double)DH) * log(10000.0));
        double ang = (double)pos_ids[s] * invf;
        cs[t] = (float)cos(ang);
        sn[t] = (float)sin(ang);
    }
    __syncthreads();

    const float qk_scale = 0.08838834764831845f;   // 1/sqrt(128), folded into Q
    const float* row = g_qkvraw + (size_t)(b * SS + s) * NQKV;

    // Q: fp16 hi/lo split
    for (int idx = t; idx < NH * 64; idx += 256) {
        int h = idx >> 6, i = idx & 63;
        float x1 = row[h * DH + i];
        float x2 = row[h * DH + 64 + i];
        float y1 = (x1 * cs[i] - x2 * sn[i]) * qk_scale;
        float y2 = (x2 * cs[i] + x1 * sn[i]) * qk_scale;
        size_t dst = ((size_t)(b * NH + h) * SS + s) * DH;
        __half h1 = __float2half_rn(y1);
        __half h2 = __float2half_rn(y2);
        g_qh16[dst + i]      = h1;
        g_ql16[dst + i]      = __float2half_rn(y1 - __half2float(h1));
        g_qh16[dst + 64 + i] = h2;
        g_ql16[dst + 64 + i] = __float2half_rn(y2 - __half2float(h2));
    }

    // K: single fp16
    const float* krow = row + 2048;
    for (int idx = t; idx < KVH * 64; idx += 256) {
        int h = idx >> 6, i = idx & 63;
        float x1 = krow[h * DH + i];
        float x2 = krow[h * DH + 64 + i];
        size_t dst = ((size_t)(b * KVH + h) * SS + s) * DH;
        g_k16[dst + i]      = __float2half_rn(x1 * cs[i] - x2 * sn[i]);
        g_k16[dst + 64 + i] = __float2half_rn(x2 * cs[i] + x1 * sn[i]);
    }

    // V: single fp16
    const float* vrow = row + 2560;
    for (int idx = t; idx < KVH * DH; idx += 256) {
        int h = idx >> 7, d = idx & 127;
        g_v16[((size_t)(b * KVH + h) * SS + s) * DH + d] = __float2half_rn(vrow[idx]);
    }
}

// ---------------- flash attention (fp16 mma.sync 2-pass, causal, GQA) -----------
// CTA: 128 q rows x 64-key blocks. 8 warps x 16 q rows.
#define AQM 128
#define AKN 64
#define KROW 272                  // smem row stride bytes (256 data + 16 pad)
#define TB (AKN * KROW)           // 17408
#define AT_SMEM (4 * TB)          // 69632: 2 stages x (K, V)

__global__ __launch_bounds__(256) void attn_kernel()
{
    extern __shared__ char smc[];
    const uint32_t sb = smem_u32(smc);
    const int tid = threadIdx.x, lane = tid & 31, warp = tid >> 5;
    const int qt = (int)gridDim.x - 1 - (int)blockIdx.x;   // heavy tiles first
    const int h = blockIdx.y, b = blockIdx.z, kvh = h >> 2;
    const int q0 = qt * AQM;
    const int wm = warp * 16;

    const char* qhp = (const char*)(g_qh16 + ((size_t)(b * NH + h) * SS + q0) * DH);
    const char* qlp = (const char*)(g_ql16 + ((size_t)(b * NH + h) * SS + q0) * DH);
    const char* kp  = (const char*)(g_k16 + (size_t)(b * KVH + kvh) * SS * DH);
    const char* vp  = (const char*)(g_v16 + (size_t)(b * KVH + kvh) * SS * DH);

    // ---- stage Q (128x128 fp16 hi/lo) into smem, ldmatrix to registers --------
    for (int i = tid; i < 128 * 16; i += 256) {
        int row = i >> 4, ch = (i & 15) << 4;
        cp16(sb + (uint32_t)row * KROW + ch,          qhp + row * 256 + ch);
        cp16(sb + 2 * TB + (uint32_t)row * KROW + ch, qlp + row * 256 + ch);
    }
    asm volatile("cp.async.commit_group;");
    asm volatile("cp.async.wait_group 0;");
    __syncthreads();

    const int arow = lane & 15, akoff = (lane >> 4) << 3;
    uint32_t qfh[8][4], qfl[8][4];
#pragma unroll
    for (int kc = 0; kc < 8; kc++) {
        uint32_t ra = sb + (uint32_t)(wm + arow) * KROW + ((uint32_t)(kc * 16 + akoff) << 1);
        ldm_x4(qfh[kc], ra);
        ldm_x4(qfl[kc], ra + 2 * TB);
    }
    __syncthreads();   // staging area free for K/V now

    float oacc[16][4];
#pragma unroll
    for (int j = 0; j < 16; j++)
#pragma unroll
        for (int c = 0; c < 4; c++) oacc[j][c] = 0.0f;
    float mrun0 = -INFINITY, mrun1 = -INFINITY;
    float lrun0 = 0.0f, lrun1 = 0.0f;

    const int nblocks = 2 * (qt + 1);
    const int brow = (lane & 7) + ((lane >> 4) << 3);
    const int bkoff = ((lane >> 3) & 1) << 3;
    const int vrow = lane & 15, vcoff = (lane >> 4) << 3;

    auto issue = [&](int t) {
        const uint32_t base = sb + (uint32_t)(t & 1) * (2 * TB);
        const size_t g0 = (size_t)t * AKN * 256;
        for (int i = tid; i < AKN * 16; i += 256) {
            int row = i >> 4, ch = (i & 15) << 4;
            uint32_t soff = (uint32_t)row * KROW + ch;
            size_t goff = g0 + (size_t)row * 256 + ch;
            cp16(base + soff,      kp + goff);
            cp16(base + TB + soff, vp + goff);
        }
        asm volatile("cp.async.commit_group;");
    };

    issue(0);

    for (int t = 0; t < nblocks; t++) {
        if (t + 1 < nblocks) { issue(t + 1); asm volatile("cp.async.wait_group 1;"); }
        else                 { asm volatile("cp.async.wait_group 0;"); }
        __syncthreads();
        const uint32_t base = sb + (uint32_t)(t & 1) * (2 * TB);

        // ---- S = Q K^T (2-pass fp16: (Qh + Ql) x K) ---------------------------
        float sacc[8][4];
#pragma unroll
        for (int j = 0; j < 8; j++)
#pragma unroll
            for (int c = 0; c < 4; c++) sacc[j][c] = 0.0f;

#pragma unroll
        for (int kc = 0; kc < 8; kc++) {
            const uint32_t kb = (uint32_t)(kc * 16 + bkoff) << 1;
#pragma unroll
            for (int np = 0; np < 4; np++) {
                uint32_t rb = base + (uint32_t)(np * 16 + brow) * KROW + kb;
                uint32_t bh4[4];
                ldm_x4(bh4, rb);
#pragma unroll
                for (int ia = 0; ia < 2; ia++) {
                    float* c = sacc[np * 2 + ia];
                    mma_f16(c, qfh[kc], bh4[2 * ia], bh4[2 * ia + 1]);
                    mma_f16(c, qfl[kc], bh4[2 * ia], bh4[2 * ia + 1]);
                }
            }
        }

        // ---- causal mask (warp-uniform skip when fully unmasked) --------------
        const int k0 = t * AKN;
        if (k0 + AKN - 1 > q0 + wm) {
            const int r0 = q0 + wm + (lane >> 2);
#pragma unroll
            for (int j = 0; j < 8; j++) {
                int cb = k0 + j * 8 + ((lane & 3) << 1);
                if (cb     > r0)     sacc[j][0] = -INFINITY;
                if (cb + 1 > r0)     sacc[j][1] = -INFINITY;
                if (cb     > r0 + 8) sacc[j][2] = -INFINITY;
                if (cb + 1 > r0 + 8) sacc[j][3] = -INFINITY;
            }
        }

        // ---- online softmax ---------------------------------------------------
        float mx0 = -INFINITY, mx1 = -INFINITY;
#pragma unroll
        for (int j = 0; j < 8; j++) {
            mx0 = fmaxf(mx0, fmaxf(sacc[j][0], sacc[j][1]));
            mx1 = fmaxf(mx1, fmaxf(sacc[j][2], sacc[j][3]));
        }
        mx0 = fmaxf(mx0, __shfl_xor_sync(0xffffffffu, mx0, 1));
        mx0 = fmaxf(mx0, __shfl_xor_sync(0xffffffffu, mx0, 2));
        mx1 = fmaxf(mx1, __shfl_xor_sync(0xffffffffu, mx1, 1));
        mx1 = fmaxf(mx1, __shfl_xor_sync(0xffffffffu, mx1, 2));
        float mn0 = fmaxf(mrun0, mx0), mn1 = fmaxf(mrun1, mx1);

        float sum0 = 0.0f, sum1 = 0.0f;
#pragma unroll
        for (int j = 0; j < 8; j++) {
            float e0 = __expf(sacc[j][0] - mn0);
            float e1 = __expf(sacc[j][1] - mn0);
            float e2 = __expf(sacc[j][2] - mn1);
            float e3 = __expf(sacc[j][3] - mn1);
            sacc[j][0] = e0; sacc[j][1] = e1; sacc[j][2] = e2; sacc[j][3] = e3;
            sum0 += e0 + e1; sum1 += e2 + e3;
        }
        sum0 += __shfl_xor_sync(0xffffffffu, sum0, 1);
        sum0 += __shfl_xor_sync(0xffffffffu, sum0, 2);
        sum1 += __shfl_xor_sync(0xffffffffu, sum1, 1);
        sum1 += __shfl_xor_sync(0xffffffffu, sum1, 2);

        float c0 = __expf(mrun0 - mn0), c1 = __expf(mrun1 - mn1);
        lrun0 = lrun0 * c0 + sum0;
        lrun1 = lrun1 * c1 + sum1;
        mrun0 = mn0; mrun1 = mn1;
#pragma unroll
        for (int j = 0; j < 16; j++) {
            oacc[j][0] *= c0; oacc[j][1] *= c0;
            oacc[j][2] *= c1; oacc[j][3] *= c1;
        }

        // ---- O += P V (2-pass fp16: (Ph + Pl) x V) ----------------------------
#pragma unroll
        for (int kc = 0; kc < 4; kc++) {
            uint32_t pah[4], pal[4];
            split_pack_h(sacc[2*kc][0],   sacc[2*kc][1],   pah[0], pal[0]);
            split_pack_h(sacc[2*kc][2],   sacc[2*kc][3],   pah[1], pal[1]);
            split_pack_h(sacc[2*kc+1][0], sacc[2*kc+1][1], pah[2], pal[2]);
            split_pack_h(sacc[2*kc+1][2], sacc[2*kc+1][3], pah[3], pal[3]);
#pragma unroll
            for (int nd = 0; nd < 8; nd++) {
                uint32_t rv = base + TB + (uint32_t)(kc * 16 + vrow) * KROW
                              + ((uint32_t)(nd * 16 + vcoff) << 1);
                uint32_t vh4[4];
                ldm_x4_t(vh4, rv);
#pragma unroll
                for (int ia = 0; ia < 2; ia++) {
                    float* o = oacc[nd * 2 + ia];
                    mma_f16(o, pah, vh4[2 * ia], vh4[2 * ia + 1]);
                    mma_f16(o, pal, vh4[2 * ia], vh4[2 * ia + 1]);
                }
            }
        }
        __syncthreads();
    }

    // ---- epilogue: normalize, write single fp16 for the Wo GEMM ----------------
    const float inv0 = 1.0f / lrun0, inv1 = 1.0f / lrun1;
    const size_t r0 = (size_t)(b * SS + q0 + wm + (lane >> 2)) * (NH * DH)
                      + h * DH + ((lane & 3) << 1);
    const size_t r1 = r0 + (size_t)8 * (NH * DH);
#pragma unroll
    for (int nd = 0; nd < 16; nd++) {
        __half2 h0 = __floats2half2_rn(oacc[nd][0] * inv0, oacc[nd][1] * inv0);
        __half2 h1 = __floats2half2_rn(oacc[nd][2] * inv1, oacc[nd][3] * inv1);
        *(__half2*)(g_att16 + r0 + nd * 8) = h0;
        *(__half2*)(g_att16 + r1 + nd * 8) = h1;
    }
}

// ---------------- launch --------------------------------------------------------
extern "C" void kernel_launch(void* const* d_in, const int* in_sizes, int n_in,
                              void* d_out, int out_size)
{
    const float* x   = (const float*)d_in[0];
    // d_in[1] = mask (causal; handled analytically)
    const int*   pos = (const int*)d_in[2];
    const float* Wq  = (const float*)d_in[3];
    const float* Wk  = (const float*)d_in[4];
    const float* Wv  = (const float*)d_in[5];
    const float* Wo  = (const float*)d_in[6];
    float* out = (float*)d_out;

    float* qkvraw;
    cudaGetSymbolAddress((void**)&qkvraw, g_qkvraw);
    __half *x16, *wqkvh, *wqkvl, *woh, *wol, *att16;
    cudaGetSymbolAddress((void**)&x16,   g_x16);
    cudaGetSymbolAddress((void**)&wqkvh, g_wqkvh16);
    cudaGetSymbolAddress((void**)&wqkvl, g_wqkvl16);
    cudaGetSymbolAddress((void**)&woh,   g_woh16);
    cudaGetSymbolAddress((void**)&wol,   g_wol16);
    cudaGetSymbolAddress((void**)&att16, g_att16);

    cudaFuncSetAttribute(attn_kernel,
                         cudaFuncAttributeMaxDynamicSharedMemorySize, AT_SMEM);
    cudaFuncSetAttribute(mm_f16_kernel,
                         cudaFuncAttributeMaxDynamicSharedMemorySize, MM_SMEM);

    // convert x to fp16
    cvt16_kernel<<<(MROWS * DIM / 4 + 255) / 256, 256>>>(x, x16, MROWS * DIM / 4);
    // transpose+split weights (fp16 hi/lo) into fused [3072][2048]
    splitT16_kernel<<<dim3(DIM / 32, DIM / 32), dim3(32, 8)>>>(Wq, wqkvh, wqkvl, DIM, DIM);
    splitT16_kernel<<<dim3((KVH * DH) / 32, DIM / 32), dim3(32, 8)>>>(
        Wk, wqkvh + (size_t)2048 * DIM, wqkvl + (size_t)2048 * DIM, DIM, KVH * DH);
    splitT16_kernel<<<dim3((KVH * DH) / 32, DIM / 32), dim3(32, 8)>>>(
        Wv, wqkvh + (size_t)2560 * DIM, wqkvl + (size_t)2560 * DIM, DIM, KVH * DH);
    splitT16_kernel<<<dim3(DIM / 32, DIM / 32), dim3(32, 8)>>>(Wo, woh, wol, DIM, DIM);

    // fused QKV projection (fp16 2-pass, one launch, N=3072)
    mm_f16_kernel<<<dim3(NQKV / 128, MROWS / 128), 128, MM_SMEM>>>(
        x16, wqkvh, wqkvl, qkvraw, NQKV);

    // RoPE -> fp16 attention operands
    rope_kernel<<<dim3(SS, BB), 256>>>(pos);

    // attention on tensor cores (fp16 2-pass)
    attn_kernel<<<dim3(SS / AQM, NH, BB), 256, AT_SMEM>>>();

    // output projection (fp16 2-pass)
    mm_f16_kernel<<<dim3(DIM / 128, MROWS / 128), 128, MM_SMEM>>>(
        att16, woh, wol, out, DIM);
}

// round 9
// speedup vs baseline: 4.6333x; 1.0022x over previous
#include <cuda_runtime.h>
#include <cuda_bf16.h>
#include <cuda_fp16.h>
#include <math.h>
#include <stdint.h>

// Problem constants
#define BB 2
#define SS 2048
#define DIM 2048
#define NH 16
#define KVH 4
#define DH 128
#define MROWS (BB * SS)   // 4096
#define NQKV 3072         // fused QKV output width (2048 q + 512 k + 512 v)

// ---------------- scratch (device globals; no allocation allowed) -------------
__device__ float g_qkvraw[MROWS * NQKV];        // fused QKV projection output

// attention operands (fp16), layout [b,h,s,d]
__device__ __half g_qh16[BB * NH * SS * DH];    // Q hi
__device__ __half g_ql16[BB * NH * SS * DH];    // Q lo (residual)
__device__ __half g_k16[BB * KVH * SS * DH];    // K single fp16
__device__ __half g_v16[BB * KVH * SS * DH];    // V single fp16

// fp16 GEMM operands
__device__ __half g_x16[MROWS * DIM];           // x single fp16
__device__ __half g_wqkvh16[NQKV * DIM];        // fused W_qkv hi, transposed [N][K]
__device__ __half g_wqkvl16[NQKV * DIM];        // fused W_qkv lo
__device__ __half g_woh16[DIM * DIM];           // W_o hi, transposed [N][K]
__device__ __half g_wol16[DIM * DIM];           // W_o lo
__device__ __half g_att16[MROWS * (NH*DH)];     // attention output, single fp16

// ---------------- PTX helpers ---------------------------------------------------
__device__ __forceinline__ uint32_t smem_u32(const void* p) {
    uint32_t a;
    asm("{ .reg .u64 t; cvta.to.shared.u64 t, %1; cvt.u32.u64 %0, t; }"
        : "=r"(a) : "l"(p));
    return a;
}

__device__ __forceinline__ void cp16(uint32_t dst, const void* src) {
    asm volatile("cp.async.cg.shared.global [%0], [%1], 16;\n"
                 :: "r"(dst), "l"(src));
}

__device__ __forceinline__ void ldm_x4(uint32_t r[4], uint32_t addr) {
    asm volatile("ldmatrix.sync.aligned.m8n8.x4.shared.b16 {%0,%1,%2,%3}, [%4];"
                 : "=r"(r[0]), "=r"(r[1]), "=r"(r[2]), "=r"(r[3]) : "r"(addr));
}

__device__ __forceinline__ void ldm_x4_t(uint32_t r[4], uint32_t addr) {
    asm volatile("ldmatrix.sync.aligned.m8n8.x4.trans.shared.b16 {%0,%1,%2,%3}, [%4];"
                 : "=r"(r[0]), "=r"(r[1]), "=r"(r[2]), "=r"(r[3]) : "r"(addr));
}

__device__ __forceinline__ void mma_f16(float c[4], const uint32_t a[4],
                                        uint32_t b0, uint32_t b1) {
    asm volatile(
        "mma.sync.aligned.m16n8k16.row.col.f32.f16.f16.f32 "
        "{%0,%1,%2,%3}, {%4,%5,%6,%7}, {%8,%9}, {%0,%1,%2,%3};"
        : "+f"(c[0]), "+f"(c[1]), "+f"(c[2]), "+f"(c[3])
        : "r"(a[0]), "r"(a[1]), "r"(a[2]), "r"(a[3]), "r"(b0), "r"(b1));
}

// split two floats into packed fp16x2 hi + residual lo
__device__ __forceinline__ void split_pack_h(float a, float b, uint32_t& hi, uint32_t& lo) {
    __half2 h = __floats2half2_rn(a, b);
    float fa = __half2float(__low2half(h)), fb = __half2float(__high2half(h));
    __half2 l = __floats2half2_rn(a - fa, b - fb);
    hi = *(uint32_t*)&h;
    lo = *(uint32_t*)&l;
}

// ---------------- fp32 -> fp16 single convert ----------------------------------
__global__ __launch_bounds__(256) void cvt16_kernel(
    const float* __restrict__ in, __half* __restrict__ out, int n4)
{
    int i = blockIdx.x * blockDim.x + threadIdx.x;
    if (i >= n4) return;
    float4 v = ((const float4*)in)[i];
    __half2 a = __floats2half2_rn(v.x, v.y);
    __half2 b = __floats2half2_rn(v.z, v.w);
    ((__half2*)out)[2*i]   = a;
    ((__half2*)out)[2*i+1] = b;
}

// ---------------- fp32 [K][N] -> fp16 hi/lo transposed [N][K] -------------------
__global__ __launch_bounds__(256) void splitT16_kernel(
    const float* __restrict__ W, __half* __restrict__ Th,
    __half* __restrict__ Tl, int K, int N)
{
    __shared__ float t[32][33];
    const int n0 = blockIdx.x * 32, k0 = blockIdx.y * 32;
    const int tx = threadIdx.x, ty = threadIdx.y;   // (32, 8)
    for (int i = ty; i < 32; i += 8)
        t[i][tx] = W[(size_t)(k0 + i) * N + n0 + tx];
    __syncthreads();
    for (int i = ty; i < 32; i += 8) {
        float v = t[tx][i];
        __half h = __float2half_rn(v);
        Th[(size_t)(n0 + i) * K + k0 + tx] = h;
        Tl[(size_t)(n0 + i) * K + k0 + tx] = __float2half_rn(v - __half2float(h));
    }
}

// ---------------- fp16 mma.sync 2-pass GEMM ------------------------------------
// C[M,N] = A @ (Bh + Bl)^T.  A:[M][K] fp16 single, B:[N][K] fp16 hi/lo.
// 4 warps, warp tile 64x64; CTA 128x128, BK=32, double-buffered cp.async.
#define GK 2048
#define ROWB 80
#define TILE_B (128 * ROWB)
#define OFF_A  0
#define OFF_BH (1 * TILE_B)
#define OFF_BL (2 * TILE_B)
#define STG (3 * TILE_B)
#define MM_SMEM (2 * STG)   // 61440

__global__ __launch_bounds__(128) void mm_f16_kernel(
    const __half* __restrict__ A,
    const __half* __restrict__ Bh, const __half* __restrict__ Bl,
    float* __restrict__ C, int N)
{
    extern __shared__ char smem[];
    const uint32_t sb = smem_u32(smem);
    const int tid = threadIdx.x;
    const int lane = tid & 31, warp = tid >> 5;
    const int m0 = blockIdx.y * 128, n0 = blockIdx.x * 128;
    const int wm0 = (warp >> 1) * 64;
    const int wn0 = (warp & 1) * 64;

    const int arow_l  = lane & 15;
    const int akoff_l = (lane >> 4) << 3;
    const int brow_l  = (lane & 7) + ((lane >> 4) << 3);
    const int bkoff_l = ((lane >> 3) & 1) << 3;

    float acc[4][8][4];
#pragma unroll
    for (int im = 0; im < 4; im++)
#pragma unroll
        for (int j = 0; j < 8; j++)
#pragma unroll
            for (int c = 0; c < 4; c++) acc[im][j][c] = 0.0f;

    const int NT = GK / 32;

    auto issue = [&](int t) {
        const int k0 = t * 32;
        const uint32_t sbase = sb + (t & 1) * STG;
#pragma unroll
        for (int i = 0; i < 4; i++) {
            const int c = tid + (i << 7);
            const int row = c >> 2;
            const int off = (c & 3) << 3;
            const uint32_t soff = (uint32_t)row * ROWB + ((uint32_t)off << 1);
            const size_t ga = (size_t)(m0 + row) * GK + k0 + off;
            const size_t gb = (size_t)(n0 + row) * GK + k0 + off;
            cp16(sbase + OFF_A + soff,  A + ga);
            cp16(sbase + OFF_BH + soff, Bh + gb);
            cp16(sbase + OFF_BL + soff, Bl + gb);
        }
        asm volatile("cp.async.commit_group;");
    };

    issue(0);

    for (int t = 0; t < NT; t++) {
        if (t + 1 < NT) issue(t + 1);
        if (t + 1 < NT) { asm volatile("cp.async.wait_group 1;"); }
        else            { asm volatile("cp.async.wait_group 0;"); }
        __syncthreads();

        const uint32_t sbase = sb + (t & 1) * STG;
#pragma unroll
        for (int ks = 0; ks < 2; ks++) {
            uint32_t ah[4][4];
            const uint32_t kba = (uint32_t)(ks * 16 + akoff_l) << 1;
#pragma unroll
            for (int im = 0; im < 4; im++) {
                uint32_t ra = sbase + (uint32_t)(wm0 + im * 16 + arow_l) * ROWB + kba;
                ldm_x4(ah[im], ra + OFF_A);
            }
            const uint32_t kbb = (uint32_t)(ks * 16 + bkoff_l) << 1;
#pragma unroll
            for (int np = 0; np < 4; np++) {
                uint32_t rb = sbase + (uint32_t)(wn0 + np * 16 + brow_l) * ROWB + kbb;
                uint32_t bh[4], bl[4];
                ldm_x4(bh, rb + OFF_BH);
                ldm_x4(bl, rb + OFF_BL);
#pragma unroll
                for (int im = 0; im < 4; im++) {
#pragma unroll
                    for (int ia = 0; ia < 2; ia++) {
                        float* c = acc[im][np * 2 + ia];
                        mma_f16(c, ah[im], bh[2 * ia], bh[2 * ia + 1]);
                        mma_f16(c, ah[im], bl[2 * ia], bl[2 * ia + 1]);
                    }
                }
            }
        }
        __syncthreads();
    }

#pragma unroll
    for (int im = 0; im < 4; im++) {
        const int rbase = m0 + wm0 + im * 16 + (lane >> 2);
#pragma unroll
        for (int j = 0; j < 8; j++) {
            const int col = n0 + wn0 + j * 8 + (lane & 3) * 2;
            float2 v0 = make_float2(acc[im][j][0], acc[im][j][1]);
            float2 v1 = make_float2(acc[im][j][2], acc[im][j][3]);
            *(float2*)(C + (size_t)rbase * N + col)       = v0;
            *(float2*)(C + (size_t)(rbase + 8) * N + col) = v1;
        }
    }
}

// ---------------- RoPE -> fp16 attention operands [b,h,s,d] --------------------
__global__ __launch_bounds__(256) void rope_kernel(const int* __restrict__ pos_ids)
{
    const int s = blockIdx.x;
    const int b = blockIdx.y;
    const int t = threadIdx.x;

    __shared__ float cs[64], sn[64];
    if (t < 64) {
        double invf = exp(-((double)(2 * t) / (double)DH) * log(10000.0));
        double ang = (double)pos_ids[s] * invf;
        cs[t] = (float)cos(ang);
        sn[t] = (float)sin(ang);
    }
    __syncthreads();

    const float qk_scale = 0.08838834764831845f;   // 1/sqrt(128), folded into Q
    const float* row = g_qkvraw + (size_t)(b * SS + s) * NQKV;

    // Q: fp16 hi/lo split
    for (int idx = t; idx < NH * 64; idx += 256) {
        int h = idx >> 6, i = idx & 63;
        float x1 = row[h * DH + i];
        float x2 = row[h * DH + 64 + i];
        float y1 = (x1 * cs[i] - x2 * sn[i]) * qk_scale;
        float y2 = (x2 * cs[i] + x1 * sn[i]) * qk_scale;
        size_t dst = ((size_t)(b * NH + h) * SS + s) * DH;
        __half h1 = __float2half_rn(y1);
        __half h2 = __float2half_rn(y2);
        g_qh16[dst + i]      = h1;
        g_ql16[dst + i]      = __float2half_rn(y1 - __half2float(h1));
        g_qh16[dst + 64 + i] = h2;
        g_ql16[dst + 64 + i] = __float2half_rn(y2 - __half2float(h2));
    }

    // K: single fp16
    const float* krow = row + 2048;
    for (int idx = t; idx < KVH * 64; idx += 256) {
        int h = idx >> 6, i = idx & 63;
        float x1 = krow[h * DH + i];
        float x2 = krow[h * DH + 64 + i];
        size_t dst = ((size_t)(b * KVH + h) * SS + s) * DH;
        g_k16[dst + i]      = __float2half_rn(x1 * cs[i] - x2 * sn[i]);
        g_k16[dst + 64 + i] = __float2half_rn(x2 * cs[i] + x1 * sn[i]);
    }

    // V: single fp16
    const float* vrow = row + 2560;
    for (int idx = t; idx < KVH * DH; idx += 256) {
        int h = idx >> 7, d = idx & 127;
        g_v16[((size_t)(b * KVH + h) * SS + s) * DH + d] = __float2half_rn(vrow[idx]);
    }
}

// ---------------- flash attention (fp16 mma.sync 2-pass, causal, GQA) -----------
// CTA: 128 q rows x 64-key blocks. 8 warps x 16 q rows.
#define AQM 128
#define AKN 64
#define KROW 272                  // smem row stride bytes (256 data + 16 pad)
#define TB (AKN * KROW)           // 17408
#define AT_SMEM (4 * TB)          // 69632: 2 stages x (K, V)

__global__ __launch_bounds__(256) void attn_kernel()
{
    extern __shared__ char smc[];
    const uint32_t sb = smem_u32(smc);
    const int tid = threadIdx.x, lane = tid & 31, warp = tid >> 5;
    const int qt = (int)gridDim.x - 1 - (int)blockIdx.x;   // heavy tiles first
    const int h = blockIdx.y, b = blockIdx.z, kvh = h >> 2;
    const int q0 = qt * AQM;
    const int wm = warp * 16;

    const char* qhp = (const char*)(g_qh16 + ((size_t)(b * NH + h) * SS + q0) * DH);
    const char* qlp = (const char*)(g_ql16 + ((size_t)(b * NH + h) * SS + q0) * DH);
    const char* kp  = (const char*)(g_k16 + (size_t)(b * KVH + kvh) * SS * DH);
    const char* vp  = (const char*)(g_v16 + (size_t)(b * KVH + kvh) * SS * DH);

    // ---- stage Q (128x128 fp16 hi/lo) into smem, ldmatrix to registers --------
    for (int i = tid; i < 128 * 16; i += 256) {
        int row = i >> 4, ch = (i & 15) << 4;
        cp16(sb + (uint32_t)row * KROW + ch,          qhp + row * 256 + ch);
        cp16(sb + 2 * TB + (uint32_t)row * KROW + ch, qlp + row * 256 + ch);
    }
    asm volatile("cp.async.commit_group;");
    asm volatile("cp.async.wait_group 0;");
    __syncthreads();

    const int arow = lane & 15, akoff = (lane >> 4) << 3;
    uint32_t qfh[8][4], qfl[8][4];
#pragma unroll
    for (int kc = 0; kc < 8; kc++) {
        uint32_t ra = sb + (uint32_t)(wm + arow) * KROW + ((uint32_t)(kc * 16 + akoff) << 1);
        ldm_x4(qfh[kc], ra);
        ldm_x4(qfl[kc], ra + 2 * TB);
    }
    __syncthreads();   // staging area free for K/V now

    float oacc[16][4];
#pragma unroll
    for (int j = 0; j < 16; j++)
#pragma unroll
        for (int c = 0; c < 4; c++) oacc[j][c] = 0.0f;
    float mrun0 = -INFINITY, mrun1 = -INFINITY;
    float lrun0 = 0.0f, lrun1 = 0.0f;

    const int nblocks = 2 * (qt + 1);
    const int brow = (lane & 7) + ((lane >> 4) << 3);
    const int bkoff = ((lane >> 3) & 1) << 3;
    const int vrow = lane & 15, vcoff = (lane >> 4) << 3;

    auto issue = [&](int t) {
        const uint32_t base = sb + (uint32_t)(t & 1) * (2 * TB);
        const size_t g0 = (size_t)t * AKN * 256;
        for (int i = tid; i < AKN * 16; i += 256) {
            int row = i >> 4, ch = (i & 15) << 4;
            uint32_t soff = (uint32_t)row * KROW + ch;
            size_t goff = g0 + (size_t)row * 256 + ch;
            cp16(base + soff,      kp + goff);
            cp16(base + TB + soff, vp + goff);
        }
        asm volatile("cp.async.commit_group;");
    };

    issue(0);

    for (int t = 0; t < nblocks; t++) {
        if (t + 1 < nblocks) { issue(t + 1); asm volatile("cp.async.wait_group 1;"); }
        else                 { asm volatile("cp.async.wait_group 0;"); }
        __syncthreads();
        const uint32_t base = sb + (uint32_t)(t & 1) * (2 * TB);

        // ---- S = Q K^T (2-pass fp16: (Qh + Ql) x K) ---------------------------
        float sacc[8][4];
#pragma unroll
        for (int j = 0; j < 8; j++)
#pragma unroll
            for (int c = 0; c < 4; c++) sacc[j][c] = 0.0f;

#pragma unroll
        for (int kc = 0; kc < 8; kc++) {
            const uint32_t kb = (uint32_t)(kc * 16 + bkoff) << 1;
#pragma unroll
            for (int np = 0; np < 4; np++) {
                uint32_t rb = base + (uint32_t)(np * 16 + brow) * KROW + kb;
                uint32_t bh4[4];
                ldm_x4(bh4, rb);
#pragma unroll
                for (int ia = 0; ia < 2; ia++) {
                    float* c = sacc[np * 2 + ia];
                    mma_f16(c, qfh[kc], bh4[2 * ia], bh4[2 * ia + 1]);
                    mma_f16(c, qfl[kc], bh4[2 * ia], bh4[2 * ia + 1]);
                }
            }
        }

        // ---- causal mask (warp-uniform skip when fully unmasked) --------------
        const int k0 = t * AKN;
        if (k0 + AKN - 1 > q0 + wm) {
            const int r0 = q0 + wm + (lane >> 2);
#pragma unroll
            for (int j = 0; j < 8; j++) {
                int cb = k0 + j * 8 + ((lane & 3) << 1);
                if (cb     > r0)     sacc[j][0] = -INFINITY;
                if (cb + 1 > r0)     sacc[j][1] = -INFINITY;
                if (cb     > r0 + 8) sacc[j][2] = -INFINITY;
                if (cb + 1 > r0 + 8) sacc[j][3] = -INFINITY;
            }
        }

        // ---- online softmax ---------------------------------------------------
        float mx0 = -INFINITY, mx1 = -INFINITY;
#pragma unroll
        for (int j = 0; j < 8; j++) {
            mx0 = fmaxf(mx0, fmaxf(sacc[j][0], sacc[j][1]));
            mx1 = fmaxf(mx1, fmaxf(sacc[j][2], sacc[j][3]));
        }
        mx0 = fmaxf(mx0, __shfl_xor_sync(0xffffffffu, mx0, 1));
        mx0 = fmaxf(mx0, __shfl_xor_sync(0xffffffffu, mx0, 2));
        mx1 = fmaxf(mx1, __shfl_xor_sync(0xffffffffu, mx1, 1));
        mx1 = fmaxf(mx1, __shfl_xor_sync(0xffffffffu, mx1, 2));
        float mn0 = fmaxf(mrun0, mx0), mn1 = fmaxf(mrun1, mx1);

        float sum0 = 0.0f, sum1 = 0.0f;
#pragma unroll
        for (int j = 0; j < 8; j++) {
            float e0 = __expf(sacc[j][0] - mn0);
            float e1 = __expf(sacc[j][1] - mn0);
            float e2 = __expf(sacc[j][2] - mn1);
            float e3 = __expf(sacc[j][3] - mn1);
            sacc[j][0] = e0; sacc[j][1] = e1; sacc[j][2] = e2; sacc[j][3] = e3;
            sum0 += e0 + e1; sum1 += e2 + e3;
        }
        sum0 += __shfl_xor_sync(0xffffffffu, sum0, 1);
        sum0 += __shfl_xor_sync(0xffffffffu, sum0, 2);
        sum1 += __shfl_xor_sync(0xffffffffu, sum1, 1);
        sum1 += __shfl_xor_sync(0xffffffffu, sum1, 2);

        float c0 = __expf(mrun0 - mn0), c1 = __expf(mrun1 - mn1);
        lrun0 = lrun0 * c0 + sum0;
        lrun1 = lrun1 * c1 + sum1;
        mrun0 = mn0; mrun1 = mn1;
#pragma unroll
        for (int j = 0; j < 16; j++) {
            oacc[j][0] *= c0; oacc[j][1] *= c0;
            oacc[j][2] *= c1; oacc[j][3] *= c1;
        }

        // ---- O += P V (2-pass fp16: (Ph + Pl) x V) ----------------------------
#pragma unroll
        for (int kc = 0; kc < 4; kc++) {
            uint32_t pah[4], pal[4];
            split_pack_h(sacc[2*kc][0],   sacc[2*kc][1],   pah[0], pal[0]);
            split_pack_h(sacc[2*kc][2],   sacc[2*kc][3],   pah[1], pal[1]);
            split_pack_h(sacc[2*kc+1][0], sacc[2*kc+1][1], pah[2], pal[2]);
            split_pack_h(sacc[2*kc+1][2], sacc[2*kc+1][3], pah[3], pal[3]);
#pragma unroll
            for (int nd = 0; nd < 8; nd++) {
                uint32_t rv = base + TB + (uint32_t)(kc * 16 + vrow) * KROW
                              + ((uint32_t)(nd * 16 + vcoff) << 1);
                uint32_t vh4[4];
                ldm_x4_t(vh4, rv);
#pragma unroll
                for (int ia = 0; ia < 2; ia++) {
                    float* o = oacc[nd * 2 + ia];
                    mma_f16(o, pah, vh4[2 * ia], vh4[2 * ia + 1]);
                    mma_f16(o, pal, vh4[2 * ia], vh4[2 * ia + 1]);
                }
            }
        }
        __syncthreads();
    }

    // ---- epilogue: normalize, write single fp16 for the Wo GEMM ----------------
    const float inv0 = 1.0f / lrun0, inv1 = 1.0f / lrun1;
    const size_t r0 = (size_t)(b * SS + q0 + wm + (lane >> 2)) * (NH * DH)
                      + h * DH + ((lane & 3) << 1);
    const size_t r1 = r0 + (size_t)8 * (NH * DH);
#pragma unroll
    for (int nd = 0; nd < 16; nd++) {
        __half2 h0 = __floats2half2_rn(oacc[nd][0] * inv0, oacc[nd][1] * inv0);
        __half2 h1 = __floats2half2_rn(oacc[nd][2] * inv1, oacc[nd][3] * inv1);
        *(__half2*)(g_att16 + r0 + nd * 8) = h0;
        *(__half2*)(g_att16 + r1 + nd * 8) = h1;
    }
}

// ---------------- launch --------------------------------------------------------
extern "C" void kernel_launch(void* const* d_in, const int* in_sizes, int n_in,
                              void* d_out, int out_size)
{
    const float* x   = (const float*)d_in[0];
    // d_in[1] = mask (causal; handled analytically)
    const int*   pos = (const int*)d_in[2];
    const float* Wq  = (const float*)d_in[3];
    const float* Wk  = (const float*)d_in[4];
    const float* Wv  = (const float*)d_in[5];
    const float* Wo  = (const float*)d_in[6];
    float* out = (float*)d_out;

    float* qkvraw;
    cudaGetSymbolAddress((void**)&qkvraw, g_qkvraw);
    __half *x16, *wqkvh, *wqkvl, *woh, *wol, *att16;
    cudaGetSymbolAddress((void**)&x16,   g_x16);
    cudaGetSymbolAddress((void**)&wqkvh, g_wqkvh16);
    cudaGetSymbolAddress((void**)&wqkvl, g_wqkvl16);
    cudaGetSymbolAddress((void**)&woh,   g_woh16);
    cudaGetSymbolAddress((void**)&wol,   g_wol16);
    cudaGetSymbolAddress((void**)&att16, g_att16);

    cudaFuncSetAttribute(attn_kernel,
                         cudaFuncAttributeMaxDynamicSharedMemorySize, AT_SMEM);
    cudaFuncSetAttribute(mm_f16_kernel,
                         cudaFuncAttributeMaxDynamicSharedMemorySize, MM_SMEM);

    // convert x to fp16
    cvt16_kernel<<<(MROWS * DIM / 4 + 255) / 256, 256>>>(x, x16, MROWS * DIM / 4);
    // transpose+split weights (fp16 hi/lo) into fused [3072][2048]
    splitT16_kernel<<<dim3(DIM / 32, DIM / 32), dim3(32, 8)>>>(Wq, wqkvh, wqkvl, DIM, DIM);
    splitT16_kernel<<<dim3((KVH * DH) / 32, DIM / 32), dim3(32, 8)>>>(
        Wk, wqkvh + (size_t)2048 * DIM, wqkvl + (size_t)2048 * DIM, DIM, KVH * DH);
    splitT16_kernel<<<dim3((KVH * DH) / 32, DIM / 32), dim3(32, 8)>>>(
        Wv, wqkvh + (size_t)2560 * DIM, wqkvl + (size_t)2560 * DIM, DIM, KVH * DH);
    splitT16_kernel<<<dim3(DIM / 32, DIM / 32), dim3(32, 8)>>>(Wo, woh, wol, DIM, DIM);

    // fused QKV projection (fp16 2-pass, one launch, N=3072)
    mm_f16_kernel<<<dim3(NQKV / 128, MROWS / 128), 128, MM_SMEM>>>(
        x16, wqkvh, wqkvl, qkvraw, NQKV);

    // RoPE -> fp16 attention operands
    rope_kernel<<<dim3(SS, BB), 256>>>(pos);

    // attention on tensor cores (fp16 2-pass)
    attn_kernel<<<dim3(SS / AQM, NH, BB), 256, AT_SMEM>>>();

    // output projection (fp16 2-pass)
    mm_f16_kernel<<<dim3(DIM / 128, MROWS / 128), 128, MM_SMEM>>>(
        att16, woh, wol, out, DIM);
}

// round 10
// speedup vs baseline: 5.1031x; 1.1014x over previous
#include <cuda_runtime.h>
#include <cuda_bf16.h>
#include <cuda_fp16.h>
#include <math.h>
#include <stdint.h>

// Problem constants
#define BB 2
#define SS 2048
#define DIM 2048
#define NH 16
#define KVH 4
#define DH 128
#define MROWS (BB * SS)   // 4096
#define NQKV 3072         // fused QKV output width (2048 q + 512 k + 512 v)

// ---------------- scratch (device globals; no allocation allowed) -------------
__device__ float g_qkvraw[MROWS * NQKV];        // fused QKV projection output

// attention operands (fp16, single precision each), layout [b,h,s,d]
__device__ __half g_q16[BB * NH * SS * DH];     // Q (scale folded)
__device__ __half g_k16[BB * KVH * SS * DH];    // K
__device__ __half g_v16[BB * KVH * SS * DH];    // V

// fp16 GEMM operands
__device__ __half g_x16[MROWS * DIM];           // x single fp16
__device__ __half g_wqkvh16[NQKV * DIM];        // fused W_qkv hi, transposed [N][K]
__device__ __half g_wqkvl16[NQKV * DIM];        // fused W_qkv lo
__device__ __half g_woh16[DIM * DIM];           // W_o hi, transposed [N][K]
__device__ __half g_wol16[DIM * DIM];           // W_o lo
__device__ __half g_att16[MROWS * (NH*DH)];     // attention output, single fp16

// ---------------- PTX helpers ---------------------------------------------------
__device__ __forceinline__ uint32_t smem_u32(const void* p) {
    uint32_t a;
    asm("{ .reg .u64 t; cvta.to.shared.u64 t, %1; cvt.u32.u64 %0, t; }"
        : "=r"(a) : "l"(p));
    return a;
}

__device__ __forceinline__ void cp16(uint32_t dst, const void* src) {
    asm volatile("cp.async.cg.shared.global [%0], [%1], 16;\n"
                 :: "r"(dst), "l"(src));
}

__device__ __forceinline__ void ldm_x4(uint32_t r[4], uint32_t addr) {
    asm volatile("ldmatrix.sync.aligned.m8n8.x4.shared.b16 {%0,%1,%2,%3}, [%4];"
                 : "=r"(r[0]), "=r"(r[1]), "=r"(r[2]), "=r"(r[3]) : "r"(addr));
}

__device__ __forceinline__ void ldm_x4_t(uint32_t r[4], uint32_t addr) {
    asm volatile("ldmatrix.sync.aligned.m8n8.x4.trans.shared.b16 {%0,%1,%2,%3}, [%4];"
                 : "=r"(r[0]), "=r"(r[1]), "=r"(r[2]), "=r"(r[3]) : "r"(addr));
}

__device__ __forceinline__ void mma_f16(float c[4], const uint32_t a[4],
                                        uint32_t b0, uint32_t b1) {
    asm volatile(
        "mma.sync.aligned.m16n8k16.row.col.f32.f16.f16.f32 "
        "{%0,%1,%2,%3}, {%4,%5,%6,%7}, {%8,%9}, {%0,%1,%2,%3};"
        : "+f"(c[0]), "+f"(c[1]), "+f"(c[2]), "+f"(c[3])
        : "r"(a[0]), "r"(a[1]), "r"(a[2]), "r"(a[3]), "r"(b0), "r"(b1));
}

// ---------------- fp32 -> fp16 single convert ----------------------------------
__global__ __launch_bounds__(256) void cvt16_kernel(
    const float* __restrict__ in, __half* __restrict__ out, int n4)
{
    int i = blockIdx.x * blockDim.x + threadIdx.x;
    if (i >= n4) return;
    float4 v = ((const float4*)in)[i];
    __half2 a = __floats2half2_rn(v.x, v.y);
    __half2 b = __floats2half2_rn(v.z, v.w);
    ((__half2*)out)[2*i]   = a;
    ((__half2*)out)[2*i+1] = b;
}

// ---------------- fp32 [K][N] -> fp16 hi/lo transposed [N][K] -------------------
__global__ __launch_bounds__(256) void splitT16_kernel(
    const float* __restrict__ W, __half* __restrict__ Th,
    __half* __restrict__ Tl, int K, int N)
{
    __shared__ float t[32][33];
    const int n0 = blockIdx.x * 32, k0 = blockIdx.y * 32;
    const int tx = threadIdx.x, ty = threadIdx.y;   // (32, 8)
    for (int i = ty; i < 32; i += 8)
        t[i][tx] = W[(size_t)(k0 + i) * N + n0 + tx];
    __syncthreads();
    for (int i = ty; i < 32; i += 8) {
        float v = t[tx][i];
        __half h = __float2half_rn(v);
        Th[(size_t)(n0 + i) * K + k0 + tx] = h;
        Tl[(size_t)(n0 + i) * K + k0 + tx] = __float2half_rn(v - __half2float(h));
    }
}

// ---------------- fp16 mma.sync 2-pass GEMM ------------------------------------
// C[M,N] = A @ (Bh + Bl)^T.  A:[M][K] fp16 single, B:[N][K] fp16 hi/lo.
// 4 warps, warp tile 64x64; CTA 128x128, BK=32, double-buffered cp.async.
#define GK 2048
#define ROWB 80
#define TILE_B (128 * ROWB)
#define OFF_A  0
#define OFF_BH (1 * TILE_B)
#define OFF_BL (2 * TILE_B)
#define STG (3 * TILE_B)
#define MM_SMEM (2 * STG)   // 61440

__global__ __launch_bounds__(128) void mm_f16_kernel(
    const __half* __restrict__ A,
    const __half* __restrict__ Bh, const __half* __restrict__ Bl,
    float* __restrict__ C, int N)
{
    extern __shared__ char smem[];
    const uint32_t sb = smem_u32(smem);
    const int tid = threadIdx.x;
    const int lane = tid & 31, warp = tid >> 5;
    const int m0 = blockIdx.y * 128, n0 = blockIdx.x * 128;
    const int wm0 = (warp >> 1) * 64;
    const int wn0 = (warp & 1) * 64;

    const int arow_l  = lane & 15;
    const int akoff_l = (lane >> 4) << 3;
    const int brow_l  = (lane & 7) + ((lane >> 4) << 3);
    const int bkoff_l = ((lane >> 3) & 1) << 3;

    float acc[4][8][4];
#pragma unroll
    for (int im = 0; im < 4; im++)
#pragma unroll
        for (int j = 0; j < 8; j++)
#pragma unroll
            for (int c = 0; c < 4; c++) acc[im][j][c] = 0.0f;

    const int NT = GK / 32;

    auto issue = [&](int t) {
        const int k0 = t * 32;
        const uint32_t sbase = sb + (t & 1) * STG;
#pragma unroll
        for (int i = 0; i < 4; i++) {
            const int c = tid + (i << 7);
            const int row = c >> 2;
            const int off = (c & 3) << 3;
            const uint32_t soff = (uint32_t)row * ROWB + ((uint32_t)off << 1);
            const size_t ga = (size_t)(m0 + row) * GK + k0 + off;
            const size_t gb = (size_t)(n0 + row) * GK + k0 + off;
            cp16(sbase + OFF_A + soff,  A + ga);
            cp16(sbase + OFF_BH + soff, Bh + gb);
            cp16(sbase + OFF_BL + soff, Bl + gb);
        }
        asm volatile("cp.async.commit_group;");
    };

    issue(0);

    for (int t = 0; t < NT; t++) {
        if (t + 1 < NT) issue(t + 1);
        if (t + 1 < NT) { asm volatile("cp.async.wait_group 1;"); }
        else            { asm volatile("cp.async.wait_group 0;"); }
        __syncthreads();

        const uint32_t sbase = sb + (t & 1) * STG;
#pragma unroll
        for (int ks = 0; ks < 2; ks++) {
            uint32_t ah[4][4];
            const uint32_t kba = (uint32_t)(ks * 16 + akoff_l) << 1;
#pragma unroll
            for (int im = 0; im < 4; im++) {
                uint32_t ra = sbase + (uint32_t)(wm0 + im * 16 + arow_l) * ROWB + kba;
                ldm_x4(ah[im], ra + OFF_A);
            }
            const uint32_t kbb = (uint32_t)(ks * 16 + bkoff_l) << 1;
#pragma unroll
            for (int np = 0; np < 4; np++) {
                uint32_t rb = sbase + (uint32_t)(wn0 + np * 16 + brow_l) * ROWB + kbb;
                uint32_t bh[4], bl[4];
                ldm_x4(bh, rb + OFF_BH);
                ldm_x4(bl, rb + OFF_BL);
#pragma unroll
                for (int im = 0; im < 4; im++) {
#pragma unroll
                    for (int ia = 0; ia < 2; ia++) {
                        float* c = acc[im][np * 2 + ia];
                        mma_f16(c, ah[im], bh[2 * ia], bh[2 * ia + 1]);
                        mma_f16(c, ah[im], bl[2 * ia], bl[2 * ia + 1]);
                    }
                }
            }
        }
        __syncthreads();
    }

#pragma unroll
    for (int im = 0; im < 4; im++) {
        const int rbase = m0 + wm0 + im * 16 + (lane >> 2);
#pragma unroll
        for (int j = 0; j < 8; j++) {
            const int col = n0 + wn0 + j * 8 + (lane & 3) * 2;
            float2 v0 = make_float2(acc[im][j][0], acc[im][j][1]);
            float2 v1 = make_float2(acc[im][j][2], acc[im][j][3]);
            *(float2*)(C + (size_t)rbase * N + col)       = v0;
            *(float2*)(C + (size_t)(rbase + 8) * N + col) = v1;
        }
    }
}

// ---------------- RoPE -> fp16 attention operands [b,h,s,d] --------------------
__global__ __launch_bounds__(256) void rope_kernel(const int* __restrict__ pos_ids)
{
    const int s = blockIdx.x;
    const int b = blockIdx.y;
    const int t = threadIdx.x;

    __shared__ float cs[64], sn[64];
    if (t < 64) {
        double invf = exp(-((double)(2 * t) / (double)DH) * log(10000.0));
        double ang = (double)pos_ids[s] * invf;
        cs[t] = (float)cos(ang);
        sn[t] = (float)sin(ang);
    }
    __syncthreads();

    const float qk_scale = 0.08838834764831845f;   // 1/sqrt(128), folded into Q
    const float* row = g_qkvraw + (size_t)(b * SS + s) * NQKV;

    // Q: single fp16 (scale folded)
    for (int idx = t; idx < NH * 64; idx += 256) {
        int h = idx >> 6, i = idx & 63;
        float x1 = row[h * DH + i];
        float x2 = row[h * DH + 64 + i];
        size_t dst = ((size_t)(b * NH + h) * SS + s) * DH;
        g_q16[dst + i]      = __float2half_rn((x1 * cs[i] - x2 * sn[i]) * qk_scale);
        g_q16[dst + 64 + i] = __float2half_rn((x2 * cs[i] + x1 * sn[i]) * qk_scale);
    }

    // K: single fp16
    const float* krow = row + 2048;
    for (int idx = t; idx < KVH * 64; idx += 256) {
        int h = idx >> 6, i = idx & 63;
        float x1 = krow[h * DH + i];
        float x2 = krow[h * DH + 64 + i];
        size_t dst = ((size_t)(b * KVH + h) * SS + s) * DH;
        g_k16[dst + i]      = __float2half_rn(x1 * cs[i] - x2 * sn[i]);
        g_k16[dst + 64 + i] = __float2half_rn(x2 * cs[i] + x1 * sn[i]);
    }

    // V: single fp16
    const float* vrow = row + 2560;
    for (int idx = t; idx < KVH * DH; idx += 256) {
        int h = idx >> 7, d = idx & 127;
        g_v16[((size_t)(b * KVH + h) * SS + s) * DH + d] = __float2half_rn(vrow[idx]);
    }
}

// ---------------- flash attention (fp16 mma.sync 1-pass, causal, GQA) -----------
// CTA: 128 q rows x 64-key blocks. 8 warps x 16 q rows.
#define AQM 128
#define AKN 64
#define KROW 272                  // smem row stride bytes (256 data + 16 pad)
#define TB (AKN * KROW)           // 17408
#define AT_SMEM (4 * TB)          // 69632: 2 stages x (K, V)

__global__ __launch_bounds__(256) void attn_kernel()
{
    extern __shared__ char smc[];
    const uint32_t sb = smem_u32(smc);
    const int tid = threadIdx.x, lane = tid & 31, warp = tid >> 5;
    const int qt = (int)gridDim.x - 1 - (int)blockIdx.x;   // heavy tiles first
    const int h = blockIdx.y, b = blockIdx.z, kvh = h >> 2;
    const int q0 = qt * AQM;
    const int wm = warp * 16;

    const char* qp = (const char*)(g_q16 + ((size_t)(b * NH + h) * SS + q0) * DH);
    const char* kp = (const char*)(g_k16 + (size_t)(b * KVH + kvh) * SS * DH);
    const char* vp = (const char*)(g_v16 + (size_t)(b * KVH + kvh) * SS * DH);

    // ---- stage Q (128x128 fp16) into smem, ldmatrix to registers --------------
    for (int i = tid; i < 128 * 16; i += 256) {
        int row = i >> 4, ch = (i & 15) << 4;
        cp16(sb + (uint32_t)row * KROW + ch, qp + row * 256 + ch);
    }
    asm volatile("cp.async.commit_group;");
    asm volatile("cp.async.wait_group 0;");
    __syncthreads();

    const int arow = lane & 15, akoff = (lane >> 4) << 3;
    uint32_t qf[8][4];
#pragma unroll
    for (int kc = 0; kc < 8; kc++) {
        uint32_t ra = sb + (uint32_t)(wm + arow) * KROW + ((uint32_t)(kc * 16 + akoff) << 1);
        ldm_x4(qf[kc], ra);
    }
    __syncthreads();   // staging area free for K/V now

    float oacc[16][4];
#pragma unroll
    for (int j = 0; j < 16; j++)
#pragma unroll
        for (int c = 0; c < 4; c++) oacc[j][c] = 0.0f;
    float mrun0 = -INFINITY, mrun1 = -INFINITY;
    float lrun0 = 0.0f, lrun1 = 0.0f;

    const int nblocks = 2 * (qt + 1);
    const int brow = (lane & 7) + ((lane >> 4) << 3);
    const int bkoff = ((lane >> 3) & 1) << 3;
    const int vrow = lane & 15, vcoff = (lane >> 4) << 3;

    auto issue = [&](int t) {
        const uint32_t base = sb + (uint32_t)(t & 1) * (2 * TB);
        const size_t g0 = (size_t)t * AKN * 256;
        for (int i = tid; i < AKN * 16; i += 256) {
            int row = i >> 4, ch = (i & 15) << 4;
            uint32_t soff = (uint32_t)row * KROW + ch;
            size_t goff = g0 + (size_t)row * 256 + ch;
            cp16(base + soff,      kp + goff);
            cp16(base + TB + soff, vp + goff);
        }
        asm volatile("cp.async.commit_group;");
    };

    issue(0);

    for (int t = 0; t < nblocks; t++) {
        if (t + 1 < nblocks) { issue(t + 1); asm volatile("cp.async.wait_group 1;"); }
        else                 { asm volatile("cp.async.wait_group 0;"); }
        __syncthreads();
        const uint32_t base = sb + (uint32_t)(t & 1) * (2 * TB);

        // ---- S = Q K^T (single-pass fp16) -------------------------------------
        float sacc[8][4];
#pragma unroll
        for (int j = 0; j < 8; j++)
#pragma unroll
            for (int c = 0; c < 4; c++) sacc[j][c] = 0.0f;

#pragma unroll
        for (int kc = 0; kc < 8; kc++) {
            const uint32_t kb = (uint32_t)(kc * 16 + bkoff) << 1;
#pragma unroll
            for (int np = 0; np < 4; np++) {
                uint32_t rb = base + (uint32_t)(np * 16 + brow) * KROW + kb;
                uint32_t bh4[4];
                ldm_x4(bh4, rb);
#pragma unroll
                for (int ia = 0; ia < 2; ia++)
                    mma_f16(sacc[np * 2 + ia], qf[kc], bh4[2 * ia], bh4[2 * ia + 1]);
            }
        }

        // ---- causal mask (warp-uniform skip when fully unmasked) --------------
        const int k0 = t * AKN;
        if (k0 + AKN - 1 > q0 + wm) {
            const int r0 = q0 + wm + (lane >> 2);
#pragma unroll
            for (int j = 0; j < 8; j++) {
                int cb = k0 + j * 8 + ((lane & 3) << 1);
                if (cb     > r0)     sacc[j][0] = -INFINITY;
                if (cb + 1 > r0)     sacc[j][1] = -INFINITY;
                if (cb     > r0 + 8) sacc[j][2] = -INFINITY;
                if (cb + 1 > r0 + 8) sacc[j][3] = -INFINITY;
            }
        }

        // ---- online softmax ---------------------------------------------------
        float mx0 = -INFINITY, mx1 = -INFINITY;
#pragma unroll
        for (int j = 0; j < 8; j++) {
            mx0 = fmaxf(mx0, fmaxf(sacc[j][0], sacc[j][1]));
            mx1 = fmaxf(mx1, fmaxf(sacc[j][2], sacc[j][3]));
        }
        mx0 = fmaxf(mx0, __shfl_xor_sync(0xffffffffu, mx0, 1));
        mx0 = fmaxf(mx0, __shfl_xor_sync(0xffffffffu, mx0, 2));
        mx1 = fmaxf(mx1, __shfl_xor_sync(0xffffffffu, mx1, 1));
        mx1 = fmaxf(mx1, __shfl_xor_sync(0xffffffffu, mx1, 2));
        float mn0 = fmaxf(mrun0, mx0), mn1 = fmaxf(mrun1, mx1);

        float sum0 = 0.0f, sum1 = 0.0f;
#pragma unroll
        for (int j = 0; j < 8; j++) {
            float e0 = __expf(sacc[j][0] - mn0);
            float e1 = __expf(sacc[j][1] - mn0);
            float e2 = __expf(sacc[j][2] - mn1);
            float e3 = __expf(sacc[j][3] - mn1);
            sacc[j][0] = e0; sacc[j][1] = e1; sacc[j][2] = e2; sacc[j][3] = e3;
            sum0 += e0 + e1; sum1 += e2 + e3;
        }
        sum0 += __shfl_xor_sync(0xffffffffu, sum0, 1);
        sum0 += __shfl_xor_sync(0xffffffffu, sum0, 2);
        sum1 += __shfl_xor_sync(0xffffffffu, sum1, 1);
        sum1 += __shfl_xor_sync(0xffffffffu, sum1, 2);

        float c0 = __expf(mrun0 - mn0), c1 = __expf(mrun1 - mn1);
        lrun0 = lrun0 * c0 + sum0;
        lrun1 = lrun1 * c1 + sum1;
        mrun0 = mn0; mrun1 = mn1;
#pragma unroll
        for (int j = 0; j < 16; j++) {
            oacc[j][0] *= c0; oacc[j][1] *= c0;
            oacc[j][2] *= c1; oacc[j][3] *= c1;
        }

        // ---- O += P V (single-pass fp16) --------------------------------------
#pragma unroll
        for (int kc = 0; kc < 4; kc++) {
            uint32_t pa[4];
            __half2 p0 = __floats2half2_rn(sacc[2*kc][0],   sacc[2*kc][1]);
            __half2 p1 = __floats2half2_rn(sacc[2*kc][2],   sacc[2*kc][3]);
            __half2 p2 = __floats2half2_rn(sacc[2*kc+1][0], sacc[2*kc+1][1]);
            __half2 p3 = __floats2half2_rn(sacc[2*kc+1][2], sacc[2*kc+1][3]);
            pa[0] = *(uint32_t*)&p0; pa[1] = *(uint32_t*)&p1;
            pa[2] = *(uint32_t*)&p2; pa[3] = *(uint32_t*)&p3;
#pragma unroll
            for (int nd = 0; nd < 8; nd++) {
                uint32_t rv = base + TB + (uint32_t)(kc * 16 + vrow) * KROW
                              + ((uint32_t)(nd * 16 + vcoff) << 1);
                uint32_t vh4[4];
                ldm_x4_t(vh4, rv);
#pragma unroll
                for (int ia = 0; ia < 2; ia++)
                    mma_f16(oacc[nd * 2 + ia], pa, vh4[2 * ia], vh4[2 * ia + 1]);
            }
        }
        __syncthreads();
    }

    // ---- epilogue: normalize, write single fp16 for the Wo GEMM ----------------
    const float inv0 = 1.0f / lrun0, inv1 = 1.0f / lrun1;
    const size_t r0 = (size_t)(b * SS + q0 + wm + (lane >> 2)) * (NH * DH)
                      + h * DH + ((lane & 3) << 1);
    const size_t r1 = r0 + (size_t)8 * (NH * DH);
#pragma unroll
    for (int nd = 0; nd < 16; nd++) {
        __half2 h0 = __floats2half2_rn(oacc[nd][0] * inv0, oacc[nd][1] * inv0);
        __half2 h1 = __floats2half2_rn(oacc[nd][2] * inv1, oacc[nd][3] * inv1);
        *(__half2*)(g_att16 + r0 + nd * 8) = h0;
        *(__half2*)(g_att16 + r1 + nd * 8) = h1;
    }
}

// ---------------- launch --------------------------------------------------------
extern "C" void kernel_launch(void* const* d_in, const int* in_sizes, int n_in,
                              void* d_out, int out_size)
{
    const float* x   = (const float*)d_in[0];
    // d_in[1] = mask (causal; handled analytically)
    const int*   pos = (const int*)d_in[2];
    const float* Wq  = (const float*)d_in[3];
    const float* Wk  = (const float*)d_in[4];
    const float* Wv  = (const float*)d_in[5];
    const float* Wo  = (const float*)d_in[6];
    float* out = (float*)d_out;

    float* qkvraw;
    cudaGetSymbolAddress((void**)&qkvraw, g_qkvraw);
    __half *x16, *wqkvh, *wqkvl, *woh, *wol, *att16;
    cudaGetSymbolAddress((void**)&x16,   g_x16);
    cudaGetSymbolAddress((void**)&wqkvh, g_wqkvh16);
    cudaGetSymbolAddress((void**)&wqkvl, g_wqkvl16);
    cudaGetSymbolAddress((void**)&woh,   g_woh16);
    cudaGetSymbolAddress((void**)&wol,   g_wol16);
    cudaGetSymbolAddress((void**)&att16, g_att16);

    cudaFuncSetAttribute(attn_kernel,
                         cudaFuncAttributeMaxDynamicSharedMemorySize, AT_SMEM);
    cudaFuncSetAttribute(mm_f16_kernel,
                         cudaFuncAttributeMaxDynamicSharedMemorySize, MM_SMEM);

    // convert x to fp16
    cvt16_kernel<<<(MROWS * DIM / 4 + 255) / 256, 256>>>(x, x16, MROWS * DIM / 4);
    // transpose+split weights (fp16 hi/lo) into fused [3072][2048]
    splitT16_kernel<<<dim3(DIM / 32, DIM / 32), dim3(32, 8)>>>(Wq, wqkvh, wqkvl, DIM, DIM);
    splitT16_kernel<<<dim3((KVH * DH) / 32, DIM / 32), dim3(32, 8)>>>(
        Wk, wqkvh + (size_t)2048 * DIM, wqkvl + (size_t)2048 * DIM, DIM, KVH * DH);
    splitT16_kernel<<<dim3((KVH * DH) / 32, DIM / 32), dim3(32, 8)>>>(
        Wv, wqkvh + (size_t)2560 * DIM, wqkvl + (size_t)2560 * DIM, DIM, KVH * DH);
    splitT16_kernel<<<dim3(DIM / 32, DIM / 32), dim3(32, 8)>>>(Wo, woh, wol, DIM, DIM);

    // fused QKV projection (fp16 2-pass, one launch, N=3072)
    mm_f16_kernel<<<dim3(NQKV / 128, MROWS / 128), 128, MM_SMEM>>>(
        x16, wqkvh, wqkvl, qkvraw, NQKV);

    // RoPE -> fp16 attention operands
    rope_kernel<<<dim3(SS, BB), 256>>>(pos);

    // attention on tensor cores (fp16 single-pass)
    attn_kernel<<<dim3(SS / AQM, NH, BB), 256, AT_SMEM>>>();

    // output projection (fp16 2-pass)
    mm_f16_kernel<<<dim3(DIM / 128, MROWS / 128), 128, MM_SMEM>>>(
        att16, woh, wol, out, DIM);
}

// round 11
// speedup vs baseline: 7.2927x; 1.4291x over previous
#include <cuda_runtime.h>
#include <cuda_bf16.h>
#include <cuda_fp16.h>
#include <math.h>
#include <stdint.h>

// Problem constants
#define BB 2
#define SS 2048
#define DIM 2048
#define NH 16
#define KVH 4
#define DH 128
#define MROWS (BB * SS)   // 4096
#define NQKV 3072         // fused QKV output width (2048 q + 512 k + 512 v)

// ---------------- scratch (device globals; no allocation allowed) -------------
__device__ float g_qkvraw[MROWS * NQKV];        // fused QKV projection output

// attention operands (fp16, single precision each), layout [b,h,s,d]
__device__ __half g_q16[BB * NH * SS * DH];     // Q (scale folded)
__device__ __half g_k16[BB * KVH * SS * DH];    // K
__device__ __half g_v16[BB * KVH * SS * DH];    // V

// fp16 GEMM operands (all single fp16 now)
__device__ __half g_x16[MROWS * DIM];           // x
__device__ __half g_wqkv16[NQKV * DIM];         // fused W_qkv, transposed [N][K]
__device__ __half g_wo16[DIM * DIM];            // W_o, transposed [N][K]
__device__ __half g_att16[MROWS * (NH*DH)];     // attention output

// ---------------- PTX helpers ---------------------------------------------------
__device__ __forceinline__ uint32_t smem_u32(const void* p) {
    uint32_t a;
    asm("{ .reg .u64 t; cvta.to.shared.u64 t, %1; cvt.u32.u64 %0, t; }"
        : "=r"(a) : "l"(p));
    return a;
}

__device__ __forceinline__ void cp16(uint32_t dst, const void* src) {
    asm volatile("cp.async.cg.shared.global [%0], [%1], 16;\n"
                 :: "r"(dst), "l"(src));
}

__device__ __forceinline__ void ldm_x4(uint32_t r[4], uint32_t addr) {
    asm volatile("ldmatrix.sync.aligned.m8n8.x4.shared.b16 {%0,%1,%2,%3}, [%4];"
                 : "=r"(r[0]), "=r"(r[1]), "=r"(r[2]), "=r"(r[3]) : "r"(addr));
}

__device__ __forceinline__ void ldm_x4_t(uint32_t r[4], uint32_t addr) {
    asm volatile("ldmatrix.sync.aligned.m8n8.x4.trans.shared.b16 {%0,%1,%2,%3}, [%4];"
                 : "=r"(r[0]), "=r"(r[1]), "=r"(r[2]), "=r"(r[3]) : "r"(addr));
}

__device__ __forceinline__ void mma_f16(float c[4], const uint32_t a[4],
                                        uint32_t b0, uint32_t b1) {
    asm volatile(
        "mma.sync.aligned.m16n8k16.row.col.f32.f16.f16.f32 "
        "{%0,%1,%2,%3}, {%4,%5,%6,%7}, {%8,%9}, {%0,%1,%2,%3};"
        : "+f"(c[0]), "+f"(c[1]), "+f"(c[2]), "+f"(c[3])
        : "r"(a[0]), "r"(a[1]), "r"(a[2]), "r"(a[3]), "r"(b0), "r"(b1));
}

// ---------------- fp32 -> fp16 single convert ----------------------------------
__global__ __launch_bounds__(256) void cvt16_kernel(
    const float* __restrict__ in, __half* __restrict__ out, int n4)
{
    int i = blockIdx.x * blockDim.x + threadIdx.x;
    if (i >= n4) return;
    float4 v = ((const float4*)in)[i];
    __half2 a = __floats2half2_rn(v.x, v.y);
    __half2 b = __floats2half2_rn(v.z, v.w);
    ((__half2*)out)[2*i]   = a;
    ((__half2*)out)[2*i+1] = b;
}

// ---------------- fp32 [K][N] -> fp16 transposed [N][K] -------------------------
__global__ __launch_bounds__(256) void cvtT16_kernel(
    const float* __restrict__ W, __half* __restrict__ T, int K, int N)
{
    __shared__ float t[32][33];
    const int n0 = blockIdx.x * 32, k0 = blockIdx.y * 32;
    const int tx = threadIdx.x, ty = threadIdx.y;   // (32, 8)
    for (int i = ty; i < 32; i += 8)
        t[i][tx] = W[(size_t)(k0 + i) * N + n0 + tx];
    __syncthreads();
    for (int i = ty; i < 32; i += 8)
        T[(size_t)(n0 + i) * K + k0 + tx] = __float2half_rn(t[tx][i]);
}

// ---------------- fp16 mma.sync single-pass GEMM --------------------------------
// C[M,N] = A @ B^T.  A:[M][K] fp16, B:[N][K] fp16.
// 4 warps, warp tile 64x64; CTA 128x128, BK=32, double-buffered cp.async.
#define GK 2048
#define ROWB 80
#define TILE_B (128 * ROWB)
#define OFF_A  0
#define OFF_B  (1 * TILE_B)
#define STG (2 * TILE_B)
#define MM_SMEM (2 * STG)   // 40960

__global__ __launch_bounds__(128) void mm_f16_kernel(
    const __half* __restrict__ A, const __half* __restrict__ B,
    float* __restrict__ C, int N)
{
    extern __shared__ char smem[];
    const uint32_t sb = smem_u32(smem);
    const int tid = threadIdx.x;
    const int lane = tid & 31, warp = tid >> 5;
    const int m0 = blockIdx.y * 128, n0 = blockIdx.x * 128;
    const int wm0 = (warp >> 1) * 64;
    const int wn0 = (warp & 1) * 64;

    const int arow_l  = lane & 15;
    const int akoff_l = (lane >> 4) << 3;
    const int brow_l  = (lane & 7) + ((lane >> 4) << 3);
    const int bkoff_l = ((lane >> 3) & 1) << 3;

    float acc[4][8][4];
#pragma unroll
    for (int im = 0; im < 4; im++)
#pragma unroll
        for (int j = 0; j < 8; j++)
#pragma unroll
            for (int c = 0; c < 4; c++) acc[im][j][c] = 0.0f;

    const int NT = GK / 32;

    auto issue = [&](int t) {
        const int k0 = t * 32;
        const uint32_t sbase = sb + (t & 1) * STG;
#pragma unroll
        for (int i = 0; i < 4; i++) {
            const int c = tid + (i << 7);
            const int row = c >> 2;
            const int off = (c & 3) << 3;
            const uint32_t soff = (uint32_t)row * ROWB + ((uint32_t)off << 1);
            cp16(sbase + OFF_A + soff, A + (size_t)(m0 + row) * GK + k0 + off);
            cp16(sbase + OFF_B + soff, B + (size_t)(n0 + row) * GK + k0 + off);
        }
        asm volatile("cp.async.commit_group;");
    };

    issue(0);

    for (int t = 0; t < NT; t++) {
        if (t + 1 < NT) issue(t + 1);
        if (t + 1 < NT) { asm volatile("cp.async.wait_group 1;"); }
        else            { asm volatile("cp.async.wait_group 0;"); }
        __syncthreads();

        const uint32_t sbase = sb + (t & 1) * STG;
#pragma unroll
        for (int ks = 0; ks < 2; ks++) {
            uint32_t ah[4][4];
            const uint32_t kba = (uint32_t)(ks * 16 + akoff_l) << 1;
#pragma unroll
            for (int im = 0; im < 4; im++) {
                uint32_t ra = sbase + (uint32_t)(wm0 + im * 16 + arow_l) * ROWB + kba;
                ldm_x4(ah[im], ra + OFF_A);
            }
            const uint32_t kbb = (uint32_t)(ks * 16 + bkoff_l) << 1;
#pragma unroll
            for (int np = 0; np < 4; np++) {
                uint32_t rb = sbase + (uint32_t)(wn0 + np * 16 + brow_l) * ROWB + kbb;
                uint32_t bh[4];
                ldm_x4(bh, rb + OFF_B);
#pragma unroll
                for (int im = 0; im < 4; im++) {
#pragma unroll
                    for (int ia = 0; ia < 2; ia++)
                        mma_f16(acc[im][np * 2 + ia], ah[im],
                                bh[2 * ia], bh[2 * ia + 1]);
                }
            }
        }
        __syncthreads();
    }

#pragma unroll
    for (int im = 0; im < 4; im++) {
        const int rbase = m0 + wm0 + im * 16 + (lane >> 2);
#pragma unroll
        for (int j = 0; j < 8; j++) {
            const int col = n0 + wn0 + j * 8 + (lane & 3) * 2;
            float2 v0 = make_float2(acc[im][j][0], acc[im][j][1]);
            float2 v1 = make_float2(acc[im][j][2], acc[im][j][3]);
            *(float2*)(C + (size_t)rbase * N + col)       = v0;
            *(float2*)(C + (size_t)(rbase + 8) * N + col) = v1;
        }
    }
}

// ---------------- RoPE -> fp16 attention operands [b,h,s,d] --------------------
__global__ __launch_bounds__(256) void rope_kernel(const int* __restrict__ pos_ids)
{
    const int s = blockIdx.x;
    const int b = blockIdx.y;
    const int t = threadIdx.x;

    __shared__ float cs[64], sn[64];
    if (t < 64) {
        double invf = exp(-((double)(2 * t) / (double)DH) * log(10000.0));
        double ang = (double)pos_ids[s] * invf;
        cs[t] = (float)cos(ang);
        sn[t] = (float)sin(ang);
    }
    __syncthreads();

    const float qk_scale = 0.08838834764831845f;   // 1/sqrt(128), folded into Q
    const float* row = g_qkvraw + (size_t)(b * SS + s) * NQKV;

    // Q: single fp16 (scale folded)
    for (int idx = t; idx < NH * 64; idx += 256) {
        int h = idx >> 6, i = idx & 63;
        float x1 = row[h * DH + i];
        float x2 = row[h * DH + 64 + i];
        size_t dst = ((size_t)(b * NH + h) * SS + s) * DH;
        g_q16[dst + i]      = __float2half_rn((x1 * cs[i] - x2 * sn[i]) * qk_scale);
        g_q16[dst + 64 + i] = __float2half_rn((x2 * cs[i] + x1 * sn[i]) * qk_scale);
    }

    // K: single fp16
    const float* krow = row + 2048;
    for (int idx = t; idx < KVH * 64; idx += 256) {
        int h = idx >> 6, i = idx & 63;
        float x1 = krow[h * DH + i];
        float x2 = krow[h * DH + 64 + i];
        size_t dst = ((size_t)(b * KVH + h) * SS + s) * DH;
        g_k16[dst + i]      = __float2half_rn(x1 * cs[i] - x2 * sn[i]);
        g_k16[dst + 64 + i] = __float2half_rn(x2 * cs[i] + x1 * sn[i]);
    }

    // V: single fp16
    const float* vrow = row + 2560;
    for (int idx = t; idx < KVH * DH; idx += 256) {
        int h = idx >> 7, d = idx & 127;
        g_v16[((size_t)(b * KVH + h) * SS + s) * DH + d] = __float2half_rn(vrow[idx]);
    }
}

// ---------------- flash attention (fp16 mma.sync 1-pass, causal, GQA) -----------
// CTA: 128 q rows x 64-key blocks. 8 warps x 16 q rows.
#define AQM 128
#define AKN 64
#define KROW 272                  // smem row stride bytes (256 data + 16 pad)
#define TB (AKN * KROW)           // 17408
#define AT_SMEM (4 * TB)          // 69632: 2 stages x (K, V)

__global__ __launch_bounds__(256) void attn_kernel()
{
    extern __shared__ char smc[];
    const uint32_t sb = smem_u32(smc);
    const int tid = threadIdx.x, lane = tid & 31, warp = tid >> 5;
    const int qt = (int)gridDim.x - 1 - (int)blockIdx.x;   // heavy tiles first
    const int h = blockIdx.y, b = blockIdx.z, kvh = h >> 2;
    const int q0 = qt * AQM;
    const int wm = warp * 16;

    const char* qp = (const char*)(g_q16 + ((size_t)(b * NH + h) * SS + q0) * DH);
    const char* kp = (const char*)(g_k16 + (size_t)(b * KVH + kvh) * SS * DH);
    const char* vp = (const char*)(g_v16 + (size_t)(b * KVH + kvh) * SS * DH);

    // ---- stage Q (128x128 fp16) into smem, ldmatrix to registers --------------
    for (int i = tid; i < 128 * 16; i += 256) {
        int row = i >> 4, ch = (i & 15) << 4;
        cp16(sb + (uint32_t)row * KROW + ch, qp + row * 256 + ch);
    }
    asm volatile("cp.async.commit_group;");
    asm volatile("cp.async.wait_group 0;");
    __syncthreads();

    const int arow = lane & 15, akoff = (lane >> 4) << 3;
    uint32_t qf[8][4];
#pragma unroll
    for (int kc = 0; kc < 8; kc++) {
        uint32_t ra = sb + (uint32_t)(wm + arow) * KROW + ((uint32_t)(kc * 16 + akoff) << 1);
        ldm_x4(qf[kc], ra);
    }
    __syncthreads();   // staging area free for K/V now

    float oacc[16][4];
#pragma unroll
    for (int j = 0; j < 16; j++)
#pragma unroll
        for (int c = 0; c < 4; c++) oacc[j][c] = 0.0f;
    float mrun0 = -INFINITY, mrun1 = -INFINITY;
    float lrun0 = 0.0f, lrun1 = 0.0f;

    const int nblocks = 2 * (qt + 1);
    const int brow = (lane & 7) + ((lane >> 4) << 3);
    const int bkoff = ((lane >> 3) & 1) << 3;
    const int vrow = lane & 15, vcoff = (lane >> 4) << 3;

    auto issue = [&](int t) {
        const uint32_t base = sb + (uint32_t)(t & 1) * (2 * TB);
        const size_t g0 = (size_t)t * AKN * 256;
        for (int i = tid; i < AKN * 16; i += 256) {
            int row = i >> 4, ch = (i & 15) << 4;
            uint32_t soff = (uint32_t)row * KROW + ch;
            size_t goff = g0 + (size_t)row * 256 + ch;
            cp16(base + soff,      kp + goff);
            cp16(base + TB + soff, vp + goff);
        }
        asm volatile("cp.async.commit_group;");
    };

    issue(0);

    for (int t = 0; t < nblocks; t++) {
        if (t + 1 < nblocks) { issue(t + 1); asm volatile("cp.async.wait_group 1;"); }
        else                 { asm volatile("cp.async.wait_group 0;"); }
        __syncthreads();
        const uint32_t base = sb + (uint32_t)(t & 1) * (2 * TB);

        // ---- S = Q K^T (single-pass fp16) -------------------------------------
        float sacc[8][4];
#pragma unroll
        for (int j = 0; j < 8; j++)
#pragma unroll
            for (int c = 0; c < 4; c++) sacc[j][c] = 0.0f;

#pragma unroll
        for (int kc = 0; kc < 8; kc++) {
            const uint32_t kb = (uint32_t)(kc * 16 + bkoff) << 1;
#pragma unroll
            for (int np = 0; np < 4; np++) {
                uint32_t rb = base + (uint32_t)(np * 16 + brow) * KROW + kb;
                uint32_t bh4[4];
                ldm_x4(bh4, rb);
#pragma unroll
                for (int ia = 0; ia < 2; ia++)
                    mma_f16(sacc[np * 2 + ia], qf[kc], bh4[2 * ia], bh4[2 * ia + 1]);
            }
        }

        // ---- causal mask (warp-uniform skip when fully unmasked) --------------
        const int k0 = t * AKN;
        if (k0 + AKN - 1 > q0 + wm) {
            const int r0 = q0 + wm + (lane >> 2);
#pragma unroll
            for (int j = 0; j < 8; j++) {
                int cb = k0 + j * 8 + ((lane & 3) << 1);
                if (cb     > r0)     sacc[j][0] = -INFINITY;
                if (cb + 1 > r0)     sacc[j][1] = -INFINITY;
                if (cb     > r0 + 8) sacc[j][2] = -INFINITY;
                if (cb + 1 > r0 + 8) sacc[j][3] = -INFINITY;
            }
        }

        // ---- online softmax ---------------------------------------------------
        float mx0 = -INFINITY, mx1 = -INFINITY;
#pragma unroll
        for (int j = 0; j < 8; j++) {
            mx0 = fmaxf(mx0, fmaxf(sacc[j][0], sacc[j][1]));
            mx1 = fmaxf(mx1, fmaxf(sacc[j][2], sacc[j][3]));
        }
        mx0 = fmaxf(mx0, __shfl_xor_sync(0xffffffffu, mx0, 1));
        mx0 = fmaxf(mx0, __shfl_xor_sync(0xffffffffu, mx0, 2));
        mx1 = fmaxf(mx1, __shfl_xor_sync(0xffffffffu, mx1, 1));
        mx1 = fmaxf(mx1, __shfl_xor_sync(0xffffffffu, mx1, 2));
        float mn0 = fmaxf(mrun0, mx0), mn1 = fmaxf(mrun1, mx1);

        float sum0 = 0.0f, sum1 = 0.0f;
#pragma unroll
        for (int j = 0; j < 8; j++) {
            float e0 = __expf(sacc[j][0] - mn0);
            float e1 = __expf(sacc[j][1] - mn0);
            float e2 = __expf(sacc[j][2] - mn1);
            float e3 = __expf(sacc[j][3] - mn1);
            sacc[j][0] = e0; sacc[j][1] = e1; sacc[j][2] = e2; sacc[j][3] = e3;
            sum0 += e0 + e1; sum1 += e2 + e3;
        }
        sum0 += __shfl_xor_sync(0xffffffffu, sum0, 1);
        sum0 += __shfl_xor_sync(0xffffffffu, sum0, 2);
        sum1 += __shfl_xor_sync(0xffffffffu, sum1, 1);
        sum1 += __shfl_xor_sync(0xffffffffu, sum1, 2);

        float c0 = __expf(mrun0 - mn0), c1 = __expf(mrun1 - mn1);
        lrun0 = lrun0 * c0 + sum0;
        lrun1 = lrun1 * c1 + sum1;
        mrun0 = mn0; mrun1 = mn1;
#pragma unroll
        for (int j = 0; j < 16; j++) {
            oacc[j][0] *= c0; oacc[j][1] *= c0;
            oacc[j][2] *= c1; oacc[j][3] *= c1;
        }

        // ---- O += P V (single-pass fp16) --------------------------------------
#pragma unroll
        for (int kc = 0; kc < 4; kc++) {
            uint32_t pa[4];
            __half2 p0 = __floats2half2_rn(sacc[2*kc][0],   sacc[2*kc][1]);
            __half2 p1 = __floats2half2_rn(sacc[2*kc][2],   sacc[2*kc][3]);
            __half2 p2 = __floats2half2_rn(sacc[2*kc+1][0], sacc[2*kc+1][1]);
            __half2 p3 = __floats2half2_rn(sacc[2*kc+1][2], sacc[2*kc+1][3]);
            pa[0] = *(uint32_t*)&p0; pa[1] = *(uint32_t*)&p1;
            pa[2] = *(uint32_t*)&p2; pa[3] = *(uint32_t*)&p3;
#pragma unroll
            for (int nd = 0; nd < 8; nd++) {
                uint32_t rv = base + TB + (uint32_t)(kc * 16 + vrow) * KROW
                              + ((uint32_t)(nd * 16 + vcoff) << 1);
                uint32_t vh4[4];
                ldm_x4_t(vh4, rv);
#pragma unroll
                for (int ia = 0; ia < 2; ia++)
                    mma_f16(oacc[nd * 2 + ia], pa, vh4[2 * ia], vh4[2 * ia + 1]);
            }
        }
        __syncthreads();
    }

    // ---- epilogue: normalize, write single fp16 for the Wo GEMM ----------------
    const float inv0 = 1.0f / lrun0, inv1 = 1.0f / lrun1;
    const size_t r0 = (size_t)(b * SS + q0 + wm + (lane >> 2)) * (NH * DH)
                      + h * DH + ((lane & 3) << 1);
    const size_t r1 = r0 + (size_t)8 * (NH * DH);
#pragma unroll
    for (int nd = 0; nd < 16; nd++) {
        __half2 h0 = __floats2half2_rn(oacc[nd][0] * inv0, oacc[nd][1] * inv0);
        __half2 h1 = __floats2half2_rn(oacc[nd][2] * inv1, oacc[nd][3] * inv1);
        *(__half2*)(g_att16 + r0 + nd * 8) = h0;
        *(__half2*)(g_att16 + r1 + nd * 8) = h1;
    }
}

// ---------------- launch --------------------------------------------------------
extern "C" void kernel_launch(void* const* d_in, const int* in_sizes, int n_in,
                              void* d_out, int out_size)
{
    const float* x   = (const float*)d_in[0];
    // d_in[1] = mask (causal; handled analytically)
    const int*   pos = (const int*)d_in[2];
    const float* Wq  = (const float*)d_in[3];
    const float* Wk  = (const float*)d_in[4];
    const float* Wv  = (const float*)d_in[5];
    const float* Wo  = (const float*)d_in[6];
    float* out = (float*)d_out;

    float* qkvraw;
    cudaGetSymbolAddress((void**)&qkvraw, g_qkvraw);
    __half *x16, *wqkv, *wo, *att16;
    cudaGetSymbolAddress((void**)&x16,   g_x16);
    cudaGetSymbolAddress((void**)&wqkv,  g_wqkv16);
    cudaGetSymbolAddress((void**)&wo,    g_wo16);
    cudaGetSymbolAddress((void**)&att16, g_att16);

    cudaFuncSetAttribute(attn_kernel,
                         cudaFuncAttributeMaxDynamicSharedMemorySize, AT_SMEM);
    cudaFuncSetAttribute(mm_f16_kernel,
                         cudaFuncAttributeMaxDynamicSharedMemorySize, MM_SMEM);

    // convert x to fp16
    cvt16_kernel<<<(MROWS * DIM / 4 + 255) / 256, 256>>>(x, x16, MROWS * DIM / 4);
    // transpose+convert weights into fused [3072][2048] fp16
    cvtT16_kernel<<<dim3(DIM / 32, DIM / 32), dim3(32, 8)>>>(Wq, wqkv, DIM, DIM);
    cvtT16_kernel<<<dim3((KVH * DH) / 32, DIM / 32), dim3(32, 8)>>>(
        Wk, wqkv + (size_t)2048 * DIM, DIM, KVH * DH);
    cvtT16_kernel<<<dim3((KVH * DH) / 32, DIM / 32), dim3(32, 8)>>>(
        Wv, wqkv + (size_t)2560 * DIM, DIM, KVH * DH);
    cvtT16_kernel<<<dim3(DIM / 32, DIM / 32), dim3(32, 8)>>>(Wo, wo, DIM, DIM);

    // fused QKV projection (fp16 single-pass, one launch, N=3072)
    mm_f16_kernel<<<dim3(NQKV / 128, MROWS / 128), 128, MM_SMEM>>>(
        x16, wqkv, qkvraw, NQKV);

    // RoPE -> fp16 attention operands
    rope_kernel<<<dim3(SS, BB), 256>>>(pos);

    // attention on tensor cores (fp16 single-pass)
    attn_kernel<<<dim3(SS / AQM, NH, BB), 256, AT_SMEM>>>();

    // output projection (fp16 single-pass)
    mm_f16_kernel<<<dim3(DIM / 128, MROWS / 128), 128, MM_SMEM>>>(
        att16, wo, out, DIM);
}